// round 7
// baseline (speedup 1.0000x reference)
#include <cuda_runtime.h>

#define TFULL 2048
#define CIN   64
#define DMODEL 128
#define SNUM  3
#define BNUM  2
#define HNUM  8
#define DH    16

typedef unsigned int uint32;

__device__ __forceinline__ uint32 cvt_tf32(float x) {
    uint32 r; asm("cvt.rna.tf32.f32 %0,%1;" : "=r"(r) : "f"(x)); return r;
}
__device__ __forceinline__ void mma_tf32(float* d, const uint32* a, uint32 b0, uint32 b1) {
    asm volatile("mma.sync.aligned.m16n8k8.row.col.f32.tf32.tf32.f32 "
        "{%0,%1,%2,%3},{%4,%5,%6,%7},{%8,%9},{%0,%1,%2,%3};"
        : "+f"(d[0]), "+f"(d[1]), "+f"(d[2]), "+f"(d[3])
        : "r"(a[0]), "r"(a[1]), "r"(a[2]), "r"(a[3]), "r"(b0), "r"(b1));
}

// ---------------- wavelet filters ----------------
__constant__ float c_DEC_LO[8] = {
    -0.010597401784997278f,  0.032883011666982945f,  0.030841381835986965f,
    -0.18703481171888114f,  -0.02798376941698385f,   0.6308807679295904f,
     0.7148465705525415f,    0.23037781330885523f };
__constant__ float c_DEC_HI[8] = {
    -0.23037781330885523f,   0.7148465705525415f,   -0.6308807679295904f,
    -0.02798376941698385f,   0.18703481171888114f,   0.030841381835986965f,
    -0.032883011666982945f, -0.010597401784997278f };

// ---------------- scratch ----------------
__device__ float g_W   [SNUM*BNUM*TFULL*CIN];
__device__ float g_A   [SNUM*3*DMODEL*CIN];
__device__ float g_cb  [SNUM*3*DMODEL];
__device__ float g_q   [SNUM*BNUM*TFULL*DMODEL];
__device__ float g_khi [SNUM*BNUM*TFULL*DMODEL];   // K pre-split tf32 hi
__device__ float g_klo [SNUM*BNUM*TFULL*DMODEL];   // K pre-split tf32 lo
__device__ float g_vt  [SNUM*BNUM*TFULL*DMODEL];   // V pre-rounded tf32
__device__ float g_o   [SNUM*BNUM*TFULL*DMODEL];
__device__ float g_meanp[SNUM*BNUM*16*DMODEL];
__device__ float g_gate[BNUM*SNUM];

// ================= K0: stationary wavelet transform =================
__global__ void k_swt(const float* __restrict__ x) {
    __shared__ float sh[2][TFULL];
    const int b = blockIdx.x >> 6;
    const int c = blockIdx.x & 63;
    const int tid = threadIdx.x;

    for (int t = tid; t < TFULL; t += 256)
        sh[0][t] = x[(b * TFULL + t) * CIN + c];
    __syncthreads();

    int cur = 0;
    for (int j = 0; j < 3; j++) {
        const int step = 1 << j;
        for (int t = tid; t < TFULL; t += 256) {
            float d = 0.f, a = 0.f;
#pragma unroll
            for (int l = 0; l < 8; l++) {
                float val = sh[cur][(t - l * step) & (TFULL - 1)];
                d += val * c_DEC_HI[l];
                a += val * c_DEC_LO[l];
            }
            g_W[(((2 - j) * BNUM + b) * TFULL + t) * CIN + c] = d;
            sh[cur ^ 1][t] = a;
        }
        __syncthreads();
        cur ^= 1;
    }
}

// ================= K1: compose (in_w x Wqkv) weights + biases =================
__global__ void k_compose(const float* __restrict__ Wq, const float* __restrict__ bq,
                          const float* __restrict__ Wk, const float* __restrict__ bk,
                          const float* __restrict__ Wv, const float* __restrict__ bv,
                          const float* __restrict__ in_w, const float* __restrict__ in_b) {
    const int sw = blockIdx.x;
    const int s = sw / 3, w = sw % 3;
    const float* Wx = (w == 0) ? Wq : (w == 1) ? Wk : Wv;
    const float* bx = (w == 0) ? bq : (w == 1) ? bk : bv;

    const int idx = blockIdx.y * 256 + threadIdx.x;
    const int e = idx >> 6, c = idx & 63;
    const float* iw = in_w + (w * DMODEL + e) * DMODEL;
    const float* wc = Wx + s * DMODEL * CIN + c;
    float acc = 0.f;
#pragma unroll 4
    for (int dd = 0; dd < DMODEL; dd++) acc += iw[dd] * wc[dd * CIN];
    g_A[(sw * DMODEL + e) * CIN + c] = acc;

    if (blockIdx.y == 0 && threadIdx.x < DMODEL) {
        const int ee = threadIdx.x;
        const float* iw2 = in_w + (w * DMODEL + ee) * DMODEL;
        float bb = in_b[w * DMODEL + ee];
#pragma unroll 4
        for (int dd = 0; dd < DMODEL; dd++) bb += iw2[dd] * bx[s * DMODEL + dd];
        g_cb[sw * DMODEL + ee] = bb;
    }
}

// ================= K2: fused q/k/v projection GEMM + tf32 pre-conversion =================
// w==0 -> raw Q; w==1 -> K split hi/lo tf32; w==2 -> V rounded tf32.
__global__ void __launch_bounds__(256) k_qkv() {
    __shared__ float shW[64][33];
    __shared__ float shA[128][33];
    const int row0 = blockIdx.x * 64;
    const int w = blockIdx.y;
    const int s = row0 >> 12;
    const int tid = threadIdx.x;
    const int ty = tid >> 4, tx = tid & 15;
    const float* Abase = g_A + (s * 3 + w) * DMODEL * CIN;

    float acc[4][8];
#pragma unroll
    for (int i = 0; i < 4; i++)
#pragma unroll
        for (int j = 0; j < 8; j++) acc[i][j] = 0.f;

    for (int c0 = 0; c0 < CIN; c0 += 32) {
#pragma unroll
        for (int i = 0; i < 8; i++) {
            int lin = tid + i * 256;
            shW[lin >> 5][lin & 31] = g_W[(row0 + (lin >> 5)) * CIN + c0 + (lin & 31)];
        }
#pragma unroll
        for (int i = 0; i < 16; i++) {
            int lin = tid + i * 256;
            shA[lin >> 5][lin & 31] = Abase[(lin >> 5) * CIN + c0 + (lin & 31)];
        }
        __syncthreads();
#pragma unroll
        for (int cc = 0; cc < 32; cc++) {
            float wr[4], ar[8];
#pragma unroll
            for (int i = 0; i < 4; i++) wr[i] = shW[i * 16 + ty][cc];
#pragma unroll
            for (int j = 0; j < 8; j++) ar[j] = shA[j * 16 + tx][cc];
#pragma unroll
            for (int i = 0; i < 4; i++)
#pragma unroll
                for (int j = 0; j < 8; j++) acc[i][j] += wr[i] * ar[j];
        }
        __syncthreads();
    }

    const float* cb = g_cb + (s * 3 + w) * DMODEL;
#pragma unroll
    for (int i = 0; i < 4; i++) {
        int r = row0 + i * 16 + ty;
#pragma unroll
        for (int j = 0; j < 8; j++) {
            int e = j * 16 + tx;
            float val = acc[i][j] + cb[e];
            size_t oidx = (size_t)r * DMODEL + e;
            if (w == 0) {
                g_q[oidx] = val;
            } else if (w == 1) {
                float hi = __uint_as_float(cvt_tf32(val));
                g_khi[oidx] = hi;
                g_klo[oidx] = __uint_as_float(cvt_tf32(val - hi));
            } else {
                g_vt[oidx] = __uint_as_float(cvt_tf32(val));
            }
        }
    }
}

// ================= K3: flash attention on tensor cores (tf32 mma) =================
// grid: (32 q-tiles of 64, 8 heads, 6 s*b). block 128 (4 warps, 16 q-rows/warp).
// K/V arrive pre-converted; smem fill is a pure float4 copy.
#define KSTRIDE 20
#define VSTRIDE 24
__global__ void __launch_bounds__(128) k_attn() {
    __shared__ float sKhi[64 * KSTRIDE];
    __shared__ float sKlo[64 * KSTRIDE];
    __shared__ float sV  [64 * VSTRIDE];

    const int tid  = threadIdx.x;
    const int warp = tid >> 5, lane = tid & 31;
    const int gid  = lane >> 2, tig = lane & 3;
    const int qt = blockIdx.x, h = blockIdx.y, sb = blockIdx.z;
    const int qbase = qt * 64 + warp * 16;

    const float sc = 0.25f * 1.4426950408889634f;   // 1/sqrt(DH) * log2(e)

    // ---- load Q rows (gid, gid+8), split hi/lo tf32 (once per thread) ----
    const float* qr = g_q + ((size_t)(sb * TFULL) + qbase + gid) * DMODEL + h * DH;
    float qv[8];
    qv[0] = qr[tig];                 qv[1] = qr[tig + 4];
    qv[2] = qr[tig + 8];             qv[3] = qr[tig + 12];
    qv[4] = qr[8 * DMODEL + tig];    qv[5] = qr[8 * DMODEL + tig + 4];
    qv[6] = qr[8 * DMODEL + tig + 8];qv[7] = qr[8 * DMODEL + tig + 12];
    uint32 qhi[8], qlo[8];
#pragma unroll
    for (int i = 0; i < 8; i++) {
        float x = qv[i] * sc;
        qhi[i] = cvt_tf32(x);
        qlo[i] = cvt_tf32(x - __uint_as_float(qhi[i]));
    }
    uint32 ahi0[4] = { qhi[0], qhi[4], qhi[1], qhi[5] };
    uint32 alo0[4] = { qlo[0], qlo[4], qlo[1], qlo[5] };
    uint32 ahi1[4] = { qhi[2], qhi[6], qhi[3], qhi[7] };
    uint32 alo1[4] = { qlo[2], qlo[6], qlo[3], qlo[7] };

    float m_lo = -1e30f, m_hi = -1e30f, l_lo = 0.f, l_hi = 0.f;
    float oc[2][4];
#pragma unroll
    for (int nv = 0; nv < 2; nv++)
#pragma unroll
        for (int i = 0; i < 4; i++) oc[nv][i] = 0.f;

    const int sigma = (gid >> 1) + ((gid & 1) << 2);   // key-col permutation

    // fill-index precompute (per thread, invariant over kc)
    const int fr0 = tid >> 2, fc0 = (tid & 3) * 4;
    const size_t gbase = (size_t)(sb * TFULL) * DMODEL + h * DH;

    // B-fragment smem pointers (invariant offsets)
    const float* kh_base = sKhi + sigma * KSTRIDE + tig;
    const float* kl_base = sKlo + sigma * KSTRIDE + tig;
    const float* v0_base = sV + tig * VSTRIDE + gid;
    const float* v1_base = sV + (tig + 4) * VSTRIDE + gid;

    for (int kc = 0; kc < TFULL; kc += 64) {
        // ---- fill smem: pure float4 copies (no conversion) ----
#pragma unroll
        for (int i = 0; i < 2; i++) {
            int r = fr0 + i * 32;
            size_t gidx = gbase + (size_t)(kc + r) * DMODEL + fc0;
            *(float4*)(sKhi + r * KSTRIDE + fc0) = *(const float4*)(g_khi + gidx);
            *(float4*)(sKlo + r * KSTRIDE + fc0) = *(const float4*)(g_klo + gidx);
            *(float4*)(sV   + r * VSTRIDE + fc0) = *(const float4*)(g_vt  + gidx);
        }
        __syncthreads();

        // ---- S = Q K^T (3xTF32), C layout pre-permuted for PV ----
        float cS[8][4];
#pragma unroll
        for (int nt = 0; nt < 8; nt++) {
            cS[nt][0] = 0.f; cS[nt][1] = 0.f; cS[nt][2] = 0.f; cS[nt][3] = 0.f;
            const float* kh = kh_base + 8 * nt * KSTRIDE;
            const float* kl = kl_base + 8 * nt * KSTRIDE;
            uint32 b0h = __float_as_uint(kh[0]);
            uint32 b1h = __float_as_uint(kh[4]);
            uint32 b0l = __float_as_uint(kl[0]);
            uint32 b1l = __float_as_uint(kl[4]);
            mma_tf32(cS[nt], ahi0, b0h, b1h);
            mma_tf32(cS[nt], alo0, b0h, b1h);
            mma_tf32(cS[nt], ahi0, b0l, b1l);
            b0h = __float_as_uint(kh[8]);
            b1h = __float_as_uint(kh[12]);
            b0l = __float_as_uint(kl[8]);
            b1l = __float_as_uint(kl[12]);
            mma_tf32(cS[nt], ahi1, b0h, b1h);
            mma_tf32(cS[nt], alo1, b0h, b1h);
            mma_tf32(cS[nt], ahi1, b0l, b1l);
        }

        // ---- online softmax on fragments ----
        float mx0 = m_lo, mx1 = m_hi;
#pragma unroll
        for (int nt = 0; nt < 8; nt++) {
            mx0 = fmaxf(mx0, fmaxf(cS[nt][0], cS[nt][1]));
            mx1 = fmaxf(mx1, fmaxf(cS[nt][2], cS[nt][3]));
        }
        mx0 = fmaxf(mx0, __shfl_xor_sync(0xffffffffu, mx0, 1));
        mx0 = fmaxf(mx0, __shfl_xor_sync(0xffffffffu, mx0, 2));
        mx1 = fmaxf(mx1, __shfl_xor_sync(0xffffffffu, mx1, 1));
        mx1 = fmaxf(mx1, __shfl_xor_sync(0xffffffffu, mx1, 2));
        float cr0 = exp2f(m_lo - mx0), cr1 = exp2f(m_hi - mx1);
        m_lo = mx0; m_hi = mx1;
        l_lo *= cr0; l_hi *= cr1;
#pragma unroll
        for (int nv = 0; nv < 2; nv++) {
            oc[nv][0] *= cr0; oc[nv][1] *= cr0;
            oc[nv][2] *= cr1; oc[nv][3] *= cr1;
        }
        uint32 pt[8][4];
#pragma unroll
        for (int nt = 0; nt < 8; nt++) {
            float p0 = exp2f(cS[nt][0] - m_lo);
            float p1 = exp2f(cS[nt][1] - m_lo);
            float p2 = exp2f(cS[nt][2] - m_hi);
            float p3 = exp2f(cS[nt][3] - m_hi);
            l_lo += p0 + p1;
            l_hi += p2 + p3;
            pt[nt][0] = cvt_tf32(p0);
            pt[nt][1] = cvt_tf32(p1);
            pt[nt][2] = cvt_tf32(p2);
            pt[nt][3] = cvt_tf32(p3);
        }

        // ---- O += P V  (A fragment = permuted C fragment) ----
#pragma unroll
        for (int j = 0; j < 8; j++) {
            uint32 ap[4] = { pt[j][0], pt[j][2], pt[j][1], pt[j][3] };
            const float* v0 = v0_base + 8 * j * VSTRIDE;
            const float* v1 = v1_base + 8 * j * VSTRIDE;
            uint32 b0 = __float_as_uint(v0[0]);
            uint32 b1 = __float_as_uint(v1[0]);
            mma_tf32(oc[0], ap, b0, b1);
            b0 = __float_as_uint(v0[8]);
            b1 = __float_as_uint(v1[8]);
            mma_tf32(oc[1], ap, b0, b1);
        }
        __syncthreads();
    }

    // ---- finalize ----
    l_lo += __shfl_xor_sync(0xffffffffu, l_lo, 1);
    l_lo += __shfl_xor_sync(0xffffffffu, l_lo, 2);
    l_hi += __shfl_xor_sync(0xffffffffu, l_hi, 1);
    l_hi += __shfl_xor_sync(0xffffffffu, l_hi, 2);
    float inv_lo = 1.f / l_lo;
    float inv_hi = 1.f / l_hi;

    float* ob = g_o + ((size_t)(sb * TFULL) + qbase + gid) * DMODEL + h * DH;
#pragma unroll
    for (int nv = 0; nv < 2; nv++) {
        *(float2*)(ob + 2 * tig + 8 * nv) =
            make_float2(oc[nv][0] * inv_lo, oc[nv][1] * inv_lo);
        *(float2*)(ob + 8 * DMODEL + 2 * tig + 8 * nv) =
            make_float2(oc[nv][2] * inv_hi, oc[nv][3] * inv_hi);
    }
}

// ================= K4: partial t-sums =================
__global__ void k_meanred() {
    const int s = blockIdx.x, b = blockIdx.y, ch = blockIdx.z;
    const int d = threadIdx.x;
    const float* base = g_o + (((size_t)(s * BNUM + b) * TFULL) + ch * 128) * DMODEL + d;
    float sum = 0.f;
#pragma unroll 8
    for (int t = 0; t < 128; t++) sum += base[t * DMODEL];
    g_meanp[((s * BNUM + b) * 16 + ch) * DMODEL + d] = sum;
}

// ================= K5: gate computation =================
__global__ void k_gate(const float* __restrict__ out_w, const float* __restrict__ out_b,
                       const float* __restrict__ gate_w, const float* __restrict__ gate_b) {
    __shared__ float sh_m[DMODEL];
    __shared__ float sh_gf[DMODEL];
    __shared__ float sh_lg[SNUM];
    const int d = threadIdx.x;
    for (int b = 0; b < BNUM; b++) {
        float mv = 0.f;
#pragma unroll
        for (int s = 0; s < SNUM; s++)
#pragma unroll
            for (int c = 0; c < 16; c++)
                mv += g_meanp[((s * BNUM + b) * 16 + c) * DMODEL + d];
        sh_m[d] = mv;
        __syncthreads();
        float acc = 0.f;
        const float* ow = out_w + d * DMODEL;
#pragma unroll 4
        for (int dd = 0; dd < DMODEL; dd++) acc += ow[dd] * sh_m[dd];
        sh_gf[d] = acc * (1.0f / (TFULL * SNUM)) + out_b[d];
        __syncthreads();
        if (d < SNUM) {
            float lg = gate_b[d];
            for (int dd = 0; dd < DMODEL; dd++) lg += sh_gf[dd] * gate_w[d * DMODEL + dd];
            sh_lg[d] = lg;
        }
        __syncthreads();
        if (d == 0) {
            float mx = fmaxf(sh_lg[0], fmaxf(sh_lg[1], sh_lg[2]));
            float e0 = __expf(sh_lg[0] - mx);
            float e1 = __expf(sh_lg[1] - mx);
            float e2 = __expf(sh_lg[2] - mx);
            float inv = 1.f / (e0 + e1 + e2);
            g_gate[b * 3 + 0] = e0 * inv;
            g_gate[b * 3 + 1] = e1 * inv;
            g_gate[b * 3 + 2] = e2 * inv;
        }
        __syncthreads();
    }
}

// ================= K6: gated combine + output projection =================
__global__ void __launch_bounds__(256) k_final(const float* __restrict__ out_w,
                                               const float* __restrict__ out_b,
                                               float* __restrict__ Z) {
    __shared__ float shI[64][33];
    __shared__ float shWt[128][33];
    const int row0 = blockIdx.x * 64;
    const int tid = threadIdx.x;
    const int b = row0 >> 11;
    const float gt0 = g_gate[b * 3 + 0];
    const float gt1 = g_gate[b * 3 + 1];
    const float gt2 = g_gate[b * 3 + 2];
    const int ty = tid >> 4, tx = tid & 15;
    const size_t SB = (size_t)BNUM * TFULL * DMODEL;

    float acc[4][8];
#pragma unroll
    for (int i = 0; i < 4; i++)
#pragma unroll
        for (int j = 0; j < 8; j++) acc[i][j] = 0.f;

    for (int c0 = 0; c0 < DMODEL; c0 += 32) {
#pragma unroll
        for (int i = 0; i < 8; i++) {
            int lin = tid + i * 256;
            int rr = lin >> 5, cc = lin & 31;
            size_t idx = (size_t)(row0 + rr) * DMODEL + c0 + cc;
            float v0 = g_o[idx];
            float v1 = g_o[SB + idx];
            float v2 = g_o[2 * SB + idx];
            shI[rr][cc] = gt0 * v0 + gt1 * v1 + gt2 * v2;
        }
#pragma unroll
        for (int i = 0; i < 16; i++) {
            int lin = tid + i * 256;
            shWt[lin >> 5][lin & 31] = out_w[(lin >> 5) * DMODEL + c0 + (lin & 31)];
        }
        __syncthreads();
#pragma unroll
        for (int cc = 0; cc < 32; cc++) {
            float ir[4], wr[8];
#pragma unroll
            for (int i = 0; i < 4; i++) ir[i] = shI[i * 16 + ty][cc];
#pragma unroll
            for (int j = 0; j < 8; j++) wr[j] = shWt[j * 16 + tx][cc];
#pragma unroll
            for (int i = 0; i < 4; i++)
#pragma unroll
                for (int j = 0; j < 8; j++) acc[i][j] += ir[i] * wr[j];
        }
        __syncthreads();
    }

#pragma unroll
    for (int i = 0; i < 4; i++) {
        int r = row0 + i * 16 + ty;
#pragma unroll
        for (int j = 0; j < 8; j++) {
            int e = j * 16 + tx;
            Z[(size_t)r * DMODEL + e] = acc[i][j] + out_b[e];
        }
    }
}

// ================= launch =================
extern "C" void kernel_launch(void* const* d_in, const int* in_sizes, int n_in,
                              void* d_out, int out_size) {
    const float* x      = (const float*)d_in[0];
    const float* Wq     = (const float*)d_in[1];
    const float* bq     = (const float*)d_in[2];
    const float* Wk     = (const float*)d_in[3];
    const float* bk     = (const float*)d_in[4];
    const float* Wv     = (const float*)d_in[5];
    const float* bv     = (const float*)d_in[6];
    const float* in_w   = (const float*)d_in[7];
    const float* in_b   = (const float*)d_in[8];
    const float* out_w  = (const float*)d_in[9];
    const float* out_b  = (const float*)d_in[10];
    const float* gate_w = (const float*)d_in[11];
    const float* gate_b = (const float*)d_in[12];
    float* Z = (float*)d_out;

    k_swt    <<<BNUM * CIN, 256>>>(x);
    k_compose<<<dim3(9, 32), 256>>>(Wq, bq, Wk, bk, Wv, bv, in_w, in_b);
    k_qkv    <<<dim3(192, 3), 256>>>();
    k_attn   <<<dim3(32, HNUM, SNUM * BNUM), 128>>>();
    k_meanred<<<dim3(SNUM, BNUM, 16), 128>>>();
    k_gate   <<<1, DMODEL>>>(out_w, out_b, gate_w, gate_b);
    k_final  <<<64, 256>>>(out_w, out_b, Z);
}

// round 8
// speedup vs baseline: 1.0595x; 1.0595x over previous
#include <cuda_runtime.h>

#define TFULL 2048
#define CIN   64
#define DMODEL 128
#define SNUM  3
#define BNUM  2
#define HNUM  8
#define DH    16

typedef unsigned int uint32;

__device__ __forceinline__ uint32 cvt_tf32(float x) {
    uint32 r; asm("cvt.rna.tf32.f32 %0,%1;" : "=r"(r) : "f"(x)); return r;
}
__device__ __forceinline__ void mma_tf32(float* d, const uint32* a, uint32 b0, uint32 b1) {
    asm volatile("mma.sync.aligned.m16n8k8.row.col.f32.tf32.tf32.f32 "
        "{%0,%1,%2,%3},{%4,%5,%6,%7},{%8,%9},{%0,%1,%2,%3};"
        : "+f"(d[0]), "+f"(d[1]), "+f"(d[2]), "+f"(d[3])
        : "r"(a[0]), "r"(a[1]), "r"(a[2]), "r"(a[3]), "r"(b0), "r"(b1));
}

// ---------------- wavelet filters ----------------
__constant__ float c_DEC_LO[8] = {
    -0.010597401784997278f,  0.032883011666982945f,  0.030841381835986965f,
    -0.18703481171888114f,  -0.02798376941698385f,   0.6308807679295904f,
     0.7148465705525415f,    0.23037781330885523f };
__constant__ float c_DEC_HI[8] = {
    -0.23037781330885523f,   0.7148465705525415f,   -0.6308807679295904f,
    -0.02798376941698385f,   0.18703481171888114f,   0.030841381835986965f,
    -0.032883011666982945f, -0.010597401784997278f };

// ---------------- scratch ----------------
__device__ float g_W   [SNUM*BNUM*TFULL*CIN];
__device__ float g_A   [SNUM*3*DMODEL*CIN];
__device__ float g_cb  [SNUM*3*DMODEL];
__device__ float g_q   [SNUM*BNUM*TFULL*DMODEL];
__device__ float g_khi [SNUM*BNUM*TFULL*DMODEL];   // K pre-split tf32 hi
__device__ float g_klo [SNUM*BNUM*TFULL*DMODEL];   // K pre-split tf32 lo
__device__ float g_vt  [SNUM*BNUM*TFULL*DMODEL];   // V pre-rounded tf32
__device__ float g_o   [SNUM*BNUM*TFULL*DMODEL];
__device__ float g_meanp[SNUM*BNUM*16*DMODEL];
__device__ float g_gate[BNUM*SNUM];

// ================= K0: stationary wavelet transform =================
__global__ void k_swt(const float* __restrict__ x) {
    __shared__ float sh[2][TFULL];
    const int b = blockIdx.x >> 6;
    const int c = blockIdx.x & 63;
    const int tid = threadIdx.x;

    for (int t = tid; t < TFULL; t += 256)
        sh[0][t] = x[(b * TFULL + t) * CIN + c];
    __syncthreads();

    int cur = 0;
    for (int j = 0; j < 3; j++) {
        const int step = 1 << j;
        for (int t = tid; t < TFULL; t += 256) {
            float d = 0.f, a = 0.f;
#pragma unroll
            for (int l = 0; l < 8; l++) {
                float val = sh[cur][(t - l * step) & (TFULL - 1)];
                d += val * c_DEC_HI[l];
                a += val * c_DEC_LO[l];
            }
            g_W[(((2 - j) * BNUM + b) * TFULL + t) * CIN + c] = d;
            sh[cur ^ 1][t] = a;
        }
        __syncthreads();
        cur ^= 1;
    }
}

// ================= K1: compose (in_w x Wqkv) weights + biases =================
__global__ void k_compose(const float* __restrict__ Wq, const float* __restrict__ bq,
                          const float* __restrict__ Wk, const float* __restrict__ bk,
                          const float* __restrict__ Wv, const float* __restrict__ bv,
                          const float* __restrict__ in_w, const float* __restrict__ in_b) {
    const int sw = blockIdx.x;
    const int s = sw / 3, w = sw % 3;
    const float* Wx = (w == 0) ? Wq : (w == 1) ? Wk : Wv;
    const float* bx = (w == 0) ? bq : (w == 1) ? bk : bv;

    const int idx = blockIdx.y * 256 + threadIdx.x;
    const int e = idx >> 6, c = idx & 63;
    const float* iw = in_w + (w * DMODEL + e) * DMODEL;
    const float* wc = Wx + s * DMODEL * CIN + c;
    float acc = 0.f;
#pragma unroll 4
    for (int dd = 0; dd < DMODEL; dd++) acc += iw[dd] * wc[dd * CIN];
    g_A[(sw * DMODEL + e) * CIN + c] = acc;

    if (blockIdx.y == 0 && threadIdx.x < DMODEL) {
        const int ee = threadIdx.x;
        const float* iw2 = in_w + (w * DMODEL + ee) * DMODEL;
        float bb = in_b[w * DMODEL + ee];
#pragma unroll 4
        for (int dd = 0; dd < DMODEL; dd++) bb += iw2[dd] * bx[s * DMODEL + dd];
        g_cb[sw * DMODEL + ee] = bb;
    }
}

// ================= K2: fused q/k/v projection GEMM + tf32 pre-conversion =================
__global__ void __launch_bounds__(256) k_qkv() {
    __shared__ float shW[64][33];
    __shared__ float shA[128][33];
    const int row0 = blockIdx.x * 64;
    const int w = blockIdx.y;
    const int s = row0 >> 12;
    const int tid = threadIdx.x;
    const int ty = tid >> 4, tx = tid & 15;
    const float* Abase = g_A + (s * 3 + w) * DMODEL * CIN;

    float acc[4][8];
#pragma unroll
    for (int i = 0; i < 4; i++)
#pragma unroll
        for (int j = 0; j < 8; j++) acc[i][j] = 0.f;

    for (int c0 = 0; c0 < CIN; c0 += 32) {
#pragma unroll
        for (int i = 0; i < 8; i++) {
            int lin = tid + i * 256;
            shW[lin >> 5][lin & 31] = g_W[(row0 + (lin >> 5)) * CIN + c0 + (lin & 31)];
        }
#pragma unroll
        for (int i = 0; i < 16; i++) {
            int lin = tid + i * 256;
            shA[lin >> 5][lin & 31] = Abase[(lin >> 5) * CIN + c0 + (lin & 31)];
        }
        __syncthreads();
#pragma unroll
        for (int cc = 0; cc < 32; cc++) {
            float wr[4], ar[8];
#pragma unroll
            for (int i = 0; i < 4; i++) wr[i] = shW[i * 16 + ty][cc];
#pragma unroll
            for (int j = 0; j < 8; j++) ar[j] = shA[j * 16 + tx][cc];
#pragma unroll
            for (int i = 0; i < 4; i++)
#pragma unroll
                for (int j = 0; j < 8; j++) acc[i][j] += wr[i] * ar[j];
        }
        __syncthreads();
    }

    const float* cb = g_cb + (s * 3 + w) * DMODEL;
#pragma unroll
    for (int i = 0; i < 4; i++) {
        int r = row0 + i * 16 + ty;
#pragma unroll
        for (int j = 0; j < 8; j++) {
            int e = j * 16 + tx;
            float val = acc[i][j] + cb[e];
            size_t oidx = (size_t)r * DMODEL + e;
            if (w == 0) {
                g_q[oidx] = val;
            } else if (w == 1) {
                float hi = __uint_as_float(cvt_tf32(val));
                g_khi[oidx] = hi;
                g_klo[oidx] = __uint_as_float(cvt_tf32(val - hi));
            } else {
                g_vt[oidx] = __uint_as_float(cvt_tf32(val));
            }
        }
    }
}

// ================= K3: flash attention on tensor cores (tf32 mma) =================
// grid: (16 q-tiles of 128, 8 heads, 6 s*b). block 128 (4 warps, 32 q-rows/warp
// as two m16 A-fragment groups). B-operand (K/V) smem traffic amortized 2x.
#define KSTRIDE 20
#define VSTRIDE 24
__global__ void __launch_bounds__(128) k_attn() {
    __shared__ float sKhi[64 * KSTRIDE];
    __shared__ float sKlo[64 * KSTRIDE];
    __shared__ float sV  [64 * VSTRIDE];

    const int tid  = threadIdx.x;
    const int warp = tid >> 5, lane = tid & 31;
    const int gid  = lane >> 2, tig = lane & 3;
    const int qt = blockIdx.x, h = blockIdx.y, sb = blockIdx.z;
    const int qbase = qt * 128 + warp * 32;

    const float sc = 0.25f * 1.4426950408889634f;   // 1/sqrt(DH) * log2(e)

    // ---- load Q for both 16-row groups, split hi/lo tf32 ----
    uint32 ahi0[2][4], alo0[2][4], ahi1[2][4], alo1[2][4];
#pragma unroll
    for (int g = 0; g < 2; g++) {
        const float* qr = g_q + ((size_t)(sb * TFULL) + qbase + g * 16 + gid) * DMODEL + h * DH;
        float qv[8];
        qv[0] = qr[tig];                 qv[1] = qr[tig + 4];
        qv[2] = qr[tig + 8];             qv[3] = qr[tig + 12];
        qv[4] = qr[8 * DMODEL + tig];    qv[5] = qr[8 * DMODEL + tig + 4];
        qv[6] = qr[8 * DMODEL + tig + 8];qv[7] = qr[8 * DMODEL + tig + 12];
        uint32 qhi[8], qlo[8];
#pragma unroll
        for (int i = 0; i < 8; i++) {
            float xq = qv[i] * sc;
            qhi[i] = cvt_tf32(xq);
            qlo[i] = cvt_tf32(xq - __uint_as_float(qhi[i]));
        }
        ahi0[g][0] = qhi[0]; ahi0[g][1] = qhi[4]; ahi0[g][2] = qhi[1]; ahi0[g][3] = qhi[5];
        alo0[g][0] = qlo[0]; alo0[g][1] = qlo[4]; alo0[g][2] = qlo[1]; alo0[g][3] = qlo[5];
        ahi1[g][0] = qhi[2]; ahi1[g][1] = qhi[6]; ahi1[g][2] = qhi[3]; ahi1[g][3] = qhi[7];
        alo1[g][0] = qlo[2]; alo1[g][1] = qlo[6]; alo1[g][2] = qlo[3]; alo1[g][3] = qlo[7];
    }

    float m_lo[2] = { -1e30f, -1e30f }, m_hi[2] = { -1e30f, -1e30f };
    float l_lo[2] = { 0.f, 0.f },       l_hi[2] = { 0.f, 0.f };
    float oc[2][2][4];
#pragma unroll
    for (int g = 0; g < 2; g++)
#pragma unroll
        for (int nv = 0; nv < 2; nv++)
#pragma unroll
            for (int i = 0; i < 4; i++) oc[g][nv][i] = 0.f;

    const int sigma = (gid >> 1) + ((gid & 1) << 2);   // key-col permutation

    const int fr0 = tid >> 2, fc0 = (tid & 3) * 4;
    const size_t gbase = (size_t)(sb * TFULL) * DMODEL + h * DH;

    const float* kh_base = sKhi + sigma * KSTRIDE + tig;
    const float* kl_base = sKlo + sigma * KSTRIDE + tig;
    const float* v0_base = sV + tig * VSTRIDE + gid;
    const float* v1_base = sV + (tig + 4) * VSTRIDE + gid;

    for (int kc = 0; kc < TFULL; kc += 64) {
        // ---- fill smem: pure float4 copies ----
#pragma unroll
        for (int i = 0; i < 2; i++) {
            int r = fr0 + i * 32;
            size_t gidx = gbase + (size_t)(kc + r) * DMODEL + fc0;
            *(float4*)(sKhi + r * KSTRIDE + fc0) = *(const float4*)(g_khi + gidx);
            *(float4*)(sKlo + r * KSTRIDE + fc0) = *(const float4*)(g_klo + gidx);
            *(float4*)(sV   + r * VSTRIDE + fc0) = *(const float4*)(g_vt  + gidx);
        }
        __syncthreads();

        // ---- S = Q K^T (3xTF32) for both groups; one B load feeds 6 MMAs ----
        float cS[2][8][4];
#pragma unroll
        for (int nt = 0; nt < 8; nt++) {
#pragma unroll
            for (int g = 0; g < 2; g++) {
                cS[g][nt][0] = 0.f; cS[g][nt][1] = 0.f;
                cS[g][nt][2] = 0.f; cS[g][nt][3] = 0.f;
            }
            const float* kh = kh_base + 8 * nt * KSTRIDE;
            const float* kl = kl_base + 8 * nt * KSTRIDE;
            uint32 b0h = __float_as_uint(kh[0]);
            uint32 b1h = __float_as_uint(kh[4]);
            uint32 b0l = __float_as_uint(kl[0]);
            uint32 b1l = __float_as_uint(kl[4]);
#pragma unroll
            for (int g = 0; g < 2; g++) {
                mma_tf32(cS[g][nt], ahi0[g], b0h, b1h);
                mma_tf32(cS[g][nt], alo0[g], b0h, b1h);
                mma_tf32(cS[g][nt], ahi0[g], b0l, b1l);
            }
            b0h = __float_as_uint(kh[8]);
            b1h = __float_as_uint(kh[12]);
            b0l = __float_as_uint(kl[8]);
            b1l = __float_as_uint(kl[12]);
#pragma unroll
            for (int g = 0; g < 2; g++) {
                mma_tf32(cS[g][nt], ahi1[g], b0h, b1h);
                mma_tf32(cS[g][nt], alo1[g], b0h, b1h);
                mma_tf32(cS[g][nt], ahi1[g], b0l, b1l);
            }
        }

        // ---- online softmax per group; p converted in place (bit-cast) ----
#pragma unroll
        for (int g = 0; g < 2; g++) {
            float mx0 = m_lo[g], mx1 = m_hi[g];
#pragma unroll
            for (int nt = 0; nt < 8; nt++) {
                mx0 = fmaxf(mx0, fmaxf(cS[g][nt][0], cS[g][nt][1]));
                mx1 = fmaxf(mx1, fmaxf(cS[g][nt][2], cS[g][nt][3]));
            }
            mx0 = fmaxf(mx0, __shfl_xor_sync(0xffffffffu, mx0, 1));
            mx0 = fmaxf(mx0, __shfl_xor_sync(0xffffffffu, mx0, 2));
            mx1 = fmaxf(mx1, __shfl_xor_sync(0xffffffffu, mx1, 1));
            mx1 = fmaxf(mx1, __shfl_xor_sync(0xffffffffu, mx1, 2));
            float cr0 = exp2f(m_lo[g] - mx0), cr1 = exp2f(m_hi[g] - mx1);
            m_lo[g] = mx0; m_hi[g] = mx1;
            l_lo[g] *= cr0; l_hi[g] *= cr1;
#pragma unroll
            for (int nv = 0; nv < 2; nv++) {
                oc[g][nv][0] *= cr0; oc[g][nv][1] *= cr0;
                oc[g][nv][2] *= cr1; oc[g][nv][3] *= cr1;
            }
#pragma unroll
            for (int nt = 0; nt < 8; nt++) {
                float p0 = exp2f(cS[g][nt][0] - mx0);
                float p1 = exp2f(cS[g][nt][1] - mx0);
                float p2 = exp2f(cS[g][nt][2] - mx1);
                float p3 = exp2f(cS[g][nt][3] - mx1);
                l_lo[g] += p0 + p1;
                l_hi[g] += p2 + p3;
                cS[g][nt][0] = __uint_as_float(cvt_tf32(p0));
                cS[g][nt][1] = __uint_as_float(cvt_tf32(p1));
                cS[g][nt][2] = __uint_as_float(cvt_tf32(p2));
                cS[g][nt][3] = __uint_as_float(cvt_tf32(p3));
            }
        }

        // ---- O += P V; one V load feeds 4 MMAs ----
#pragma unroll
        for (int j = 0; j < 8; j++) {
            const float* v0 = v0_base + 8 * j * VSTRIDE;
            const float* v1 = v1_base + 8 * j * VSTRIDE;
            uint32 b0a = __float_as_uint(v0[0]);
            uint32 b1a = __float_as_uint(v1[0]);
            uint32 b0b = __float_as_uint(v0[8]);
            uint32 b1b = __float_as_uint(v1[8]);
#pragma unroll
            for (int g = 0; g < 2; g++) {
                uint32 ap[4] = { __float_as_uint(cS[g][j][0]), __float_as_uint(cS[g][j][2]),
                                 __float_as_uint(cS[g][j][1]), __float_as_uint(cS[g][j][3]) };
                mma_tf32(oc[g][0], ap, b0a, b1a);
                mma_tf32(oc[g][1], ap, b0b, b1b);
            }
        }
        __syncthreads();
    }

    // ---- finalize both groups ----
#pragma unroll
    for (int g = 0; g < 2; g++) {
        float ll = l_lo[g], lh = l_hi[g];
        ll += __shfl_xor_sync(0xffffffffu, ll, 1);
        ll += __shfl_xor_sync(0xffffffffu, ll, 2);
        lh += __shfl_xor_sync(0xffffffffu, lh, 1);
        lh += __shfl_xor_sync(0xffffffffu, lh, 2);
        float inv_lo = 1.f / ll;
        float inv_hi = 1.f / lh;

        float* ob = g_o + ((size_t)(sb * TFULL) + qbase + g * 16 + gid) * DMODEL + h * DH;
#pragma unroll
        for (int nv = 0; nv < 2; nv++) {
            *(float2*)(ob + 2 * tig + 8 * nv) =
                make_float2(oc[g][nv][0] * inv_lo, oc[g][nv][1] * inv_lo);
            *(float2*)(ob + 8 * DMODEL + 2 * tig + 8 * nv) =
                make_float2(oc[g][nv][2] * inv_hi, oc[g][nv][3] * inv_hi);
        }
    }
}

// ================= K4: partial t-sums =================
__global__ void k_meanred() {
    const int s = blockIdx.x, b = blockIdx.y, ch = blockIdx.z;
    const int d = threadIdx.x;
    const float* base = g_o + (((size_t)(s * BNUM + b) * TFULL) + ch * 128) * DMODEL + d;
    float sum = 0.f;
#pragma unroll 8
    for (int t = 0; t < 128; t++) sum += base[t * DMODEL];
    g_meanp[((s * BNUM + b) * 16 + ch) * DMODEL + d] = sum;
}

// ================= K5: gate computation =================
__global__ void k_gate(const float* __restrict__ out_w, const float* __restrict__ out_b,
                       const float* __restrict__ gate_w, const float* __restrict__ gate_b) {
    __shared__ float sh_m[DMODEL];
    __shared__ float sh_gf[DMODEL];
    __shared__ float sh_lg[SNUM];
    const int d = threadIdx.x;
    for (int b = 0; b < BNUM; b++) {
        float mv = 0.f;
#pragma unroll
        for (int s = 0; s < SNUM; s++)
#pragma unroll
            for (int c = 0; c < 16; c++)
                mv += g_meanp[((s * BNUM + b) * 16 + c) * DMODEL + d];
        sh_m[d] = mv;
        __syncthreads();
        float acc = 0.f;
        const float* ow = out_w + d * DMODEL;
#pragma unroll 4
        for (int dd = 0; dd < DMODEL; dd++) acc += ow[dd] * sh_m[dd];
        sh_gf[d] = acc * (1.0f / (TFULL * SNUM)) + out_b[d];
        __syncthreads();
        if (d < SNUM) {
            float lg = gate_b[d];
            for (int dd = 0; dd < DMODEL; dd++) lg += sh_gf[dd] * gate_w[d * DMODEL + dd];
            sh_lg[d] = lg;
        }
        __syncthreads();
        if (d == 0) {
            float mx = fmaxf(sh_lg[0], fmaxf(sh_lg[1], sh_lg[2]));
            float e0 = __expf(sh_lg[0] - mx);
            float e1 = __expf(sh_lg[1] - mx);
            float e2 = __expf(sh_lg[2] - mx);
            float inv = 1.f / (e0 + e1 + e2);
            g_gate[b * 3 + 0] = e0 * inv;
            g_gate[b * 3 + 1] = e1 * inv;
            g_gate[b * 3 + 2] = e2 * inv;
        }
        __syncthreads();
    }
}

// ================= K6: gated combine + output projection =================
__global__ void __launch_bounds__(256) k_final(const float* __restrict__ out_w,
                                               const float* __restrict__ out_b,
                                               float* __restrict__ Z) {
    __shared__ float shI[64][33];
    __shared__ float shWt[128][33];
    const int row0 = blockIdx.x * 64;
    const int tid = threadIdx.x;
    const int b = row0 >> 11;
    const float gt0 = g_gate[b * 3 + 0];
    const float gt1 = g_gate[b * 3 + 1];
    const float gt2 = g_gate[b * 3 + 2];
    const int ty = tid >> 4, tx = tid & 15;
    const size_t SB = (size_t)BNUM * TFULL * DMODEL;

    float acc[4][8];
#pragma unroll
    for (int i = 0; i < 4; i++)
#pragma unroll
        for (int j = 0; j < 8; j++) acc[i][j] = 0.f;

    for (int c0 = 0; c0 < DMODEL; c0 += 32) {
#pragma unroll
        for (int i = 0; i < 8; i++) {
            int lin = tid + i * 256;
            int rr = lin >> 5, cc = lin & 31;
            size_t idx = (size_t)(row0 + rr) * DMODEL + c0 + cc;
            float v0 = g_o[idx];
            float v1 = g_o[SB + idx];
            float v2 = g_o[2 * SB + idx];
            shI[rr][cc] = gt0 * v0 + gt1 * v1 + gt2 * v2;
        }
#pragma unroll
        for (int i = 0; i < 16; i++) {
            int lin = tid + i * 256;
            shWt[lin >> 5][lin & 31] = out_w[(lin >> 5) * DMODEL + c0 + (lin & 31)];
        }
        __syncthreads();
#pragma unroll
        for (int cc = 0; cc < 32; cc++) {
            float ir[4], wr[8];
#pragma unroll
            for (int i = 0; i < 4; i++) ir[i] = shI[i * 16 + ty][cc];
#pragma unroll
            for (int j = 0; j < 8; j++) wr[j] = shWt[j * 16 + tx][cc];
#pragma unroll
            for (int i = 0; i < 4; i++)
#pragma unroll
                for (int j = 0; j < 8; j++) acc[i][j] += ir[i] * wr[j];
        }
        __syncthreads();
    }

#pragma unroll
    for (int i = 0; i < 4; i++) {
        int r = row0 + i * 16 + ty;
#pragma unroll
        for (int j = 0; j < 8; j++) {
            int e = j * 16 + tx;
            Z[(size_t)r * DMODEL + e] = acc[i][j] + out_b[e];
        }
    }
}

// ================= launch =================
extern "C" void kernel_launch(void* const* d_in, const int* in_sizes, int n_in,
                              void* d_out, int out_size) {
    const float* x      = (const float*)d_in[0];
    const float* Wq     = (const float*)d_in[1];
    const float* bq     = (const float*)d_in[2];
    const float* Wk     = (const float*)d_in[3];
    const float* bk     = (const float*)d_in[4];
    const float* Wv     = (const float*)d_in[5];
    const float* bv     = (const float*)d_in[6];
    const float* in_w   = (const float*)d_in[7];
    const float* in_b   = (const float*)d_in[8];
    const float* out_w  = (const float*)d_in[9];
    const float* out_b  = (const float*)d_in[10];
    const float* gate_w = (const float*)d_in[11];
    const float* gate_b = (const float*)d_in[12];
    float* Z = (float*)d_out;

    k_swt    <<<BNUM * CIN, 256>>>(x);
    k_compose<<<dim3(9, 32), 256>>>(Wq, bq, Wk, bk, Wv, bv, in_w, in_b);
    k_qkv    <<<dim3(192, 3), 256>>>();
    k_attn   <<<dim3(16, HNUM, SNUM * BNUM), 128>>>();
    k_meanred<<<dim3(SNUM, BNUM, 16), 128>>>();
    k_gate   <<<1, DMODEL>>>(out_w, out_b, gate_w, gate_b);
    k_final  <<<64, 256>>>(out_w, out_b, Z);
}

// round 9
// speedup vs baseline: 1.0599x; 1.0004x over previous
#include <cuda_runtime.h>

#define TFULL 2048
#define CIN   64
#define DMODEL 128
#define SNUM  3
#define BNUM  2
#define HNUM  8
#define DH    16

typedef unsigned int uint32;

__device__ __forceinline__ uint32 cvt_tf32(float x) {
    uint32 r; asm("cvt.rna.tf32.f32 %0,%1;" : "=r"(r) : "f"(x)); return r;
}
__device__ __forceinline__ void mma_tf32(float* d, const uint32* a, uint32 b0, uint32 b1) {
    asm volatile("mma.sync.aligned.m16n8k8.row.col.f32.tf32.tf32.f32 "
        "{%0,%1,%2,%3},{%4,%5,%6,%7},{%8,%9},{%0,%1,%2,%3};"
        : "+f"(d[0]), "+f"(d[1]), "+f"(d[2]), "+f"(d[3])
        : "r"(a[0]), "r"(a[1]), "r"(a[2]), "r"(a[3]), "r"(b0), "r"(b1));
}
__device__ __forceinline__ void cp16(uint32 saddr, const float* g) {
    asm volatile("cp.async.cg.shared.global [%0], [%1], 16;" :: "r"(saddr), "l"(g));
}

// ---------------- wavelet filters ----------------
__constant__ float c_DEC_LO[8] = {
    -0.010597401784997278f,  0.032883011666982945f,  0.030841381835986965f,
    -0.18703481171888114f,  -0.02798376941698385f,   0.6308807679295904f,
     0.7148465705525415f,    0.23037781330885523f };
__constant__ float c_DEC_HI[8] = {
    -0.23037781330885523f,   0.7148465705525415f,   -0.6308807679295904f,
    -0.02798376941698385f,   0.18703481171888114f,   0.030841381835986965f,
    -0.032883011666982945f, -0.010597401784997278f };

// ---------------- scratch ----------------
__device__ float g_W   [SNUM*BNUM*TFULL*CIN];
__device__ float g_A   [SNUM*3*DMODEL*CIN];
__device__ float g_cb  [SNUM*3*DMODEL];
__device__ float g_q   [SNUM*BNUM*TFULL*DMODEL];
__device__ float g_khi [SNUM*BNUM*TFULL*DMODEL];   // K pre-split tf32 hi
__device__ float g_klo [SNUM*BNUM*TFULL*DMODEL];   // K pre-split tf32 lo
__device__ float g_vt  [SNUM*BNUM*TFULL*DMODEL];   // V pre-rounded tf32
__device__ float g_o   [SNUM*BNUM*TFULL*DMODEL];
__device__ float g_meanp[SNUM*BNUM*16*DMODEL];
__device__ float g_gate[BNUM*SNUM];

// ================= K0: stationary wavelet transform =================
__global__ void k_swt(const float* __restrict__ x) {
    __shared__ float sh[2][TFULL];
    const int b = blockIdx.x >> 6;
    const int c = blockIdx.x & 63;
    const int tid = threadIdx.x;

    for (int t = tid; t < TFULL; t += 256)
        sh[0][t] = x[(b * TFULL + t) * CIN + c];
    __syncthreads();

    int cur = 0;
    for (int j = 0; j < 3; j++) {
        const int step = 1 << j;
        for (int t = tid; t < TFULL; t += 256) {
            float d = 0.f, a = 0.f;
#pragma unroll
            for (int l = 0; l < 8; l++) {
                float val = sh[cur][(t - l * step) & (TFULL - 1)];
                d += val * c_DEC_HI[l];
                a += val * c_DEC_LO[l];
            }
            g_W[(((2 - j) * BNUM + b) * TFULL + t) * CIN + c] = d;
            sh[cur ^ 1][t] = a;
        }
        __syncthreads();
        cur ^= 1;
    }
}

// ================= K1: compose (in_w x Wqkv) weights + biases =================
__global__ void k_compose(const float* __restrict__ Wq, const float* __restrict__ bq,
                          const float* __restrict__ Wk, const float* __restrict__ bk,
                          const float* __restrict__ Wv, const float* __restrict__ bv,
                          const float* __restrict__ in_w, const float* __restrict__ in_b) {
    const int sw = blockIdx.x;
    const int s = sw / 3, w = sw % 3;
    const float* Wx = (w == 0) ? Wq : (w == 1) ? Wk : Wv;
    const float* bx = (w == 0) ? bq : (w == 1) ? bk : bv;

    const int idx = blockIdx.y * 256 + threadIdx.x;
    const int e = idx >> 6, c = idx & 63;
    const float* iw = in_w + (w * DMODEL + e) * DMODEL;
    const float* wc = Wx + s * DMODEL * CIN + c;
    float acc = 0.f;
#pragma unroll 4
    for (int dd = 0; dd < DMODEL; dd++) acc += iw[dd] * wc[dd * CIN];
    g_A[(sw * DMODEL + e) * CIN + c] = acc;

    if (blockIdx.y == 0 && threadIdx.x < DMODEL) {
        const int ee = threadIdx.x;
        const float* iw2 = in_w + (w * DMODEL + ee) * DMODEL;
        float bb = in_b[w * DMODEL + ee];
#pragma unroll 4
        for (int dd = 0; dd < DMODEL; dd++) bb += iw2[dd] * bx[s * DMODEL + dd];
        g_cb[sw * DMODEL + ee] = bb;
    }
}

// ================= K2: fused q/k/v projection GEMM + tf32 pre-conversion =================
__global__ void __launch_bounds__(256) k_qkv() {
    __shared__ float shW[64][33];
    __shared__ float shA[128][33];
    const int row0 = blockIdx.x * 64;
    const int w = blockIdx.y;
    const int s = row0 >> 12;
    const int tid = threadIdx.x;
    const int ty = tid >> 4, tx = tid & 15;
    const float* Abase = g_A + (s * 3 + w) * DMODEL * CIN;

    float acc[4][8];
#pragma unroll
    for (int i = 0; i < 4; i++)
#pragma unroll
        for (int j = 0; j < 8; j++) acc[i][j] = 0.f;

    for (int c0 = 0; c0 < CIN; c0 += 32) {
#pragma unroll
        for (int i = 0; i < 8; i++) {
            int lin = tid + i * 256;
            shW[lin >> 5][lin & 31] = g_W[(row0 + (lin >> 5)) * CIN + c0 + (lin & 31)];
        }
#pragma unroll
        for (int i = 0; i < 16; i++) {
            int lin = tid + i * 256;
            shA[lin >> 5][lin & 31] = Abase[(lin >> 5) * CIN + c0 + (lin & 31)];
        }
        __syncthreads();
#pragma unroll
        for (int cc = 0; cc < 32; cc++) {
            float wr[4], ar[8];
#pragma unroll
            for (int i = 0; i < 4; i++) wr[i] = shW[i * 16 + ty][cc];
#pragma unroll
            for (int j = 0; j < 8; j++) ar[j] = shA[j * 16 + tx][cc];
#pragma unroll
            for (int i = 0; i < 4; i++)
#pragma unroll
                for (int j = 0; j < 8; j++) acc[i][j] += wr[i] * ar[j];
        }
        __syncthreads();
    }

    const float* cb = g_cb + (s * 3 + w) * DMODEL;
#pragma unroll
    for (int i = 0; i < 4; i++) {
        int r = row0 + i * 16 + ty;
#pragma unroll
        for (int j = 0; j < 8; j++) {
            int e = j * 16 + tx;
            float val = acc[i][j] + cb[e];
            size_t oidx = (size_t)r * DMODEL + e;
            if (w == 0) {
                g_q[oidx] = val;
            } else if (w == 1) {
                float hi = __uint_as_float(cvt_tf32(val));
                g_khi[oidx] = hi;
                g_klo[oidx] = __uint_as_float(cvt_tf32(val - hi));
            } else {
                g_vt[oidx] = __uint_as_float(cvt_tf32(val));
            }
        }
    }
}

// ================= K3: flash attention on tensor cores (tf32 mma) =================
// grid: (16 q-tiles of 128, 8 heads, 6 s*b). block 128 (4 warps, 32 q-rows/warp).
// 32-key chunks (cS halved -> ~120 regs -> 4 blocks/SM), cp.async double-buffered.
#define KSTRIDE 20
#define VSTRIDE 24
#define KCH 32
__global__ void k_attn() {
    __shared__ float sKhi[2 * KCH * KSTRIDE];
    __shared__ float sKlo[2 * KCH * KSTRIDE];
    __shared__ float sV  [2 * KCH * VSTRIDE];

    const int tid  = threadIdx.x;
    const int warp = tid >> 5, lane = tid & 31;
    const int gid  = lane >> 2, tig = lane & 3;
    const int qt = blockIdx.x, h = blockIdx.y, sb = blockIdx.z;
    const int qbase = qt * 128 + warp * 32;

    const float sc = 0.25f * 1.4426950408889634f;   // 1/sqrt(DH) * log2(e)

    // ---- load Q for both 16-row groups, split hi/lo tf32 ----
    uint32 ahi0[2][4], alo0[2][4], ahi1[2][4], alo1[2][4];
#pragma unroll
    for (int g = 0; g < 2; g++) {
        const float* qr = g_q + ((size_t)(sb * TFULL) + qbase + g * 16 + gid) * DMODEL + h * DH;
        float qv[8];
        qv[0] = qr[tig];                 qv[1] = qr[tig + 4];
        qv[2] = qr[tig + 8];             qv[3] = qr[tig + 12];
        qv[4] = qr[8 * DMODEL + tig];    qv[5] = qr[8 * DMODEL + tig + 4];
        qv[6] = qr[8 * DMODEL + tig + 8];qv[7] = qr[8 * DMODEL + tig + 12];
        uint32 qhi[8], qlo[8];
#pragma unroll
        for (int i = 0; i < 8; i++) {
            float xq = qv[i] * sc;
            qhi[i] = cvt_tf32(xq);
            qlo[i] = cvt_tf32(xq - __uint_as_float(qhi[i]));
        }
        ahi0[g][0] = qhi[0]; ahi0[g][1] = qhi[4]; ahi0[g][2] = qhi[1]; ahi0[g][3] = qhi[5];
        alo0[g][0] = qlo[0]; alo0[g][1] = qlo[4]; alo0[g][2] = qlo[1]; alo0[g][3] = qlo[5];
        ahi1[g][0] = qhi[2]; ahi1[g][1] = qhi[6]; ahi1[g][2] = qhi[3]; ahi1[g][3] = qhi[7];
        alo1[g][0] = qlo[2]; alo1[g][1] = qlo[6]; alo1[g][2] = qlo[3]; alo1[g][3] = qlo[7];
    }

    float m_lo[2] = { -1e30f, -1e30f }, m_hi[2] = { -1e30f, -1e30f };
    float l_lo[2] = { 0.f, 0.f },       l_hi[2] = { 0.f, 0.f };
    float oc[2][2][4];
#pragma unroll
    for (int g = 0; g < 2; g++)
#pragma unroll
        for (int nv = 0; nv < 2; nv++)
#pragma unroll
            for (int i = 0; i < 4; i++) oc[g][nv][i] = 0.f;

    const int sigma = (gid >> 1) + ((gid & 1) << 2);   // key-col permutation

    // fill mapping: 128 threads = 32 rows x 4 float4-cols, one 16B cp.async per array
    const int fr0 = tid >> 2, fc0 = (tid & 3) * 4;
    const size_t gbase = (size_t)(sb * TFULL) * DMODEL + h * DH;
    const uint32 sKhi_b = (uint32)__cvta_generic_to_shared(sKhi) + (fr0 * KSTRIDE + fc0) * 4;
    const uint32 sKlo_b = (uint32)__cvta_generic_to_shared(sKlo) + (fr0 * KSTRIDE + fc0) * 4;
    const uint32 sV_b   = (uint32)__cvta_generic_to_shared(sV)   + (fr0 * VSTRIDE + fc0) * 4;

    const float* kh_base = sKhi + sigma * KSTRIDE + tig;
    const float* kl_base = sKlo + sigma * KSTRIDE + tig;
    const float* v0_base = sV + tig * VSTRIDE + gid;
    const float* v1_base = sV + (tig + 4) * VSTRIDE + gid;

    // prefetch chunk 0 into buffer 0
    {
        size_t gidx = gbase + (size_t)fr0 * DMODEL + fc0;
        cp16(sKhi_b, g_khi + gidx);
        cp16(sKlo_b, g_klo + gidx);
        cp16(sV_b,   g_vt  + gidx);
        asm volatile("cp.async.commit_group;" ::: "memory");
    }

    for (int c = 0; c < TFULL / KCH; c++) {
        asm volatile("cp.async.wait_group 0;" ::: "memory");
        __syncthreads();
        if (c + 1 < TFULL / KCH) {
            int nb = (c + 1) & 1;
            size_t gidx = gbase + (size_t)((c + 1) * KCH + fr0) * DMODEL + fc0;
            cp16(sKhi_b + nb * (KCH * KSTRIDE * 4), g_khi + gidx);
            cp16(sKlo_b + nb * (KCH * KSTRIDE * 4), g_klo + gidx);
            cp16(sV_b   + nb * (KCH * VSTRIDE * 4), g_vt  + gidx);
            asm volatile("cp.async.commit_group;" ::: "memory");
        }
        const int buf = c & 1;
        const float* khB = kh_base + buf * (KCH * KSTRIDE);
        const float* klB = kl_base + buf * (KCH * KSTRIDE);
        const float* v0B = v0_base + buf * (KCH * VSTRIDE);
        const float* v1B = v1_base + buf * (KCH * VSTRIDE);

        // ---- S = Q K^T (3xTF32) for both groups; one B load feeds 6 MMAs ----
        float cS[2][4][4];
#pragma unroll
        for (int nt = 0; nt < 4; nt++) {
#pragma unroll
            for (int g = 0; g < 2; g++) {
                cS[g][nt][0] = 0.f; cS[g][nt][1] = 0.f;
                cS[g][nt][2] = 0.f; cS[g][nt][3] = 0.f;
            }
            const float* kh = khB + 8 * nt * KSTRIDE;
            const float* kl = klB + 8 * nt * KSTRIDE;
            uint32 b0h = __float_as_uint(kh[0]);
            uint32 b1h = __float_as_uint(kh[4]);
            uint32 b0l = __float_as_uint(kl[0]);
            uint32 b1l = __float_as_uint(kl[4]);
#pragma unroll
            for (int g = 0; g < 2; g++) {
                mma_tf32(cS[g][nt], ahi0[g], b0h, b1h);
                mma_tf32(cS[g][nt], alo0[g], b0h, b1h);
                mma_tf32(cS[g][nt], ahi0[g], b0l, b1l);
            }
            b0h = __float_as_uint(kh[8]);
            b1h = __float_as_uint(kh[12]);
            b0l = __float_as_uint(kl[8]);
            b1l = __float_as_uint(kl[12]);
#pragma unroll
            for (int g = 0; g < 2; g++) {
                mma_tf32(cS[g][nt], ahi1[g], b0h, b1h);
                mma_tf32(cS[g][nt], alo1[g], b0h, b1h);
                mma_tf32(cS[g][nt], ahi1[g], b0l, b1l);
            }
        }

        // ---- online softmax per group; p converted in place ----
#pragma unroll
        for (int g = 0; g < 2; g++) {
            float mx0 = m_lo[g], mx1 = m_hi[g];
#pragma unroll
            for (int nt = 0; nt < 4; nt++) {
                mx0 = fmaxf(mx0, fmaxf(cS[g][nt][0], cS[g][nt][1]));
                mx1 = fmaxf(mx1, fmaxf(cS[g][nt][2], cS[g][nt][3]));
            }
            mx0 = fmaxf(mx0, __shfl_xor_sync(0xffffffffu, mx0, 1));
            mx0 = fmaxf(mx0, __shfl_xor_sync(0xffffffffu, mx0, 2));
            mx1 = fmaxf(mx1, __shfl_xor_sync(0xffffffffu, mx1, 1));
            mx1 = fmaxf(mx1, __shfl_xor_sync(0xffffffffu, mx1, 2));
            float cr0 = exp2f(m_lo[g] - mx0), cr1 = exp2f(m_hi[g] - mx1);
            m_lo[g] = mx0; m_hi[g] = mx1;
            l_lo[g] *= cr0; l_hi[g] *= cr1;
#pragma unroll
            for (int nv = 0; nv < 2; nv++) {
                oc[g][nv][0] *= cr0; oc[g][nv][1] *= cr0;
                oc[g][nv][2] *= cr1; oc[g][nv][3] *= cr1;
            }
#pragma unroll
            for (int nt = 0; nt < 4; nt++) {
                float p0 = exp2f(cS[g][nt][0] - mx0);
                float p1 = exp2f(cS[g][nt][1] - mx0);
                float p2 = exp2f(cS[g][nt][2] - mx1);
                float p3 = exp2f(cS[g][nt][3] - mx1);
                l_lo[g] += p0 + p1;
                l_hi[g] += p2 + p3;
                cS[g][nt][0] = __uint_as_float(cvt_tf32(p0));
                cS[g][nt][1] = __uint_as_float(cvt_tf32(p1));
                cS[g][nt][2] = __uint_as_float(cvt_tf32(p2));
                cS[g][nt][3] = __uint_as_float(cvt_tf32(p3));
            }
        }

        // ---- O += P V; one V load feeds 4 MMAs ----
#pragma unroll
        for (int j = 0; j < 4; j++) {
            const float* v0 = v0B + 8 * j * VSTRIDE;
            const float* v1 = v1B + 8 * j * VSTRIDE;
            uint32 b0a = __float_as_uint(v0[0]);
            uint32 b1a = __float_as_uint(v1[0]);
            uint32 b0b = __float_as_uint(v0[8]);
            uint32 b1b = __float_as_uint(v1[8]);
#pragma unroll
            for (int g = 0; g < 2; g++) {
                uint32 ap[4] = { __float_as_uint(cS[g][j][0]), __float_as_uint(cS[g][j][2]),
                                 __float_as_uint(cS[g][j][1]), __float_as_uint(cS[g][j][3]) };
                mma_tf32(oc[g][0], ap, b0a, b1a);
                mma_tf32(oc[g][1], ap, b0b, b1b);
            }
        }
    }

    // ---- finalize both groups ----
#pragma unroll
    for (int g = 0; g < 2; g++) {
        float ll = l_lo[g], lh = l_hi[g];
        ll += __shfl_xor_sync(0xffffffffu, ll, 1);
        ll += __shfl_xor_sync(0xffffffffu, ll, 2);
        lh += __shfl_xor_sync(0xffffffffu, lh, 1);
        lh += __shfl_xor_sync(0xffffffffu, lh, 2);
        float inv_lo = 1.f / ll;
        float inv_hi = 1.f / lh;

        float* ob = g_o + ((size_t)(sb * TFULL) + qbase + g * 16 + gid) * DMODEL + h * DH;
#pragma unroll
        for (int nv = 0; nv < 2; nv++) {
            *(float2*)(ob + 2 * tig + 8 * nv) =
                make_float2(oc[g][nv][0] * inv_lo, oc[g][nv][1] * inv_lo);
            *(float2*)(ob + 8 * DMODEL + 2 * tig + 8 * nv) =
                make_float2(oc[g][nv][2] * inv_hi, oc[g][nv][3] * inv_hi);
        }
    }
}

// ================= K4: partial t-sums =================
__global__ void k_meanred() {
    const int s = blockIdx.x, b = blockIdx.y, ch = blockIdx.z;
    const int d = threadIdx.x;
    const float* base = g_o + (((size_t)(s * BNUM + b) * TFULL) + ch * 128) * DMODEL + d;
    float sum = 0.f;
#pragma unroll 8
    for (int t = 0; t < 128; t++) sum += base[t * DMODEL];
    g_meanp[((s * BNUM + b) * 16 + ch) * DMODEL + d] = sum;
}

// ================= K5: gate computation =================
__global__ void k_gate(const float* __restrict__ out_w, const float* __restrict__ out_b,
                       const float* __restrict__ gate_w, const float* __restrict__ gate_b) {
    __shared__ float sh_m[DMODEL];
    __shared__ float sh_gf[DMODEL];
    __shared__ float sh_lg[SNUM];
    const int d = threadIdx.x;
    for (int b = 0; b < BNUM; b++) {
        float mv = 0.f;
#pragma unroll
        for (int s = 0; s < SNUM; s++)
#pragma unroll
            for (int c = 0; c < 16; c++)
                mv += g_meanp[((s * BNUM + b) * 16 + c) * DMODEL + d];
        sh_m[d] = mv;
        __syncthreads();
        float acc = 0.f;
        const float* ow = out_w + d * DMODEL;
#pragma unroll 4
        for (int dd = 0; dd < DMODEL; dd++) acc += ow[dd] * sh_m[dd];
        sh_gf[d] = acc * (1.0f / (TFULL * SNUM)) + out_b[d];
        __syncthreads();
        if (d < SNUM) {
            float lg = gate_b[d];
            for (int dd = 0; dd < DMODEL; dd++) lg += sh_gf[dd] * gate_w[d * DMODEL + dd];
            sh_lg[d] = lg;
        }
        __syncthreads();
        if (d == 0) {
            float mx = fmaxf(sh_lg[0], fmaxf(sh_lg[1], sh_lg[2]));
            float e0 = __expf(sh_lg[0] - mx);
            float e1 = __expf(sh_lg[1] - mx);
            float e2 = __expf(sh_lg[2] - mx);
            float inv = 1.f / (e0 + e1 + e2);
            g_gate[b * 3 + 0] = e0 * inv;
            g_gate[b * 3 + 1] = e1 * inv;
            g_gate[b * 3 + 2] = e2 * inv;
        }
        __syncthreads();
    }
}

// ================= K6: gated combine + output projection =================
__global__ void __launch_bounds__(256) k_final(const float* __restrict__ out_w,
                                               const float* __restrict__ out_b,
                                               float* __restrict__ Z) {
    __shared__ float shI[64][33];
    __shared__ float shWt[128][33];
    const int row0 = blockIdx.x * 64;
    const int tid = threadIdx.x;
    const int b = row0 >> 11;
    const float gt0 = g_gate[b * 3 + 0];
    const float gt1 = g_gate[b * 3 + 1];
    const float gt2 = g_gate[b * 3 + 2];
    const int ty = tid >> 4, tx = tid & 15;
    const size_t SB = (size_t)BNUM * TFULL * DMODEL;

    float acc[4][8];
#pragma unroll
    for (int i = 0; i < 4; i++)
#pragma unroll
        for (int j = 0; j < 8; j++) acc[i][j] = 0.f;

    for (int c0 = 0; c0 < DMODEL; c0 += 32) {
#pragma unroll
        for (int i = 0; i < 8; i++) {
            int lin = tid + i * 256;
            int rr = lin >> 5, cc = lin & 31;
            size_t idx = (size_t)(row0 + rr) * DMODEL + c0 + cc;
            float v0 = g_o[idx];
            float v1 = g_o[SB + idx];
            float v2 = g_o[2 * SB + idx];
            shI[rr][cc] = gt0 * v0 + gt1 * v1 + gt2 * v2;
        }
#pragma unroll
        for (int i = 0; i < 16; i++) {
            int lin = tid + i * 256;
            shWt[lin >> 5][lin & 31] = out_w[(lin >> 5) * DMODEL + c0 + (lin & 31)];
        }
        __syncthreads();
#pragma unroll
        for (int cc = 0; cc < 32; cc++) {
            float ir[4], wr[8];
#pragma unroll
            for (int i = 0; i < 4; i++) ir[i] = shI[i * 16 + ty][cc];
#pragma unroll
            for (int j = 0; j < 8; j++) wr[j] = shWt[j * 16 + tx][cc];
#pragma unroll
            for (int i = 0; i < 4; i++)
#pragma unroll
                for (int j = 0; j < 8; j++) acc[i][j] += ir[i] * wr[j];
        }
        __syncthreads();
    }

#pragma unroll
    for (int i = 0; i < 4; i++) {
        int r = row0 + i * 16 + ty;
#pragma unroll
        for (int j = 0; j < 8; j++) {
            int e = j * 16 + tx;
            Z[(size_t)r * DMODEL + e] = acc[i][j] + out_b[e];
        }
    }
}

// ================= launch =================
extern "C" void kernel_launch(void* const* d_in, const int* in_sizes, int n_in,
                              void* d_out, int out_size) {
    const float* x      = (const float*)d_in[0];
    const float* Wq     = (const float*)d_in[1];
    const float* bq     = (const float*)d_in[2];
    const float* Wk     = (const float*)d_in[3];
    const float* bk     = (const float*)d_in[4];
    const float* Wv     = (const float*)d_in[5];
    const float* bv     = (const float*)d_in[6];
    const float* in_w   = (const float*)d_in[7];
    const float* in_b   = (const float*)d_in[8];
    const float* out_w  = (const float*)d_in[9];
    const float* out_b  = (const float*)d_in[10];
    const float* gate_w = (const float*)d_in[11];
    const float* gate_b = (const float*)d_in[12];
    float* Z = (float*)d_out;

    k_swt    <<<BNUM * CIN, 256>>>(x);
    k_compose<<<dim3(9, 32), 256>>>(Wq, bq, Wk, bk, Wv, bv, in_w, in_b);
    k_qkv    <<<dim3(192, 3), 256>>>();
    k_attn   <<<dim3(16, HNUM, SNUM * BNUM), 128>>>();
    k_meanred<<<dim3(SNUM, BNUM, 16), 128>>>();
    k_gate   <<<1, DMODEL>>>(out_w, out_b, gate_w, gate_b);
    k_final  <<<64, 256>>>(out_w, out_b, Z);
}

// round 10
// speedup vs baseline: 1.2251x; 1.1558x over previous
#include <cuda_runtime.h>
#include <cuda_bf16.h>

#define TFULL 2048
#define CIN   64
#define DMODEL 128
#define SNUM  3
#define BNUM  2
#define HNUM  8
#define DH    16

typedef unsigned int uint32;

__device__ __forceinline__ uint32 cvt_tf32(float x) {
    uint32 r; asm("cvt.rna.tf32.f32 %0,%1;" : "=r"(r) : "f"(x)); return r;
}
__device__ __forceinline__ void mma_tf32(float* d, const uint32* a, uint32 b0, uint32 b1) {
    asm volatile("mma.sync.aligned.m16n8k8.row.col.f32.tf32.tf32.f32 "
        "{%0,%1,%2,%3},{%4,%5,%6,%7},{%8,%9},{%0,%1,%2,%3};"
        : "+f"(d[0]), "+f"(d[1]), "+f"(d[2]), "+f"(d[3])
        : "r"(a[0]), "r"(a[1]), "r"(a[2]), "r"(a[3]), "r"(b0), "r"(b1));
}
__device__ __forceinline__ void mma_bf16(float* d, const uint32* a, uint32 b0, uint32 b1) {
    asm volatile("mma.sync.aligned.m16n8k16.row.col.f32.bf16.bf16.f32 "
        "{%0,%1,%2,%3},{%4,%5,%6,%7},{%8,%9},{%0,%1,%2,%3};"
        : "+f"(d[0]), "+f"(d[1]), "+f"(d[2]), "+f"(d[3])
        : "r"(a[0]), "r"(a[1]), "r"(a[2]), "r"(a[3]), "r"(b0), "r"(b1));
}
__device__ __forceinline__ void cp16(uint32 saddr, const void* g) {
    asm volatile("cp.async.cg.shared.global [%0], [%1], 16;" :: "r"(saddr), "l"(g));
}
__device__ __forceinline__ uint32 pkbf(float a, float b) {
    __nv_bfloat162 t = __floats2bfloat162_rn(a, b);   // .x = a (low half = lower k)
    return *reinterpret_cast<uint32*>(&t);
}

// ---------------- wavelet filters ----------------
__constant__ float c_DEC_LO[8] = {
    -0.010597401784997278f,  0.032883011666982945f,  0.030841381835986965f,
    -0.18703481171888114f,  -0.02798376941698385f,   0.6308807679295904f,
     0.7148465705525415f,    0.23037781330885523f };
__constant__ float c_DEC_HI[8] = {
    -0.23037781330885523f,   0.7148465705525415f,   -0.6308807679295904f,
    -0.02798376941698385f,   0.18703481171888114f,   0.030841381835986965f,
    -0.032883011666982945f, -0.010597401784997278f };

// ---------------- scratch ----------------
__device__ float g_W   [SNUM*BNUM*TFULL*CIN];
__device__ float g_A   [SNUM*3*DMODEL*CIN];
__device__ float g_cb  [SNUM*3*DMODEL];
__device__ float g_q   [SNUM*BNUM*TFULL*DMODEL];
__device__ __nv_bfloat16 g_kh16[SNUM*BNUM*TFULL*DMODEL];  // K bf16 hi
__device__ __nv_bfloat16 g_kl16[SNUM*BNUM*TFULL*DMODEL];  // K bf16 lo (residual)
__device__ float g_vt  [SNUM*BNUM*TFULL*DMODEL];          // V tf32-rounded
__device__ float g_o   [SNUM*BNUM*TFULL*DMODEL];
__device__ float g_meanp[SNUM*BNUM*16*DMODEL];
__device__ float g_gate[BNUM*SNUM];

// ================= K0: stationary wavelet transform =================
__global__ void k_swt(const float* __restrict__ x) {
    __shared__ float sh[2][TFULL];
    const int b = blockIdx.x >> 6;
    const int c = blockIdx.x & 63;
    const int tid = threadIdx.x;

    for (int t = tid; t < TFULL; t += 256)
        sh[0][t] = x[(b * TFULL + t) * CIN + c];
    __syncthreads();

    int cur = 0;
    for (int j = 0; j < 3; j++) {
        const int step = 1 << j;
        for (int t = tid; t < TFULL; t += 256) {
            float d = 0.f, a = 0.f;
#pragma unroll
            for (int l = 0; l < 8; l++) {
                float val = sh[cur][(t - l * step) & (TFULL - 1)];
                d += val * c_DEC_HI[l];
                a += val * c_DEC_LO[l];
            }
            g_W[(((2 - j) * BNUM + b) * TFULL + t) * CIN + c] = d;
            sh[cur ^ 1][t] = a;
        }
        __syncthreads();
        cur ^= 1;
    }
}

// ================= K1: compose (in_w x Wqkv) weights + biases =================
__global__ void k_compose(const float* __restrict__ Wq, const float* __restrict__ bq,
                          const float* __restrict__ Wk, const float* __restrict__ bk,
                          const float* __restrict__ Wv, const float* __restrict__ bv,
                          const float* __restrict__ in_w, const float* __restrict__ in_b) {
    const int sw = blockIdx.x;
    const int s = sw / 3, w = sw % 3;
    const float* Wx = (w == 0) ? Wq : (w == 1) ? Wk : Wv;
    const float* bx = (w == 0) ? bq : (w == 1) ? bk : bv;

    const int idx = blockIdx.y * 256 + threadIdx.x;
    const int e = idx >> 6, c = idx & 63;
    const float* iw = in_w + (w * DMODEL + e) * DMODEL;
    const float* wc = Wx + s * DMODEL * CIN + c;
    float acc = 0.f;
#pragma unroll 4
    for (int dd = 0; dd < DMODEL; dd++) acc += iw[dd] * wc[dd * CIN];
    g_A[(sw * DMODEL + e) * CIN + c] = acc;

    if (blockIdx.y == 0 && threadIdx.x < DMODEL) {
        const int ee = threadIdx.x;
        const float* iw2 = in_w + (w * DMODEL + ee) * DMODEL;
        float bb = in_b[w * DMODEL + ee];
#pragma unroll 4
        for (int dd = 0; dd < DMODEL; dd++) bb += iw2[dd] * bx[s * DMODEL + dd];
        g_cb[sw * DMODEL + ee] = bb;
    }
}

// ================= K2: fused q/k/v projection GEMM + pre-conversion =================
// w==0 -> raw Q; w==1 -> K split hi/lo bf16; w==2 -> V rounded tf32.
__global__ void __launch_bounds__(256) k_qkv() {
    __shared__ float shW[64][33];
    __shared__ float shA[128][33];
    const int row0 = blockIdx.x * 64;
    const int w = blockIdx.y;
    const int s = row0 >> 12;
    const int tid = threadIdx.x;
    const int ty = tid >> 4, tx = tid & 15;
    const float* Abase = g_A + (s * 3 + w) * DMODEL * CIN;

    float acc[4][8];
#pragma unroll
    for (int i = 0; i < 4; i++)
#pragma unroll
        for (int j = 0; j < 8; j++) acc[i][j] = 0.f;

    for (int c0 = 0; c0 < CIN; c0 += 32) {
#pragma unroll
        for (int i = 0; i < 8; i++) {
            int lin = tid + i * 256;
            shW[lin >> 5][lin & 31] = g_W[(row0 + (lin >> 5)) * CIN + c0 + (lin & 31)];
        }
#pragma unroll
        for (int i = 0; i < 16; i++) {
            int lin = tid + i * 256;
            shA[lin >> 5][lin & 31] = Abase[(lin >> 5) * CIN + c0 + (lin & 31)];
        }
        __syncthreads();
#pragma unroll
        for (int cc = 0; cc < 32; cc++) {
            float wr[4], ar[8];
#pragma unroll
            for (int i = 0; i < 4; i++) wr[i] = shW[i * 16 + ty][cc];
#pragma unroll
            for (int j = 0; j < 8; j++) ar[j] = shA[j * 16 + tx][cc];
#pragma unroll
            for (int i = 0; i < 4; i++)
#pragma unroll
                for (int j = 0; j < 8; j++) acc[i][j] += wr[i] * ar[j];
        }
        __syncthreads();
    }

    const float* cb = g_cb + (s * 3 + w) * DMODEL;
#pragma unroll
    for (int i = 0; i < 4; i++) {
        int r = row0 + i * 16 + ty;
#pragma unroll
        for (int j = 0; j < 8; j++) {
            int e = j * 16 + tx;
            float val = acc[i][j] + cb[e];
            size_t oidx = (size_t)r * DMODEL + e;
            if (w == 0) {
                g_q[oidx] = val;
            } else if (w == 1) {
                __nv_bfloat16 hb = __float2bfloat16(val);
                g_kh16[oidx] = hb;
                g_kl16[oidx] = __float2bfloat16(val - __bfloat162float(hb));
            } else {
                g_vt[oidx] = __uint_as_float(cvt_tf32(val));
            }
        }
    }
}

// ================= K3: flash attention on tensor cores =================
// QK: bf16 2-term split on m16n8k16 (3 MMAs/nt/g, k=16=DH in one shot).
// PV: tf32 m16n8k8 with sigma-permutation identity mapping (unchanged).
// 32-key chunks, cp.async double-buffered K(hi/lo bf16-packed) + V(tf32).
#define KS16    12      // u32 stride per key row for bf16-packed K (conflict-free)
#define VSTRIDE 24
#define KCH     32
__global__ void k_attn() {
    __shared__ __align__(16) uint32 sKh[2 * KCH * KS16];
    __shared__ __align__(16) uint32 sKl[2 * KCH * KS16];
    __shared__ __align__(16) float  sV [2 * KCH * VSTRIDE];

    const int tid  = threadIdx.x;
    const int warp = tid >> 5, lane = tid & 31;
    const int gid  = lane >> 2, tig = lane & 3;
    const int qt = blockIdx.x, h = blockIdx.y, sb = blockIdx.z;
    const int qbase = qt * 128 + warp * 32;

    const float sc = 0.25f * 1.4426950408889634f;   // 1/sqrt(DH) * log2(e)

    // ---- load Q for both 16-row groups; bf16 hi/lo split, packed pairs ----
    uint32 ahi[2][4], alo[2][4];
#pragma unroll
    for (int g = 0; g < 2; g++) {
#pragma unroll
        for (int rr = 0; rr < 2; rr++) {
            const float* qr = g_q + ((size_t)(sb * TFULL) + qbase + g * 16 + gid + rr * 8) * DMODEL + h * DH;
            float2 pa = *(const float2*)(qr + 2 * tig);
            float2 pb = *(const float2*)(qr + 2 * tig + 8);
            float ax = pa.x * sc, ay = pa.y * sc;
            float bx = pb.x * sc, by = pb.y * sc;
            float axh = __bfloat162float(__float2bfloat16(ax));
            float ayh = __bfloat162float(__float2bfloat16(ay));
            float bxh = __bfloat162float(__float2bfloat16(bx));
            float byh = __bfloat162float(__float2bfloat16(by));
            ahi[g][rr]     = pkbf(axh, ayh);
            alo[g][rr]     = pkbf(ax - axh, ay - ayh);
            ahi[g][rr + 2] = pkbf(bxh, byh);
            alo[g][rr + 2] = pkbf(bx - bxh, by - byh);
        }
    }

    float m_lo[2] = { -1e30f, -1e30f }, m_hi[2] = { -1e30f, -1e30f };
    float l_lo[2] = { 0.f, 0.f },       l_hi[2] = { 0.f, 0.f };
    float oc[2][2][4];
#pragma unroll
    for (int g = 0; g < 2; g++)
#pragma unroll
        for (int nv = 0; nv < 2; nv++)
#pragma unroll
            for (int i = 0; i < 4; i++) oc[g][nv][i] = 0.f;

    const int sigma = (gid >> 1) + ((gid & 1) << 2);   // key-col permutation

    // fill mapping:
    //  tid<64  -> K hi : row=(tid&63)>>1, 16B-half=tid&1
    //  tid>=64 -> K lo : same mapping
    //  all     -> V    : row=tid>>2, 16B-chunk=tid&3
    const int kr = (tid & 63) >> 1, kh2 = tid & 1;
    const int vr = tid >> 2,        vc  = tid & 3;
    const size_t gbase = (size_t)(sb * TFULL) * DMODEL + h * DH;
    const __nv_bfloat16* gK = (tid < 64) ? g_kh16 : g_kl16;
    const uint32 sK_b = (uint32)__cvta_generic_to_shared(tid < 64 ? sKh : sKl)
                        + (kr * KS16 + kh2 * 4) * 4;
    const uint32 sV_b = (uint32)__cvta_generic_to_shared(sV) + (vr * VSTRIDE + vc * 4) * 4;

    const uint32* kh_base = sKh + sigma * KS16 + tig;
    const uint32* kl_base = sKl + sigma * KS16 + tig;
    const float* v0_base = sV + tig * VSTRIDE + gid;
    const float* v1_base = sV + (tig + 4) * VSTRIDE + gid;

    // prefetch chunk 0 into buffer 0
    {
        cp16(sK_b, gK + gbase + (size_t)kr * DMODEL + kh2 * 8);
        cp16(sV_b, g_vt + gbase + (size_t)vr * DMODEL + vc * 4);
        asm volatile("cp.async.commit_group;" ::: "memory");
    }

    for (int c = 0; c < TFULL / KCH; c++) {
        asm volatile("cp.async.wait_group 0;" ::: "memory");
        __syncthreads();
        if (c + 1 < TFULL / KCH) {
            int nb = (c + 1) & 1;
            int rbase = (c + 1) * KCH;
            cp16(sK_b + nb * (KCH * KS16 * 4),
                 gK + gbase + (size_t)(rbase + kr) * DMODEL + kh2 * 8);
            cp16(sV_b + nb * (KCH * VSTRIDE * 4),
                 g_vt + gbase + (size_t)(rbase + vr) * DMODEL + vc * 4);
            asm volatile("cp.async.commit_group;" ::: "memory");
        }
        const int buf = c & 1;
        const uint32* khB = kh_base + buf * (KCH * KS16);
        const uint32* klB = kl_base + buf * (KCH * KS16);
        const float* v0B = v0_base + buf * (KCH * VSTRIDE);
        const float* v1B = v1_base + buf * (KCH * VSTRIDE);

        // ---- S = Q K^T: qhi*khi + qhi*klo + qlo*khi (bf16 m16n8k16) ----
        float cS[2][4][4];
#pragma unroll
        for (int nt = 0; nt < 4; nt++) {
#pragma unroll
            for (int g = 0; g < 2; g++) {
                cS[g][nt][0] = 0.f; cS[g][nt][1] = 0.f;
                cS[g][nt][2] = 0.f; cS[g][nt][3] = 0.f;
            }
            uint32 b0h = khB[nt * 8 * KS16];
            uint32 b1h = khB[nt * 8 * KS16 + 4];
            uint32 b0l = klB[nt * 8 * KS16];
            uint32 b1l = klB[nt * 8 * KS16 + 4];
#pragma unroll
            for (int g = 0; g < 2; g++) {
                mma_bf16(cS[g][nt], ahi[g], b0h, b1h);
                mma_bf16(cS[g][nt], ahi[g], b0l, b1l);
                mma_bf16(cS[g][nt], alo[g], b0h, b1h);
            }
        }

        // ---- online softmax per group; p converted in place to tf32 ----
#pragma unroll
        for (int g = 0; g < 2; g++) {
            float mx0 = m_lo[g], mx1 = m_hi[g];
#pragma unroll
            for (int nt = 0; nt < 4; nt++) {
                mx0 = fmaxf(mx0, fmaxf(cS[g][nt][0], cS[g][nt][1]));
                mx1 = fmaxf(mx1, fmaxf(cS[g][nt][2], cS[g][nt][3]));
            }
            mx0 = fmaxf(mx0, __shfl_xor_sync(0xffffffffu, mx0, 1));
            mx0 = fmaxf(mx0, __shfl_xor_sync(0xffffffffu, mx0, 2));
            mx1 = fmaxf(mx1, __shfl_xor_sync(0xffffffffu, mx1, 1));
            mx1 = fmaxf(mx1, __shfl_xor_sync(0xffffffffu, mx1, 2));
            float cr0 = exp2f(m_lo[g] - mx0), cr1 = exp2f(m_hi[g] - mx1);
            m_lo[g] = mx0; m_hi[g] = mx1;
            l_lo[g] *= cr0; l_hi[g] *= cr1;
#pragma unroll
            for (int nv = 0; nv < 2; nv++) {
                oc[g][nv][0] *= cr0; oc[g][nv][1] *= cr0;
                oc[g][nv][2] *= cr1; oc[g][nv][3] *= cr1;
            }
#pragma unroll
            for (int nt = 0; nt < 4; nt++) {
                float p0 = exp2f(cS[g][nt][0] - mx0);
                float p1 = exp2f(cS[g][nt][1] - mx0);
                float p2 = exp2f(cS[g][nt][2] - mx1);
                float p3 = exp2f(cS[g][nt][3] - mx1);
                l_lo[g] += p0 + p1;
                l_hi[g] += p2 + p3;
                cS[g][nt][0] = __uint_as_float(cvt_tf32(p0));
                cS[g][nt][1] = __uint_as_float(cvt_tf32(p1));
                cS[g][nt][2] = __uint_as_float(cvt_tf32(p2));
                cS[g][nt][3] = __uint_as_float(cvt_tf32(p3));
            }
        }

        // ---- O += P V (tf32 m16n8k8; one V load feeds 4 MMAs) ----
#pragma unroll
        for (int j = 0; j < 4; j++) {
            const float* v0 = v0B + 8 * j * VSTRIDE;
            const float* v1 = v1B + 8 * j * VSTRIDE;
            uint32 b0a = __float_as_uint(v0[0]);
            uint32 b1a = __float_as_uint(v1[0]);
            uint32 b0b = __float_as_uint(v0[8]);
            uint32 b1b = __float_as_uint(v1[8]);
#pragma unroll
            for (int g = 0; g < 2; g++) {
                uint32 ap[4] = { __float_as_uint(cS[g][j][0]), __float_as_uint(cS[g][j][2]),
                                 __float_as_uint(cS[g][j][1]), __float_as_uint(cS[g][j][3]) };
                mma_tf32(oc[g][0], ap, b0a, b1a);
                mma_tf32(oc[g][1], ap, b0b, b1b);
            }
        }
    }

    // ---- finalize both groups ----
#pragma unroll
    for (int g = 0; g < 2; g++) {
        float ll = l_lo[g], lh = l_hi[g];
        ll += __shfl_xor_sync(0xffffffffu, ll, 1);
        ll += __shfl_xor_sync(0xffffffffu, ll, 2);
        lh += __shfl_xor_sync(0xffffffffu, lh, 1);
        lh += __shfl_xor_sync(0xffffffffu, lh, 2);
        float inv_lo = 1.f / ll;
        float inv_hi = 1.f / lh;

        float* ob = g_o + ((size_t)(sb * TFULL) + qbase + g * 16 + gid) * DMODEL + h * DH;
#pragma unroll
        for (int nv = 0; nv < 2; nv++) {
            *(float2*)(ob + 2 * tig + 8 * nv) =
                make_float2(oc[g][nv][0] * inv_lo, oc[g][nv][1] * inv_lo);
            *(float2*)(ob + 8 * DMODEL + 2 * tig + 8 * nv) =
                make_float2(oc[g][nv][2] * inv_hi, oc[g][nv][3] * inv_hi);
        }
    }
}

// ================= K4: partial t-sums =================
__global__ void k_meanred() {
    const int s = blockIdx.x, b = blockIdx.y, ch = blockIdx.z;
    const int d = threadIdx.x;
    const float* base = g_o + (((size_t)(s * BNUM + b) * TFULL) + ch * 128) * DMODEL + d;
    float sum = 0.f;
#pragma unroll 8
    for (int t = 0; t < 128; t++) sum += base[t * DMODEL];
    g_meanp[((s * BNUM + b) * 16 + ch) * DMODEL + d] = sum;
}

// ================= K5: gate computation =================
__global__ void k_gate(const float* __restrict__ out_w, const float* __restrict__ out_b,
                       const float* __restrict__ gate_w, const float* __restrict__ gate_b) {
    __shared__ float sh_m[DMODEL];
    __shared__ float sh_gf[DMODEL];
    __shared__ float sh_lg[SNUM];
    const int d = threadIdx.x;
    for (int b = 0; b < BNUM; b++) {
        float mv = 0.f;
#pragma unroll
        for (int s = 0; s < SNUM; s++)
#pragma unroll
            for (int c = 0; c < 16; c++)
                mv += g_meanp[((s * BNUM + b) * 16 + c) * DMODEL + d];
        sh_m[d] = mv;
        __syncthreads();
        float acc = 0.f;
        const float* ow = out_w + d * DMODEL;
#pragma unroll 4
        for (int dd = 0; dd < DMODEL; dd++) acc += ow[dd] * sh_m[dd];
        sh_gf[d] = acc * (1.0f / (TFULL * SNUM)) + out_b[d];
        __syncthreads();
        if (d < SNUM) {
            float lg = gate_b[d];
            for (int dd = 0; dd < DMODEL; dd++) lg += sh_gf[dd] * gate_w[d * DMODEL + dd];
            sh_lg[d] = lg;
        }
        __syncthreads();
        if (d == 0) {
            float mx = fmaxf(sh_lg[0], fmaxf(sh_lg[1], sh_lg[2]));
            float e0 = __expf(sh_lg[0] - mx);
            float e1 = __expf(sh_lg[1] - mx);
            float e2 = __expf(sh_lg[2] - mx);
            float inv = 1.f / (e0 + e1 + e2);
            g_gate[b * 3 + 0] = e0 * inv;
            g_gate[b * 3 + 1] = e1 * inv;
            g_gate[b * 3 + 2] = e2 * inv;
        }
        __syncthreads();
    }
}

// ================= K6: gated combine + output projection =================
__global__ void __launch_bounds__(256) k_final(const float* __restrict__ out_w,
                                               const float* __restrict__ out_b,
                                               float* __restrict__ Z) {
    __shared__ float shI[64][33];
    __shared__ float shWt[128][33];
    const int row0 = blockIdx.x * 64;
    const int tid = threadIdx.x;
    const int b = row0 >> 11;
    const float gt0 = g_gate[b * 3 + 0];
    const float gt1 = g_gate[b * 3 + 1];
    const float gt2 = g_gate[b * 3 + 2];
    const int ty = tid >> 4, tx = tid & 15;
    const size_t SB = (size_t)BNUM * TFULL * DMODEL;

    float acc[4][8];
#pragma unroll
    for (int i = 0; i < 4; i++)
#pragma unroll
        for (int j = 0; j < 8; j++) acc[i][j] = 0.f;

    for (int c0 = 0; c0 < DMODEL; c0 += 32) {
#pragma unroll
        for (int i = 0; i < 8; i++) {
            int lin = tid + i * 256;
            int rr = lin >> 5, cc = lin & 31;
            size_t idx = (size_t)(row0 + rr) * DMODEL + c0 + cc;
            float v0 = g_o[idx];
            float v1 = g_o[SB + idx];
            float v2 = g_o[2 * SB + idx];
            shI[rr][cc] = gt0 * v0 + gt1 * v1 + gt2 * v2;
        }
#pragma unroll
        for (int i = 0; i < 16; i++) {
            int lin = tid + i * 256;
            shWt[lin >> 5][lin & 31] = out_w[(lin >> 5) * DMODEL + c0 + (lin & 31)];
        }
        __syncthreads();
#pragma unroll
        for (int cc = 0; cc < 32; cc++) {
            float ir[4], wr[8];
#pragma unroll
            for (int i = 0; i < 4; i++) ir[i] = shI[i * 16 + ty][cc];
#pragma unroll
            for (int j = 0; j < 8; j++) wr[j] = shWt[j * 16 + tx][cc];
#pragma unroll
            for (int i = 0; i < 4; i++)
#pragma unroll
                for (int j = 0; j < 8; j++) acc[i][j] += ir[i] * wr[j];
        }
        __syncthreads();
    }

#pragma unroll
    for (int i = 0; i < 4; i++) {
        int r = row0 + i * 16 + ty;
#pragma unroll
        for (int j = 0; j < 8; j++) {
            int e = j * 16 + tx;
            Z[(size_t)r * DMODEL + e] = acc[i][j] + out_b[e];
        }
    }
}

// ================= launch =================
extern "C" void kernel_launch(void* const* d_in, const int* in_sizes, int n_in,
                              void* d_out, int out_size) {
    const float* x      = (const float*)d_in[0];
    const float* Wq     = (const float*)d_in[1];
    const float* bq     = (const float*)d_in[2];
    const float* Wk     = (const float*)d_in[3];
    const float* bk     = (const float*)d_in[4];
    const float* Wv     = (const float*)d_in[5];
    const float* bv     = (const float*)d_in[6];
    const float* in_w   = (const float*)d_in[7];
    const float* in_b   = (const float*)d_in[8];
    const float* out_w  = (const float*)d_in[9];
    const float* out_b  = (const float*)d_in[10];
    const float* gate_w = (const float*)d_in[11];
    const float* gate_b = (const float*)d_in[12];
    float* Z = (float*)d_out;

    k_swt    <<<BNUM * CIN, 256>>>(x);
    k_compose<<<dim3(9, 32), 256>>>(Wq, bq, Wk, bk, Wv, bv, in_w, in_b);
    k_qkv    <<<dim3(192, 3), 256>>>();
    k_attn   <<<dim3(16, HNUM, SNUM * BNUM), 128>>>();
    k_meanred<<<dim3(SNUM, BNUM, 16), 128>>>();
    k_gate   <<<1, DMODEL>>>(out_w, out_b, gate_w, gate_b);
    k_final  <<<64, 256>>>(out_w, out_b, Z);
}

// round 11
// speedup vs baseline: 1.3480x; 1.1003x over previous
#include <cuda_runtime.h>
#include <cuda_bf16.h>

#define TFULL 2048
#define CIN   64
#define DMODEL 128
#define SNUM  3
#define BNUM  2
#define HNUM  8
#define DH    16
#define KHALF 1024

typedef unsigned int uint32;

__device__ __forceinline__ uint32 cvt_tf32(float x) {
    uint32 r; asm("cvt.rna.tf32.f32 %0,%1;" : "=r"(r) : "f"(x)); return r;
}
__device__ __forceinline__ void mma_tf32(float* d, const uint32* a, uint32 b0, uint32 b1) {
    asm volatile("mma.sync.aligned.m16n8k8.row.col.f32.tf32.tf32.f32 "
        "{%0,%1,%2,%3},{%4,%5,%6,%7},{%8,%9},{%0,%1,%2,%3};"
        : "+f"(d[0]), "+f"(d[1]), "+f"(d[2]), "+f"(d[3])
        : "r"(a[0]), "r"(a[1]), "r"(a[2]), "r"(a[3]), "r"(b0), "r"(b1));
}
__device__ __forceinline__ void mma_bf16(float* d, const uint32* a, uint32 b0, uint32 b1) {
    asm volatile("mma.sync.aligned.m16n8k16.row.col.f32.bf16.bf16.f32 "
        "{%0,%1,%2,%3},{%4,%5,%6,%7},{%8,%9},{%0,%1,%2,%3};"
        : "+f"(d[0]), "+f"(d[1]), "+f"(d[2]), "+f"(d[3])
        : "r"(a[0]), "r"(a[1]), "r"(a[2]), "r"(a[3]), "r"(b0), "r"(b1));
}
__device__ __forceinline__ void cp16(uint32 saddr, const void* g) {
    asm volatile("cp.async.cg.shared.global [%0], [%1], 16;" :: "r"(saddr), "l"(g));
}
__device__ __forceinline__ uint32 pkbf(float a, float b) {
    __nv_bfloat162 t = __floats2bfloat162_rn(a, b);
    return *reinterpret_cast<uint32*>(&t);
}

// ---------------- wavelet filters ----------------
__constant__ float c_DEC_LO[8] = {
    -0.010597401784997278f,  0.032883011666982945f,  0.030841381835986965f,
    -0.18703481171888114f,  -0.02798376941698385f,   0.6308807679295904f,
     0.7148465705525415f,    0.23037781330885523f };
__constant__ float c_DEC_HI[8] = {
    -0.23037781330885523f,   0.7148465705525415f,   -0.6308807679295904f,
    -0.02798376941698385f,   0.18703481171888114f,   0.030841381835986965f,
    -0.032883011666982945f, -0.010597401784997278f };

// ---------------- scratch ----------------
__device__ float g_W   [SNUM*BNUM*TFULL*CIN];
__device__ float g_A   [SNUM*3*DMODEL*CIN];
__device__ float g_cb  [SNUM*3*DMODEL];
__device__ float g_q   [SNUM*BNUM*TFULL*DMODEL];
__device__ __nv_bfloat16 g_kh16[SNUM*BNUM*TFULL*DMODEL];  // K bf16 hi
__device__ __nv_bfloat16 g_kl16[SNUM*BNUM*TFULL*DMODEL];  // K bf16 lo (residual)
__device__ float g_vt  [SNUM*BNUM*TFULL*DMODEL];          // V tf32-rounded
__device__ float g_o   [SNUM*BNUM*TFULL*DMODEL];
__device__ float g_pacc[2*SNUM*BNUM*TFULL*DMODEL];        // split-K unnormalized acc
__device__ float g_pml [2*SNUM*BNUM*TFULL*HNUM*2];        // split-K (m,l) per row/head
__device__ float g_meanp[SNUM*BNUM*16*DMODEL];
__device__ float g_gate[BNUM*SNUM];

// ================= K0: stationary wavelet transform =================
__global__ void k_swt(const float* __restrict__ x) {
    __shared__ float sh[2][TFULL];
    const int b = blockIdx.x >> 6;
    const int c = blockIdx.x & 63;
    const int tid = threadIdx.x;

    for (int t = tid; t < TFULL; t += 256)
        sh[0][t] = x[(b * TFULL + t) * CIN + c];
    __syncthreads();

    int cur = 0;
    for (int j = 0; j < 3; j++) {
        const int step = 1 << j;
        for (int t = tid; t < TFULL; t += 256) {
            float d = 0.f, a = 0.f;
#pragma unroll
            for (int l = 0; l < 8; l++) {
                float val = sh[cur][(t - l * step) & (TFULL - 1)];
                d += val * c_DEC_HI[l];
                a += val * c_DEC_LO[l];
            }
            g_W[(((2 - j) * BNUM + b) * TFULL + t) * CIN + c] = d;
            sh[cur ^ 1][t] = a;
        }
        __syncthreads();
        cur ^= 1;
    }
}

// ================= K1: compose (in_w x Wqkv) weights + biases =================
__global__ void k_compose(const float* __restrict__ Wq, const float* __restrict__ bq,
                          const float* __restrict__ Wk, const float* __restrict__ bk,
                          const float* __restrict__ Wv, const float* __restrict__ bv,
                          const float* __restrict__ in_w, const float* __restrict__ in_b) {
    const int sw = blockIdx.x;
    const int s = sw / 3, w = sw % 3;
    const float* Wx = (w == 0) ? Wq : (w == 1) ? Wk : Wv;
    const float* bx = (w == 0) ? bq : (w == 1) ? bk : bv;

    const int idx = blockIdx.y * 256 + threadIdx.x;
    const int e = idx >> 6, c = idx & 63;
    const float* iw = in_w + (w * DMODEL + e) * DMODEL;
    const float* wc = Wx + s * DMODEL * CIN + c;
    float acc = 0.f;
#pragma unroll 4
    for (int dd = 0; dd < DMODEL; dd++) acc += iw[dd] * wc[dd * CIN];
    g_A[(sw * DMODEL + e) * CIN + c] = acc;

    if (blockIdx.y == 0 && threadIdx.x < DMODEL) {
        const int ee = threadIdx.x;
        const float* iw2 = in_w + (w * DMODEL + ee) * DMODEL;
        float bb = in_b[w * DMODEL + ee];
#pragma unroll 4
        for (int dd = 0; dd < DMODEL; dd++) bb += iw2[dd] * bx[s * DMODEL + dd];
        g_cb[sw * DMODEL + ee] = bb;
    }
}

// ================= K2: fused q/k/v projection GEMM + pre-conversion =================
__global__ void __launch_bounds__(256) k_qkv() {
    __shared__ float shW[64][33];
    __shared__ float shA[128][33];
    const int row0 = blockIdx.x * 64;
    const int w = blockIdx.y;
    const int s = row0 >> 12;
    const int tid = threadIdx.x;
    const int ty = tid >> 4, tx = tid & 15;
    const float* Abase = g_A + (s * 3 + w) * DMODEL * CIN;

    float acc[4][8];
#pragma unroll
    for (int i = 0; i < 4; i++)
#pragma unroll
        for (int j = 0; j < 8; j++) acc[i][j] = 0.f;

    for (int c0 = 0; c0 < CIN; c0 += 32) {
#pragma unroll
        for (int i = 0; i < 8; i++) {
            int lin = tid + i * 256;
            shW[lin >> 5][lin & 31] = g_W[(row0 + (lin >> 5)) * CIN + c0 + (lin & 31)];
        }
#pragma unroll
        for (int i = 0; i < 16; i++) {
            int lin = tid + i * 256;
            shA[lin >> 5][lin & 31] = Abase[(lin >> 5) * CIN + c0 + (lin & 31)];
        }
        __syncthreads();
#pragma unroll
        for (int cc = 0; cc < 32; cc++) {
            float wr[4], ar[8];
#pragma unroll
            for (int i = 0; i < 4; i++) wr[i] = shW[i * 16 + ty][cc];
#pragma unroll
            for (int j = 0; j < 8; j++) ar[j] = shA[j * 16 + tx][cc];
#pragma unroll
            for (int i = 0; i < 4; i++)
#pragma unroll
                for (int j = 0; j < 8; j++) acc[i][j] += wr[i] * ar[j];
        }
        __syncthreads();
    }

    const float* cb = g_cb + (s * 3 + w) * DMODEL;
#pragma unroll
    for (int i = 0; i < 4; i++) {
        int r = row0 + i * 16 + ty;
#pragma unroll
        for (int j = 0; j < 8; j++) {
            int e = j * 16 + tx;
            float val = acc[i][j] + cb[e];
            size_t oidx = (size_t)r * DMODEL + e;
            if (w == 0) {
                g_q[oidx] = val;
            } else if (w == 1) {
                __nv_bfloat16 hb = __float2bfloat16(val);
                g_kh16[oidx] = hb;
                g_kl16[oidx] = __float2bfloat16(val - __bfloat162float(hb));
            } else {
                g_vt[oidx] = __uint_as_float(cvt_tf32(val));
            }
        }
    }
}

// ================= K3: flash attention, split-K x2, bf16 QK + tf32 PV =================
// grid: (16 q-tiles of 128, 8 heads, 6 s*b * 2 key-halves). block 128.
#define KS16    12
#define VSTRIDE 24
#define KCH     32
__global__ void k_attn() {
    __shared__ __align__(16) uint32 sKh[2 * KCH * KS16];
    __shared__ __align__(16) uint32 sKl[2 * KCH * KS16];
    __shared__ __align__(16) float  sV [2 * KCH * VSTRIDE];

    const int tid  = threadIdx.x;
    const int warp = tid >> 5, lane = tid & 31;
    const int gid  = lane >> 2, tig = lane & 3;
    const int qt = blockIdx.x, h = blockIdx.y;
    const int sb = blockIdx.z >> 1, kh = blockIdx.z & 1;
    const int qbase = qt * 128 + warp * 32;
    const int kbeg = kh * KHALF;

    const float sc = 0.25f * 1.4426950408889634f;

    // ---- load Q for both 16-row groups; bf16 hi/lo split, packed pairs ----
    uint32 ahi[2][4], alo[2][4];
#pragma unroll
    for (int g = 0; g < 2; g++) {
#pragma unroll
        for (int rr = 0; rr < 2; rr++) {
            const float* qr = g_q + ((size_t)(sb * TFULL) + qbase + g * 16 + gid + rr * 8) * DMODEL + h * DH;
            float2 pa = *(const float2*)(qr + 2 * tig);
            float2 pb = *(const float2*)(qr + 2 * tig + 8);
            float ax = pa.x * sc, ay = pa.y * sc;
            float bx = pb.x * sc, by = pb.y * sc;
            float axh = __bfloat162float(__float2bfloat16(ax));
            float ayh = __bfloat162float(__float2bfloat16(ay));
            float bxh = __bfloat162float(__float2bfloat16(bx));
            float byh = __bfloat162float(__float2bfloat16(by));
            ahi[g][rr]     = pkbf(axh, ayh);
            alo[g][rr]     = pkbf(ax - axh, ay - ayh);
            ahi[g][rr + 2] = pkbf(bxh, byh);
            alo[g][rr + 2] = pkbf(bx - bxh, by - byh);
        }
    }

    float m_lo[2] = { -1e30f, -1e30f }, m_hi[2] = { -1e30f, -1e30f };
    float l_lo[2] = { 0.f, 0.f },       l_hi[2] = { 0.f, 0.f };
    float oc[2][2][4];
#pragma unroll
    for (int g = 0; g < 2; g++)
#pragma unroll
        for (int nv = 0; nv < 2; nv++)
#pragma unroll
            for (int i = 0; i < 4; i++) oc[g][nv][i] = 0.f;

    const int sigma = (gid >> 1) + ((gid & 1) << 2);

    const int kr = (tid & 63) >> 1, kh2 = tid & 1;
    const int vr = tid >> 2,        vc  = tid & 3;
    const size_t gbase = (size_t)(sb * TFULL) * DMODEL + h * DH;
    const __nv_bfloat16* gK = (tid < 64) ? g_kh16 : g_kl16;
    const uint32 sK_b = (uint32)__cvta_generic_to_shared(tid < 64 ? sKh : sKl)
                        + (kr * KS16 + kh2 * 4) * 4;
    const uint32 sV_b = (uint32)__cvta_generic_to_shared(sV) + (vr * VSTRIDE + vc * 4) * 4;

    const uint32* kh_base = sKh + sigma * KS16 + tig;
    const uint32* kl_base = sKl + sigma * KS16 + tig;
    const float* v0_base = sV + tig * VSTRIDE + gid;
    const float* v1_base = sV + (tig + 4) * VSTRIDE + gid;

    // prefetch chunk 0
    {
        cp16(sK_b, gK + gbase + (size_t)(kbeg + kr) * DMODEL + kh2 * 8);
        cp16(sV_b, g_vt + gbase + (size_t)(kbeg + vr) * DMODEL + vc * 4);
        asm volatile("cp.async.commit_group;" ::: "memory");
    }

    for (int c = 0; c < KHALF / KCH; c++) {
        asm volatile("cp.async.wait_group 0;" ::: "memory");
        __syncthreads();
        if (c + 1 < KHALF / KCH) {
            int nb = (c + 1) & 1;
            int rbase = kbeg + (c + 1) * KCH;
            cp16(sK_b + nb * (KCH * KS16 * 4),
                 gK + gbase + (size_t)(rbase + kr) * DMODEL + kh2 * 8);
            cp16(sV_b + nb * (KCH * VSTRIDE * 4),
                 g_vt + gbase + (size_t)(rbase + vr) * DMODEL + vc * 4);
            asm volatile("cp.async.commit_group;" ::: "memory");
        }
        const int buf = c & 1;
        const uint32* khB = kh_base + buf * (KCH * KS16);
        const uint32* klB = kl_base + buf * (KCH * KS16);
        const float* v0B = v0_base + buf * (KCH * VSTRIDE);
        const float* v1B = v1_base + buf * (KCH * VSTRIDE);

        // ---- S = Q K^T: qhi*khi + qhi*klo + qlo*khi (bf16 m16n8k16) ----
        float cS[2][4][4];
#pragma unroll
        for (int nt = 0; nt < 4; nt++) {
#pragma unroll
            for (int g = 0; g < 2; g++) {
                cS[g][nt][0] = 0.f; cS[g][nt][1] = 0.f;
                cS[g][nt][2] = 0.f; cS[g][nt][3] = 0.f;
            }
            uint32 b0h = khB[nt * 8 * KS16];
            uint32 b1h = khB[nt * 8 * KS16 + 4];
            uint32 b0l = klB[nt * 8 * KS16];
            uint32 b1l = klB[nt * 8 * KS16 + 4];
#pragma unroll
            for (int g = 0; g < 2; g++) {
                mma_bf16(cS[g][nt], ahi[g], b0h, b1h);
                mma_bf16(cS[g][nt], ahi[g], b0l, b1l);
                mma_bf16(cS[g][nt], alo[g], b0h, b1h);
            }
        }

        // ---- online softmax; p left as raw f32 (MMA truncates to tf32) ----
#pragma unroll
        for (int g = 0; g < 2; g++) {
            float mx0 = m_lo[g], mx1 = m_hi[g];
#pragma unroll
            for (int nt = 0; nt < 4; nt++) {
                mx0 = fmaxf(mx0, fmaxf(cS[g][nt][0], cS[g][nt][1]));
                mx1 = fmaxf(mx1, fmaxf(cS[g][nt][2], cS[g][nt][3]));
            }
            mx0 = fmaxf(mx0, __shfl_xor_sync(0xffffffffu, mx0, 1));
            mx0 = fmaxf(mx0, __shfl_xor_sync(0xffffffffu, mx0, 2));
            mx1 = fmaxf(mx1, __shfl_xor_sync(0xffffffffu, mx1, 1));
            mx1 = fmaxf(mx1, __shfl_xor_sync(0xffffffffu, mx1, 2));
            float cr0 = exp2f(m_lo[g] - mx0), cr1 = exp2f(m_hi[g] - mx1);
            m_lo[g] = mx0; m_hi[g] = mx1;
            l_lo[g] *= cr0; l_hi[g] *= cr1;
#pragma unroll
            for (int nv = 0; nv < 2; nv++) {
                oc[g][nv][0] *= cr0; oc[g][nv][1] *= cr0;
                oc[g][nv][2] *= cr1; oc[g][nv][3] *= cr1;
            }
#pragma unroll
            for (int nt = 0; nt < 4; nt++) {
                float p0 = exp2f(cS[g][nt][0] - mx0);
                float p1 = exp2f(cS[g][nt][1] - mx0);
                float p2 = exp2f(cS[g][nt][2] - mx1);
                float p3 = exp2f(cS[g][nt][3] - mx1);
                l_lo[g] += p0 + p1;
                l_hi[g] += p2 + p3;
                cS[g][nt][0] = p0;
                cS[g][nt][1] = p1;
                cS[g][nt][2] = p2;
                cS[g][nt][3] = p3;
            }
        }

        // ---- O += P V (tf32 m16n8k8) ----
#pragma unroll
        for (int j = 0; j < 4; j++) {
            const float* v0 = v0B + 8 * j * VSTRIDE;
            const float* v1 = v1B + 8 * j * VSTRIDE;
            uint32 b0a = __float_as_uint(v0[0]);
            uint32 b1a = __float_as_uint(v1[0]);
            uint32 b0b = __float_as_uint(v0[8]);
            uint32 b1b = __float_as_uint(v1[8]);
#pragma unroll
            for (int g = 0; g < 2; g++) {
                uint32 ap[4] = { __float_as_uint(cS[g][j][0]), __float_as_uint(cS[g][j][2]),
                                 __float_as_uint(cS[g][j][1]), __float_as_uint(cS[g][j][3]) };
                mma_tf32(oc[g][0], ap, b0a, b1a);
                mma_tf32(oc[g][1], ap, b0b, b1b);
            }
        }
    }

    // ---- write split-K partials (unnormalized) + (m,l) ----
#pragma unroll
    for (int g = 0; g < 2; g++) {
        float ll = l_lo[g], lh = l_hi[g];
        ll += __shfl_xor_sync(0xffffffffu, ll, 1);
        ll += __shfl_xor_sync(0xffffffffu, ll, 2);
        lh += __shfl_xor_sync(0xffffffffu, lh, 1);
        lh += __shfl_xor_sync(0xffffffffu, lh, 2);

        const int r1 = qbase + g * 16 + gid;   // rows r1 (lo) and r1+8 (hi)
        float* pb = g_pacc + (((size_t)(kh * (SNUM * BNUM) + sb)) * TFULL + r1) * DMODEL + h * DH;
#pragma unroll
        for (int nv = 0; nv < 2; nv++) {
            *(float2*)(pb + 2 * tig + 8 * nv) =
                make_float2(oc[g][nv][0], oc[g][nv][1]);
            *(float2*)(pb + 8 * DMODEL + 2 * tig + 8 * nv) =
                make_float2(oc[g][nv][2], oc[g][nv][3]);
        }
        if (tig == 0) {
            float2* pml = (float2*)g_pml;
            size_t base = ((size_t)(kh * (SNUM * BNUM) + sb)) * TFULL;
            pml[(base + r1) * HNUM + h]     = make_float2(m_lo[g], ll);
            pml[(base + r1 + 8) * HNUM + h] = make_float2(m_hi[g], lh);
        }
    }
}

// ================= K3b: merge split-K halves =================
// one thread per (sb,t,h): 6*2048*8 = 98304 threads.
__global__ void k_merge() {
    const int idx = blockIdx.x * 256 + threadIdx.x;
    const int h = idx & 7;
    const int t = (idx >> 3) & (TFULL - 1);
    const int sb = idx >> 14;
    const size_t r0 = (size_t)sb * TFULL + t;
    const size_t r1 = (size_t)(SNUM * BNUM + sb) * TFULL + t;

    float2 ml0 = ((const float2*)g_pml)[r0 * HNUM + h];
    float2 ml1 = ((const float2*)g_pml)[r1 * HNUM + h];
    float M = fmaxf(ml0.x, ml1.x);
    float e0 = exp2f(ml0.x - M);
    float e1 = exp2f(ml1.x - M);
    float inv = 1.f / (e0 * ml0.y + e1 * ml1.y);
    e0 *= inv; e1 *= inv;

    const float* p0 = g_pacc + r0 * DMODEL + h * DH;
    const float* p1 = g_pacc + r1 * DMODEL + h * DH;
    float* ob = g_o + ((size_t)sb * TFULL + t) * DMODEL + h * DH;
#pragma unroll
    for (int i = 0; i < 4; i++) {
        float4 a = *(const float4*)(p0 + i * 4);
        float4 b = *(const float4*)(p1 + i * 4);
        *(float4*)(ob + i * 4) = make_float4(a.x * e0 + b.x * e1,
                                             a.y * e0 + b.y * e1,
                                             a.z * e0 + b.z * e1,
                                             a.w * e0 + b.w * e1);
    }
}

// ================= K4: partial t-sums =================
__global__ void k_meanred() {
    const int s = blockIdx.x, b = blockIdx.y, ch = blockIdx.z;
    const int d = threadIdx.x;
    const float* base = g_o + (((size_t)(s * BNUM + b) * TFULL) + ch * 128) * DMODEL + d;
    float sum = 0.f;
#pragma unroll 8
    for (int t = 0; t < 128; t++) sum += base[t * DMODEL];
    g_meanp[((s * BNUM + b) * 16 + ch) * DMODEL + d] = sum;
}

// ================= K5: gate computation =================
__global__ void k_gate(const float* __restrict__ out_w, const float* __restrict__ out_b,
                       const float* __restrict__ gate_w, const float* __restrict__ gate_b) {
    __shared__ float sh_m[DMODEL];
    __shared__ float sh_gf[DMODEL];
    __shared__ float sh_lg[SNUM];
    const int d = threadIdx.x;
    for (int b = 0; b < BNUM; b++) {
        float mv = 0.f;
#pragma unroll
        for (int s = 0; s < SNUM; s++)
#pragma unroll
            for (int c = 0; c < 16; c++)
                mv += g_meanp[((s * BNUM + b) * 16 + c) * DMODEL + d];
        sh_m[d] = mv;
        __syncthreads();
        float acc = 0.f;
        const float* ow = out_w + d * DMODEL;
#pragma unroll 4
        for (int dd = 0; dd < DMODEL; dd++) acc += ow[dd] * sh_m[dd];
        sh_gf[d] = acc * (1.0f / (TFULL * SNUM)) + out_b[d];
        __syncthreads();
        if (d < SNUM) {
            float lg = gate_b[d];
            for (int dd = 0; dd < DMODEL; dd++) lg += sh_gf[dd] * gate_w[d * DMODEL + dd];
            sh_lg[d] = lg;
        }
        __syncthreads();
        if (d == 0) {
            float mx = fmaxf(sh_lg[0], fmaxf(sh_lg[1], sh_lg[2]));
            float e0 = __expf(sh_lg[0] - mx);
            float e1 = __expf(sh_lg[1] - mx);
            float e2 = __expf(sh_lg[2] - mx);
            float inv = 1.f / (e0 + e1 + e2);
            g_gate[b * 3 + 0] = e0 * inv;
            g_gate[b * 3 + 1] = e1 * inv;
            g_gate[b * 3 + 2] = e2 * inv;
        }
        __syncthreads();
    }
}

// ================= K6: gated combine + output projection (128 blocks) =================
__global__ void __launch_bounds__(256) k_final(const float* __restrict__ out_w,
                                               const float* __restrict__ out_b,
                                               float* __restrict__ Z) {
    __shared__ float shI[32][33];
    __shared__ float shWt[128][33];
    const int row0 = blockIdx.x * 32;          // 128 blocks over 4096 rows
    const int tid = threadIdx.x;
    const int b = row0 >> 11;
    const float gt0 = g_gate[b * 3 + 0];
    const float gt1 = g_gate[b * 3 + 1];
    const float gt2 = g_gate[b * 3 + 2];
    const int ty = tid >> 4, tx = tid & 15;
    const size_t SB = (size_t)BNUM * TFULL * DMODEL;

    float acc[2][8];
#pragma unroll
    for (int i = 0; i < 2; i++)
#pragma unroll
        for (int j = 0; j < 8; j++) acc[i][j] = 0.f;

    for (int c0 = 0; c0 < DMODEL; c0 += 32) {
#pragma unroll
        for (int i = 0; i < 4; i++) {          // 32x32 combined-input tile
            int lin = tid + i * 256;
            int rr = lin >> 5, cc = lin & 31;
            size_t idx = (size_t)(row0 + rr) * DMODEL + c0 + cc;
            float v0 = g_o[idx];
            float v1 = g_o[SB + idx];
            float v2 = g_o[2 * SB + idx];
            shI[rr][cc] = gt0 * v0 + gt1 * v1 + gt2 * v2;
        }
#pragma unroll
        for (int i = 0; i < 16; i++) {         // 128x32 out_w tile
            int lin = tid + i * 256;
            shWt[lin >> 5][lin & 31] = out_w[(lin >> 5) * DMODEL + c0 + (lin & 31)];
        }
        __syncthreads();
#pragma unroll
        for (int cc = 0; cc < 32; cc++) {
            float ir[2], wr[8];
#pragma unroll
            for (int i = 0; i < 2; i++) ir[i] = shI[i * 16 + ty][cc];
#pragma unroll
            for (int j = 0; j < 8; j++) wr[j] = shWt[j * 16 + tx][cc];
#pragma unroll
            for (int i = 0; i < 2; i++)
#pragma unroll
                for (int j = 0; j < 8; j++) acc[i][j] += ir[i] * wr[j];
        }
        __syncthreads();
    }

#pragma unroll
    for (int i = 0; i < 2; i++) {
        int r = row0 + i * 16 + ty;
#pragma unroll
        for (int j = 0; j < 8; j++) {
            int e = j * 16 + tx;
            Z[(size_t)r * DMODEL + e] = acc[i][j] + out_b[e];
        }
    }
}

// ================= launch =================
extern "C" void kernel_launch(void* const* d_in, const int* in_sizes, int n_in,
                              void* d_out, int out_size) {
    const float* x      = (const float*)d_in[0];
    const float* Wq     = (const float*)d_in[1];
    const float* bq     = (const float*)d_in[2];
    const float* Wk     = (const float*)d_in[3];
    const float* bk     = (const float*)d_in[4];
    const float* Wv     = (const float*)d_in[5];
    const float* bv     = (const float*)d_in[6];
    const float* in_w   = (const float*)d_in[7];
    const float* in_b   = (const float*)d_in[8];
    const float* out_w  = (const float*)d_in[9];
    const float* out_b  = (const float*)d_in[10];
    const float* gate_w = (const float*)d_in[11];
    const float* gate_b = (const float*)d_in[12];
    float* Z = (float*)d_out;

    k_swt    <<<BNUM * CIN, 256>>>(x);
    k_compose<<<dim3(9, 32), 256>>>(Wq, bq, Wk, bk, Wv, bv, in_w, in_b);
    k_qkv    <<<dim3(192, 3), 256>>>();
    k_attn   <<<dim3(16, HNUM, SNUM * BNUM * 2), 128>>>();
    k_merge  <<<384, 256>>>();
    k_meanred<<<dim3(SNUM, BNUM, 16), 128>>>();
    k_gate   <<<1, DMODEL>>>(out_w, out_b, gate_w, gate_b);
    k_final  <<<128, 256>>>(out_w, out_b, Z);
}

// round 12
// speedup vs baseline: 1.3833x; 1.0262x over previous
#include <cuda_runtime.h>
#include <cuda_bf16.h>

#define TFULL 2048
#define CIN   64
#define DMODEL 128
#define SNUM  3
#define BNUM  2
#define HNUM  8
#define DH    16
#define KHALF 1024

typedef unsigned int uint32;
typedef unsigned long long u64;

__device__ __forceinline__ uint32 cvt_tf32(float x) {
    uint32 r; asm("cvt.rna.tf32.f32 %0,%1;" : "=r"(r) : "f"(x)); return r;
}
__device__ __forceinline__ void mma_tf32(float* d, const uint32* a, uint32 b0, uint32 b1) {
    asm volatile("mma.sync.aligned.m16n8k8.row.col.f32.tf32.tf32.f32 "
        "{%0,%1,%2,%3},{%4,%5,%6,%7},{%8,%9},{%0,%1,%2,%3};"
        : "+f"(d[0]), "+f"(d[1]), "+f"(d[2]), "+f"(d[3])
        : "r"(a[0]), "r"(a[1]), "r"(a[2]), "r"(a[3]), "r"(b0), "r"(b1));
}
__device__ __forceinline__ void mma_bf16(float* d, const uint32* a, uint32 b0, uint32 b1) {
    asm volatile("mma.sync.aligned.m16n8k16.row.col.f32.bf16.bf16.f32 "
        "{%0,%1,%2,%3},{%4,%5,%6,%7},{%8,%9},{%0,%1,%2,%3};"
        : "+f"(d[0]), "+f"(d[1]), "+f"(d[2]), "+f"(d[3])
        : "r"(a[0]), "r"(a[1]), "r"(a[2]), "r"(a[3]), "r"(b0), "r"(b1));
}
__device__ __forceinline__ void cp16(uint32 saddr, const void* g) {
    asm volatile("cp.async.cg.shared.global [%0], [%1], 16;" :: "r"(saddr), "l"(g));
}
__device__ __forceinline__ uint32 pkbf(float a, float b) {
    __nv_bfloat162 t = __floats2bfloat162_rn(a, b);
    return *reinterpret_cast<uint32*>(&t);
}
__device__ __forceinline__ u64 pack2(float lo, float hi) {
    u64 r; asm("mov.b64 %0,{%1,%2};" : "=l"(r) : "f"(lo), "f"(hi)); return r;
}
__device__ __forceinline__ void unpack2(u64 v, float& lo, float& hi) {
    asm("mov.b64 {%0,%1},%2;" : "=f"(lo), "=f"(hi) : "l"(v));
}
__device__ __forceinline__ u64 ffma2(u64 a, u64 b, u64 c) {
    u64 d; asm("fma.rn.f32x2 %0,%1,%2,%3;" : "=l"(d) : "l"(a), "l"(b), "l"(c)); return d;
}

// ---------------- wavelet filters ----------------
__constant__ float c_DEC_LO[8] = {
    -0.010597401784997278f,  0.032883011666982945f,  0.030841381835986965f,
    -0.18703481171888114f,  -0.02798376941698385f,   0.6308807679295904f,
     0.7148465705525415f,    0.23037781330885523f };
__constant__ float c_DEC_HI[8] = {
    -0.23037781330885523f,   0.7148465705525415f,   -0.6308807679295904f,
    -0.02798376941698385f,   0.18703481171888114f,   0.030841381835986965f,
    -0.032883011666982945f, -0.010597401784997278f };

// ---------------- scratch ----------------
__device__ float g_W   [SNUM*BNUM*TFULL*CIN];
__device__ float g_A   [SNUM*3*DMODEL*CIN];
__device__ float g_cb  [SNUM*3*DMODEL];
__device__ float g_q   [SNUM*BNUM*TFULL*DMODEL];
__device__ __nv_bfloat16 g_kh16[SNUM*BNUM*TFULL*DMODEL];  // K bf16 hi
__device__ __nv_bfloat16 g_kl16[SNUM*BNUM*TFULL*DMODEL];  // K bf16 lo (residual)
__device__ float g_vt  [SNUM*BNUM*TFULL*DMODEL];          // V tf32-rounded
__device__ float g_o   [SNUM*BNUM*TFULL*DMODEL];
__device__ float g_pacc[2*SNUM*BNUM*TFULL*DMODEL];        // split-K unnormalized acc
__device__ float g_pml [2*SNUM*BNUM*TFULL*HNUM*2];        // split-K (m,l) per row/head
__device__ float g_meanp[SNUM*BNUM*16*DMODEL];
__device__ float g_gate[BNUM*SNUM];

// ================= K0: stationary wavelet transform =================
__global__ void k_swt(const float* __restrict__ x) {
    __shared__ float sh[2][TFULL];
    const int b = blockIdx.x >> 6;
    const int c = blockIdx.x & 63;
    const int tid = threadIdx.x;

    for (int t = tid; t < TFULL; t += 256)
        sh[0][t] = x[(b * TFULL + t) * CIN + c];
    __syncthreads();

    int cur = 0;
    for (int j = 0; j < 3; j++) {
        const int step = 1 << j;
        for (int t = tid; t < TFULL; t += 256) {
            float d = 0.f, a = 0.f;
#pragma unroll
            for (int l = 0; l < 8; l++) {
                float val = sh[cur][(t - l * step) & (TFULL - 1)];
                d += val * c_DEC_HI[l];
                a += val * c_DEC_LO[l];
            }
            g_W[(((2 - j) * BNUM + b) * TFULL + t) * CIN + c] = d;
            sh[cur ^ 1][t] = a;
        }
        __syncthreads();
        cur ^= 1;
    }
}

// ================= K1: compose (in_w x Wqkv) weights + biases =================
__global__ void k_compose(const float* __restrict__ Wq, const float* __restrict__ bq,
                          const float* __restrict__ Wk, const float* __restrict__ bk,
                          const float* __restrict__ Wv, const float* __restrict__ bv,
                          const float* __restrict__ in_w, const float* __restrict__ in_b) {
    const int sw = blockIdx.x;
    const int s = sw / 3, w = sw % 3;
    const float* Wx = (w == 0) ? Wq : (w == 1) ? Wk : Wv;
    const float* bx = (w == 0) ? bq : (w == 1) ? bk : bv;

    const int idx = blockIdx.y * 256 + threadIdx.x;
    const int e = idx >> 6, c = idx & 63;
    const float* iw = in_w + (w * DMODEL + e) * DMODEL;
    const float* wc = Wx + s * DMODEL * CIN + c;
    float acc = 0.f;
#pragma unroll 4
    for (int dd = 0; dd < DMODEL; dd++) acc += iw[dd] * wc[dd * CIN];
    g_A[(sw * DMODEL + e) * CIN + c] = acc;

    if (blockIdx.y == 0 && threadIdx.x < DMODEL) {
        const int ee = threadIdx.x;
        const float* iw2 = in_w + (w * DMODEL + ee) * DMODEL;
        float bb = in_b[w * DMODEL + ee];
#pragma unroll 4
        for (int dd = 0; dd < DMODEL; dd++) bb += iw2[dd] * bx[s * DMODEL + dd];
        g_cb[sw * DMODEL + ee] = bb;
    }
}

// ================= K2: fused q/k/v projection GEMM (f32x2) + pre-conversion =================
// A tile transposed in smem so column-pairs are contiguous -> 64-bit LDS + FFMA2.
__global__ void __launch_bounds__(256) k_qkv() {
    __shared__ float shW [64][33];
    __shared__ float shAT[32][130];            // [cc][e] transposed, padded
    const int row0 = blockIdx.x * 64;
    const int w = blockIdx.y;
    const int s = row0 >> 12;
    const int tid = threadIdx.x;
    const int ty = tid >> 4, tx = tid & 15;
    const float* Abase = g_A + (s * 3 + w) * DMODEL * CIN;

    u64 accp[4][4];
    const u64 zz = pack2(0.f, 0.f);
#pragma unroll
    for (int i = 0; i < 4; i++)
#pragma unroll
        for (int j = 0; j < 4; j++) accp[i][j] = zz;

    for (int c0 = 0; c0 < CIN; c0 += 32) {
#pragma unroll
        for (int i = 0; i < 8; i++) {          // 64x32 W tile
            int lin = tid + i * 256;
            shW[lin >> 5][lin & 31] = g_W[(row0 + (lin >> 5)) * CIN + c0 + (lin & 31)];
        }
#pragma unroll
        for (int i = 0; i < 16; i++) {         // 128 e x 32 cc, transposed store
            int lin = tid + i * 256;
            int e = lin >> 5, cc = lin & 31;
            shAT[cc][e] = Abase[e * CIN + c0 + cc];
        }
        __syncthreads();
#pragma unroll
        for (int cc = 0; cc < 32; cc++) {
            u64 wp[4], ap[4];
#pragma unroll
            for (int i = 0; i < 4; i++) {
                float wv = shW[i * 16 + ty][cc];
                wp[i] = pack2(wv, wv);
            }
#pragma unroll
            for (int j = 0; j < 4; j++)
                ap[j] = *(const u64*)&shAT[cc][j * 32 + 2 * tx];
#pragma unroll
            for (int i = 0; i < 4; i++)
#pragma unroll
                for (int j = 0; j < 4; j++)
                    accp[i][j] = ffma2(wp[i], ap[j], accp[i][j]);
        }
        __syncthreads();
    }

    const float* cb = g_cb + (s * 3 + w) * DMODEL;
#pragma unroll
    for (int i = 0; i < 4; i++) {
        int r = row0 + i * 16 + ty;
#pragma unroll
        for (int j = 0; j < 4; j++) {
            int e0 = j * 32 + 2 * tx;
            float v0, v1;
            unpack2(accp[i][j], v0, v1);
            float val0 = v0 + cb[e0];
            float val1 = v1 + cb[e0 + 1];
            size_t o0 = (size_t)r * DMODEL + e0;
            if (w == 0) {
                g_q[o0] = val0; g_q[o0 + 1] = val1;
            } else if (w == 1) {
                __nv_bfloat16 h0 = __float2bfloat16(val0);
                __nv_bfloat16 h1 = __float2bfloat16(val1);
                g_kh16[o0] = h0; g_kh16[o0 + 1] = h1;
                g_kl16[o0]     = __float2bfloat16(val0 - __bfloat162float(h0));
                g_kl16[o0 + 1] = __float2bfloat16(val1 - __bfloat162float(h1));
            } else {
                g_vt[o0]     = __uint_as_float(cvt_tf32(val0));
                g_vt[o0 + 1] = __uint_as_float(cvt_tf32(val1));
            }
        }
    }
}

// ================= K3: flash attention, split-K x2, bf16 QK + tf32 PV =================
// grid: (16 q-tiles of 128, 8 heads, 6 s*b * 2 key-halves). block 128.
#define KS16    12
#define VSTRIDE 24
#define KCH     32
__global__ void k_attn() {
    __shared__ __align__(16) uint32 sKh[2 * KCH * KS16];
    __shared__ __align__(16) uint32 sKl[2 * KCH * KS16];
    __shared__ __align__(16) float  sV [2 * KCH * VSTRIDE];

    const int tid  = threadIdx.x;
    const int warp = tid >> 5, lane = tid & 31;
    const int gid  = lane >> 2, tig = lane & 3;
    const int qt = blockIdx.x, h = blockIdx.y;
    const int sb = blockIdx.z >> 1, kh = blockIdx.z & 1;
    const int qbase = qt * 128 + warp * 32;
    const int kbeg = kh * KHALF;

    const float sc = 0.25f * 1.4426950408889634f;

    // ---- load Q for both 16-row groups; bf16 hi/lo split, packed pairs ----
    uint32 ahi[2][4], alo[2][4];
#pragma unroll
    for (int g = 0; g < 2; g++) {
#pragma unroll
        for (int rr = 0; rr < 2; rr++) {
            const float* qr = g_q + ((size_t)(sb * TFULL) + qbase + g * 16 + gid + rr * 8) * DMODEL + h * DH;
            float2 pa = *(const float2*)(qr + 2 * tig);
            float2 pb = *(const float2*)(qr + 2 * tig + 8);
            float ax = pa.x * sc, ay = pa.y * sc;
            float bx = pb.x * sc, by = pb.y * sc;
            float axh = __bfloat162float(__float2bfloat16(ax));
            float ayh = __bfloat162float(__float2bfloat16(ay));
            float bxh = __bfloat162float(__float2bfloat16(bx));
            float byh = __bfloat162float(__float2bfloat16(by));
            ahi[g][rr]     = pkbf(axh, ayh);
            alo[g][rr]     = pkbf(ax - axh, ay - ayh);
            ahi[g][rr + 2] = pkbf(bxh, byh);
            alo[g][rr + 2] = pkbf(bx - bxh, by - byh);
        }
    }

    float m_lo[2] = { -1e30f, -1e30f }, m_hi[2] = { -1e30f, -1e30f };
    float l_lo[2] = { 0.f, 0.f },       l_hi[2] = { 0.f, 0.f };
    float oc[2][2][4];
#pragma unroll
    for (int g = 0; g < 2; g++)
#pragma unroll
        for (int nv = 0; nv < 2; nv++)
#pragma unroll
            for (int i = 0; i < 4; i++) oc[g][nv][i] = 0.f;

    const int sigma = (gid >> 1) + ((gid & 1) << 2);

    const int kr = (tid & 63) >> 1, kh2 = tid & 1;
    const int vr = tid >> 2,        vc  = tid & 3;
    const size_t gbase = (size_t)(sb * TFULL) * DMODEL + h * DH;
    const __nv_bfloat16* gK = (tid < 64) ? g_kh16 : g_kl16;
    const uint32 sK_b = (uint32)__cvta_generic_to_shared(tid < 64 ? sKh : sKl)
                        + (kr * KS16 + kh2 * 4) * 4;
    const uint32 sV_b = (uint32)__cvta_generic_to_shared(sV) + (vr * VSTRIDE + vc * 4) * 4;

    const uint32* kh_base = sKh + sigma * KS16 + tig;
    const uint32* kl_base = sKl + sigma * KS16 + tig;
    const float* v0_base = sV + tig * VSTRIDE + gid;
    const float* v1_base = sV + (tig + 4) * VSTRIDE + gid;

    // prefetch chunk 0
    {
        cp16(sK_b, gK + gbase + (size_t)(kbeg + kr) * DMODEL + kh2 * 8);
        cp16(sV_b, g_vt + gbase + (size_t)(kbeg + vr) * DMODEL + vc * 4);
        asm volatile("cp.async.commit_group;" ::: "memory");
    }

#pragma unroll 2
    for (int c = 0; c < KHALF / KCH; c++) {
        asm volatile("cp.async.wait_group 0;" ::: "memory");
        __syncthreads();
        if (c + 1 < KHALF / KCH) {
            int nb = (c + 1) & 1;
            int rbase = kbeg + (c + 1) * KCH;
            cp16(sK_b + nb * (KCH * KS16 * 4),
                 gK + gbase + (size_t)(rbase + kr) * DMODEL + kh2 * 8);
            cp16(sV_b + nb * (KCH * VSTRIDE * 4),
                 g_vt + gbase + (size_t)(rbase + vr) * DMODEL + vc * 4);
            asm volatile("cp.async.commit_group;" ::: "memory");
        }
        const int buf = c & 1;
        const uint32* khB = kh_base + buf * (KCH * KS16);
        const uint32* klB = kl_base + buf * (KCH * KS16);
        const float* v0B = v0_base + buf * (KCH * VSTRIDE);
        const float* v1B = v1_base + buf * (KCH * VSTRIDE);

        // ---- S = Q K^T: qhi*khi + qhi*klo + qlo*khi (bf16 m16n8k16) ----
        float cS[2][4][4];
#pragma unroll
        for (int nt = 0; nt < 4; nt++) {
#pragma unroll
            for (int g = 0; g < 2; g++) {
                cS[g][nt][0] = 0.f; cS[g][nt][1] = 0.f;
                cS[g][nt][2] = 0.f; cS[g][nt][3] = 0.f;
            }
            uint32 b0h = khB[nt * 8 * KS16];
            uint32 b1h = khB[nt * 8 * KS16 + 4];
            uint32 b0l = klB[nt * 8 * KS16];
            uint32 b1l = klB[nt * 8 * KS16 + 4];
#pragma unroll
            for (int g = 0; g < 2; g++) {
                mma_bf16(cS[g][nt], ahi[g], b0h, b1h);
                mma_bf16(cS[g][nt], ahi[g], b0l, b1l);
                mma_bf16(cS[g][nt], alo[g], b0h, b1h);
            }
        }

        // ---- online softmax; p left as raw f32 (MMA truncates to tf32) ----
#pragma unroll
        for (int g = 0; g < 2; g++) {
            float mx0 = m_lo[g], mx1 = m_hi[g];
#pragma unroll
            for (int nt = 0; nt < 4; nt++) {
                mx0 = fmaxf(mx0, fmaxf(cS[g][nt][0], cS[g][nt][1]));
                mx1 = fmaxf(mx1, fmaxf(cS[g][nt][2], cS[g][nt][3]));
            }
            mx0 = fmaxf(mx0, __shfl_xor_sync(0xffffffffu, mx0, 1));
            mx0 = fmaxf(mx0, __shfl_xor_sync(0xffffffffu, mx0, 2));
            mx1 = fmaxf(mx1, __shfl_xor_sync(0xffffffffu, mx1, 1));
            mx1 = fmaxf(mx1, __shfl_xor_sync(0xffffffffu, mx1, 2));
            float cr0 = exp2f(m_lo[g] - mx0), cr1 = exp2f(m_hi[g] - mx1);
            m_lo[g] = mx0; m_hi[g] = mx1;
            l_lo[g] *= cr0; l_hi[g] *= cr1;
#pragma unroll
            for (int nv = 0; nv < 2; nv++) {
                oc[g][nv][0] *= cr0; oc[g][nv][1] *= cr0;
                oc[g][nv][2] *= cr1; oc[g][nv][3] *= cr1;
            }
#pragma unroll
            for (int nt = 0; nt < 4; nt++) {
                float p0 = exp2f(cS[g][nt][0] - mx0);
                float p1 = exp2f(cS[g][nt][1] - mx0);
                float p2 = exp2f(cS[g][nt][2] - mx1);
                float p3 = exp2f(cS[g][nt][3] - mx1);
                l_lo[g] += p0 + p1;
                l_hi[g] += p2 + p3;
                cS[g][nt][0] = p0;
                cS[g][nt][1] = p1;
                cS[g][nt][2] = p2;
                cS[g][nt][3] = p3;
            }
        }

        // ---- O += P V (tf32 m16n8k8) ----
#pragma unroll
        for (int j = 0; j < 4; j++) {
            const float* v0 = v0B + 8 * j * VSTRIDE;
            const float* v1 = v1B + 8 * j * VSTRIDE;
            uint32 b0a = __float_as_uint(v0[0]);
            uint32 b1a = __float_as_uint(v1[0]);
            uint32 b0b = __float_as_uint(v0[8]);
            uint32 b1b = __float_as_uint(v1[8]);
#pragma unroll
            for (int g = 0; g < 2; g++) {
                uint32 ap[4] = { __float_as_uint(cS[g][j][0]), __float_as_uint(cS[g][j][2]),
                                 __float_as_uint(cS[g][j][1]), __float_as_uint(cS[g][j][3]) };
                mma_tf32(oc[g][0], ap, b0a, b1a);
                mma_tf32(oc[g][1], ap, b0b, b1b);
            }
        }
    }

    // ---- write split-K partials (unnormalized) + (m,l) ----
#pragma unroll
    for (int g = 0; g < 2; g++) {
        float ll = l_lo[g], lh = l_hi[g];
        ll += __shfl_xor_sync(0xffffffffu, ll, 1);
        ll += __shfl_xor_sync(0xffffffffu, ll, 2);
        lh += __shfl_xor_sync(0xffffffffu, lh, 1);
        lh += __shfl_xor_sync(0xffffffffu, lh, 2);

        const int r1 = qbase + g * 16 + gid;
        float* pb = g_pacc + (((size_t)(kh * (SNUM * BNUM) + sb)) * TFULL + r1) * DMODEL + h * DH;
#pragma unroll
        for (int nv = 0; nv < 2; nv++) {
            *(float2*)(pb + 2 * tig + 8 * nv) =
                make_float2(oc[g][nv][0], oc[g][nv][1]);
            *(float2*)(pb + 8 * DMODEL + 2 * tig + 8 * nv) =
                make_float2(oc[g][nv][2], oc[g][nv][3]);
        }
        if (tig == 0) {
            float2* pml = (float2*)g_pml;
            size_t base = ((size_t)(kh * (SNUM * BNUM) + sb)) * TFULL;
            pml[(base + r1) * HNUM + h]     = make_float2(m_lo[g], ll);
            pml[(base + r1 + 8) * HNUM + h] = make_float2(m_hi[g], lh);
        }
    }
}

// ================= K3b: merge split-K halves =================
__global__ void k_merge() {
    const int idx = blockIdx.x * 256 + threadIdx.x;
    const int h = idx & 7;
    const int t = (idx >> 3) & (TFULL - 1);
    const int sb = idx >> 14;
    const size_t r0 = (size_t)sb * TFULL + t;
    const size_t r1 = (size_t)(SNUM * BNUM + sb) * TFULL + t;

    float2 ml0 = ((const float2*)g_pml)[r0 * HNUM + h];
    float2 ml1 = ((const float2*)g_pml)[r1 * HNUM + h];
    float M = fmaxf(ml0.x, ml1.x);
    float e0 = exp2f(ml0.x - M);
    float e1 = exp2f(ml1.x - M);
    float inv = 1.f / (e0 * ml0.y + e1 * ml1.y);
    e0 *= inv; e1 *= inv;

    const float* p0 = g_pacc + r0 * DMODEL + h * DH;
    const float* p1 = g_pacc + r1 * DMODEL + h * DH;
    float* ob = g_o + ((size_t)sb * TFULL + t) * DMODEL + h * DH;
#pragma unroll
    for (int i = 0; i < 4; i++) {
        float4 a = *(const float4*)(p0 + i * 4);
        float4 b = *(const float4*)(p1 + i * 4);
        *(float4*)(ob + i * 4) = make_float4(a.x * e0 + b.x * e1,
                                             a.y * e0 + b.y * e1,
                                             a.z * e0 + b.z * e1,
                                             a.w * e0 + b.w * e1);
    }
}

// ================= K4: partial t-sums =================
__global__ void k_meanred() {
    const int s = blockIdx.x, b = blockIdx.y, ch = blockIdx.z;
    const int d = threadIdx.x;
    const float* base = g_o + (((size_t)(s * BNUM + b) * TFULL) + ch * 128) * DMODEL + d;
    float sum = 0.f;
#pragma unroll 8
    for (int t = 0; t < 128; t++) sum += base[t * DMODEL];
    g_meanp[((s * BNUM + b) * 16 + ch) * DMODEL + d] = sum;
}

// ================= K5: gate computation =================
__global__ void k_gate(const float* __restrict__ out_w, const float* __restrict__ out_b,
                       const float* __restrict__ gate_w, const float* __restrict__ gate_b) {
    __shared__ float sh_m[DMODEL];
    __shared__ float sh_gf[DMODEL];
    __shared__ float sh_lg[SNUM];
    const int d = threadIdx.x;
    for (int b = 0; b < BNUM; b++) {
        float mv = 0.f;
#pragma unroll
        for (int s = 0; s < SNUM; s++)
#pragma unroll
            for (int c = 0; c < 16; c++)
                mv += g_meanp[((s * BNUM + b) * 16 + c) * DMODEL + d];
        sh_m[d] = mv;
        __syncthreads();
        float acc = 0.f;
        const float* ow = out_w + d * DMODEL;
#pragma unroll 4
        for (int dd = 0; dd < DMODEL; dd++) acc += ow[dd] * sh_m[dd];
        sh_gf[d] = acc * (1.0f / (TFULL * SNUM)) + out_b[d];
        __syncthreads();
        if (d < SNUM) {
            float lg = gate_b[d];
            for (int dd = 0; dd < DMODEL; dd++) lg += sh_gf[dd] * gate_w[d * DMODEL + dd];
            sh_lg[d] = lg;
        }
        __syncthreads();
        if (d == 0) {
            float mx = fmaxf(sh_lg[0], fmaxf(sh_lg[1], sh_lg[2]));
            float e0 = __expf(sh_lg[0] - mx);
            float e1 = __expf(sh_lg[1] - mx);
            float e2 = __expf(sh_lg[2] - mx);
            float inv = 1.f / (e0 + e1 + e2);
            g_gate[b * 3 + 0] = e0 * inv;
            g_gate[b * 3 + 1] = e1 * inv;
            g_gate[b * 3 + 2] = e2 * inv;
        }
        __syncthreads();
    }
}

// ================= K6: gated combine + output projection (128 blocks) =================
__global__ void __launch_bounds__(256) k_final(const float* __restrict__ out_w,
                                               const float* __restrict__ out_b,
                                               float* __restrict__ Z) {
    __shared__ float shI[32][33];
    __shared__ float shWt[128][33];
    const int row0 = blockIdx.x * 32;
    const int tid = threadIdx.x;
    const int b = row0 >> 11;
    const float gt0 = g_gate[b * 3 + 0];
    const float gt1 = g_gate[b * 3 + 1];
    const float gt2 = g_gate[b * 3 + 2];
    const int ty = tid >> 4, tx = tid & 15;
    const size_t SB = (size_t)BNUM * TFULL * DMODEL;

    float acc[2][8];
#pragma unroll
    for (int i = 0; i < 2; i++)
#pragma unroll
        for (int j = 0; j < 8; j++) acc[i][j] = 0.f;

    for (int c0 = 0; c0 < DMODEL; c0 += 32) {
#pragma unroll
        for (int i = 0; i < 4; i++) {
            int lin = tid + i * 256;
            int rr = lin >> 5, cc = lin & 31;
            size_t idx = (size_t)(row0 + rr) * DMODEL + c0 + cc;
            float v0 = g_o[idx];
            float v1 = g_o[SB + idx];
            float v2 = g_o[2 * SB + idx];
            shI[rr][cc] = gt0 * v0 + gt1 * v1 + gt2 * v2;
        }
#pragma unroll
        for (int i = 0; i < 16; i++) {
            int lin = tid + i * 256;
            shWt[lin >> 5][lin & 31] = out_w[(lin >> 5) * DMODEL + c0 + (lin & 31)];
        }
        __syncthreads();
#pragma unroll
        for (int cc = 0; cc < 32; cc++) {
            float ir[2], wr[8];
#pragma unroll
            for (int i = 0; i < 2; i++) ir[i] = shI[i * 16 + ty][cc];
#pragma unroll
            for (int j = 0; j < 8; j++) wr[j] = shWt[j * 16 + tx][cc];
#pragma unroll
            for (int i = 0; i < 2; i++)
#pragma unroll
                for (int j = 0; j < 8; j++) acc[i][j] += ir[i] * wr[j];
        }
        __syncthreads();
    }

#pragma unroll
    for (int i = 0; i < 2; i++) {
        int r = row0 + i * 16 + ty;
#pragma unroll
        for (int j = 0; j < 8; j++) {
            int e = j * 16 + tx;
            Z[(size_t)r * DMODEL + e] = acc[i][j] + out_b[e];
        }
    }
}

// ================= launch =================
extern "C" void kernel_launch(void* const* d_in, const int* in_sizes, int n_in,
                              void* d_out, int out_size) {
    const float* x      = (const float*)d_in[0];
    const float* Wq     = (const float*)d_in[1];
    const float* bq     = (const float*)d_in[2];
    const float* Wk     = (const float*)d_in[3];
    const float* bk     = (const float*)d_in[4];
    const float* Wv     = (const float*)d_in[5];
    const float* bv     = (const float*)d_in[6];
    const float* in_w   = (const float*)d_in[7];
    const float* in_b   = (const float*)d_in[8];
    const float* out_w  = (const float*)d_in[9];
    const float* out_b  = (const float*)d_in[10];
    const float* gate_w = (const float*)d_in[11];
    const float* gate_b = (const float*)d_in[12];
    float* Z = (float*)d_out;

    k_swt    <<<BNUM * CIN, 256>>>(x);
    k_compose<<<dim3(9, 32), 256>>>(Wq, bq, Wk, bk, Wv, bv, in_w, in_b);
    k_qkv    <<<dim3(192, 3), 256>>>();
    k_attn   <<<dim3(16, HNUM, SNUM * BNUM * 2), 128>>>();
    k_merge  <<<384, 256>>>();
    k_meanred<<<dim3(SNUM, BNUM, 16), 128>>>();
    k_gate   <<<1, DMODEL>>>(out_w, out_b, gate_w, gate_b);
    k_final  <<<128, 256>>>(out_w, out_b, Z);
}

// round 14
// speedup vs baseline: 1.3965x; 1.0096x over previous
#include <cuda_runtime.h>
#include <cuda_bf16.h>

#define TFULL 2048
#define CIN   64
#define DMODEL 128
#define SNUM  3
#define BNUM  2
#define HNUM  8
#define DH    16
#define KHALF 1024

typedef unsigned int uint32;

__device__ __forceinline__ uint32 cvt_tf32(float x) {
    uint32 r; asm("cvt.rna.tf32.f32 %0,%1;" : "=r"(r) : "f"(x)); return r;
}
__device__ __forceinline__ void mma_tf32(float* d, const uint32* a, uint32 b0, uint32 b1) {
    asm volatile("mma.sync.aligned.m16n8k8.row.col.f32.tf32.tf32.f32 "
        "{%0,%1,%2,%3},{%4,%5,%6,%7},{%8,%9},{%0,%1,%2,%3};"
        : "+f"(d[0]), "+f"(d[1]), "+f"(d[2]), "+f"(d[3])
        : "r"(a[0]), "r"(a[1]), "r"(a[2]), "r"(a[3]), "r"(b0), "r"(b1));
}
__device__ __forceinline__ void mma_bf16(float* d, const uint32* a, uint32 b0, uint32 b1) {
    asm volatile("mma.sync.aligned.m16n8k16.row.col.f32.bf16.bf16.f32 "
        "{%0,%1,%2,%3},{%4,%5,%6,%7},{%8,%9},{%0,%1,%2,%3};"
        : "+f"(d[0]), "+f"(d[1]), "+f"(d[2]), "+f"(d[3])
        : "r"(a[0]), "r"(a[1]), "r"(a[2]), "r"(a[3]), "r"(b0), "r"(b1));
}
__device__ __forceinline__ void cp16(uint32 saddr, const void* g) {
    asm volatile("cp.async.cg.shared.global [%0], [%1], 16;" :: "r"(saddr), "l"(g));
}
__device__ __forceinline__ uint32 pkbf(float a, float b) {
    __nv_bfloat162 t = __floats2bfloat162_rn(a, b);
    return *reinterpret_cast<uint32*>(&t);
}

// ---------------- wavelet filters ----------------
__constant__ float c_DEC_LO[8] = {
    -0.010597401784997278f,  0.032883011666982945f,  0.030841381835986965f,
    -0.18703481171888114f,  -0.02798376941698385f,   0.6308807679295904f,
     0.7148465705525415f,    0.23037781330885523f };
__constant__ float c_DEC_HI[8] = {
    -0.23037781330885523f,   0.7148465705525415f,   -0.6308807679295904f,
    -0.02798376941698385f,   0.18703481171888114f,   0.030841381835986965f,
    -0.032883011666982945f, -0.010597401784997278f };

// ---------------- scratch ----------------
// g_W is CHANNEL-MAJOR: [(sb*CIN + c) * TFULL + t]  (coalesced SWT writes)
__device__ float g_W   [SNUM*BNUM*CIN*TFULL];
__device__ uint32 g_Ahi[SNUM*3*DMODEL*(CIN/2)];           // composed weights bf16-hi packed
__device__ uint32 g_Alo[SNUM*3*DMODEL*(CIN/2)];           // composed weights bf16-lo packed
__device__ float g_cb  [SNUM*3*DMODEL];
__device__ float g_q   [SNUM*BNUM*TFULL*DMODEL];
__device__ __nv_bfloat16 g_kh16[SNUM*BNUM*TFULL*DMODEL];  // K bf16 hi
__device__ __nv_bfloat16 g_kl16[SNUM*BNUM*TFULL*DMODEL];  // K bf16 lo (residual)
__device__ float g_vt  [SNUM*BNUM*TFULL*DMODEL];          // V tf32-rounded
__device__ float g_o   [SNUM*BNUM*TFULL*DMODEL];
__device__ float g_pacc[2*SNUM*BNUM*TFULL*DMODEL];        // split-K unnormalized acc
__device__ float g_pml [2*SNUM*BNUM*TFULL*HNUM*2];        // split-K (m,l) per row/head
__device__ float g_meanp[SNUM*BNUM*16*DMODEL];
__device__ float g_gate[BNUM*SNUM];

// ================= K0: stationary wavelet transform (coalesced writes) =================
__global__ void k_swt(const float* __restrict__ x) {
    __shared__ float sh[2][TFULL];
    const int b = blockIdx.x >> 6;
    const int c = blockIdx.x & 63;
    const int tid = threadIdx.x;

    for (int t = tid; t < TFULL; t += 256)
        sh[0][t] = x[(b * TFULL + t) * CIN + c];
    __syncthreads();

    int cur = 0;
    for (int j = 0; j < 3; j++) {
        const int step = 1 << j;
        float* wout = g_W + ((size_t)(((2 - j) * BNUM + b) * CIN + c)) * TFULL;
        for (int t = tid; t < TFULL; t += 256) {
            float d = 0.f, a = 0.f;
#pragma unroll
            for (int l = 0; l < 8; l++) {
                float val = sh[cur][(t - l * step) & (TFULL - 1)];
                d += val * c_DEC_HI[l];
                a += val * c_DEC_LO[l];
            }
            wout[t] = d;                       // contiguous in t -> coalesced
            sh[cur ^ 1][t] = a;
        }
        __syncthreads();
        cur ^= 1;
    }
}

// ================= K1: compose weights -> packed bf16 hi/lo + biases =================
__global__ void k_compose(const float* __restrict__ Wq, const float* __restrict__ bq,
                          const float* __restrict__ Wk, const float* __restrict__ bk,
                          const float* __restrict__ Wv, const float* __restrict__ bv,
                          const float* __restrict__ in_w, const float* __restrict__ in_b) {
    const int sw = blockIdx.x;
    const int s = sw / 3, w = sw % 3;
    const float* Wx = (w == 0) ? Wq : (w == 1) ? Wk : Wv;
    const float* bx = (w == 0) ? bq : (w == 1) ? bk : bv;

    const int idx = blockIdx.y * 256 + threadIdx.x;   // 0..4095
    const int e = idx >> 5, cp = idx & 31;
    const int c0 = 2 * cp;
    const float* iw = in_w + (w * DMODEL + e) * DMODEL;
    const float* wc0 = Wx + s * DMODEL * CIN + c0;
    float a0 = 0.f, a1 = 0.f;
#pragma unroll 4
    for (int dd = 0; dd < DMODEL; dd++) {
        float ww = iw[dd];
        a0 += ww * wc0[dd * CIN];
        a1 += ww * wc0[dd * CIN + 1];
    }
    float h0 = __bfloat162float(__float2bfloat16(a0));
    float h1 = __bfloat162float(__float2bfloat16(a1));
    const size_t oidx = (size_t)(sw * DMODEL + e) * (CIN / 2) + cp;
    g_Ahi[oidx] = pkbf(h0, h1);
    g_Alo[oidx] = pkbf(a0 - h0, a1 - h1);

    if (blockIdx.y == 0 && threadIdx.x < DMODEL) {
        const int ee = threadIdx.x;
        const float* iw2 = in_w + (w * DMODEL + ee) * DMODEL;
        float bb = in_b[w * DMODEL + ee];
#pragma unroll 4
        for (int dd = 0; dd < DMODEL; dd++) bb += iw2[dd] * bx[s * DMODEL + dd];
        g_cb[sw * DMODEL + ee] = bb;
    }
}

// ================= K2: q/k/v projection on tensor cores (bf16 2-term split) =================
// grid (192 row-tiles of 64, 3 w), block 128 (4 warps x 16 rows).
#define QS 20   // u32 row stride in smem
__global__ void __launch_bounds__(128) k_qkv() {
    __shared__ uint32 sWh[64 * QS], sWl[64 * QS];
    __shared__ uint32 sAh[128 * QS], sAl[128 * QS];
    const int row0 = blockIdx.x * 64;
    const int w = blockIdx.y;
    const int s = row0 >> 12;
    const int sbi = row0 >> 11;                 // (s*2+b)
    const int t0 = row0 & (TFULL - 1);
    const int tid = threadIdx.x;
    const int warp = tid >> 5, lane = tid & 31;
    const int gid = lane >> 2, tig = lane & 3;

    float cacc[16][4];
#pragma unroll
    for (int nt = 0; nt < 16; nt++)
#pragma unroll
        for (int i = 0; i < 4; i++) cacc[nt][i] = 0.f;

    const size_t abase = (size_t)((s * 3 + w) * DMODEL) * (CIN / 2);

    for (int p = 0; p < 2; p++) {
        const int c0p = p * 32;
        // ---- W tile fill: 64 t x 32 c (coalesced in t), split to bf16 hi/lo ----
        __nv_bfloat16* wh16 = (__nv_bfloat16*)sWh;
        __nv_bfloat16* wl16 = (__nv_bfloat16*)sWl;
#pragma unroll
        for (int i = 0; i < 16; i++) {         // 2048 elems / 128 threads
            int lin = tid + i * 128;
            int c = lin >> 6, tt = lin & 63;
            float wv = g_W[((size_t)(sbi * CIN + c0p + c)) * TFULL + t0 + tt];
            __nv_bfloat16 hb = __float2bfloat16(wv);
            wh16[tt * (2 * QS) + c] = hb;
            wl16[tt * (2 * QS) + c] = __float2bfloat16(wv - __bfloat162float(hb));
        }
        // ---- A tile fill: 128 e x 16 u32 (pre-packed bf16 pairs) ----
#pragma unroll
        for (int i = 0; i < 16; i++) {         // 2048 u32 / 128 threads
            int lin = tid + i * 128;
            int e = lin >> 4, cu = lin & 15;
            size_t gi = abase + (size_t)e * (CIN / 2) + p * 16 + cu;
            sAh[e * QS + cu] = g_Ahi[gi];
            sAl[e * QS + cu] = g_Alo[gi];
        }
        __syncthreads();

#pragma unroll
        for (int ks = 0; ks < 2; ks++) {
            const int ko = ks * 8;
            const int r0 = warp * 16 + gid;
            uint32 ah[4], al[4];
            ah[0] = sWh[r0 * QS + ko + tig];
            ah[1] = sWh[(r0 + 8) * QS + ko + tig];
            ah[2] = sWh[r0 * QS + ko + tig + 4];
            ah[3] = sWh[(r0 + 8) * QS + ko + tig + 4];
            al[0] = sWl[r0 * QS + ko + tig];
            al[1] = sWl[(r0 + 8) * QS + ko + tig];
            al[2] = sWl[r0 * QS + ko + tig + 4];
            al[3] = sWl[(r0 + 8) * QS + ko + tig + 4];
#pragma unroll
            for (int nt = 0; nt < 16; nt++) {
                const int er = 8 * nt + gid;
                uint32 b0h = sAh[er * QS + ko + tig];
                uint32 b1h = sAh[er * QS + ko + tig + 4];
                uint32 b0l = sAl[er * QS + ko + tig];
                uint32 b1l = sAl[er * QS + ko + tig + 4];
                mma_bf16(cacc[nt], ah, b0h, b1h);
                mma_bf16(cacc[nt], ah, b0l, b1l);
                mma_bf16(cacc[nt], al, b0h, b1h);
            }
        }
        __syncthreads();
    }

    // ---- epilogue: bias + per-w conversion ----
    const float* cb = g_cb + (s * 3 + w) * DMODEL;
    const int r = row0 + warp * 16 + gid;
#pragma unroll
    for (int nt = 0; nt < 16; nt++) {
        const int e0 = 8 * nt + 2 * tig;
        float b0v = cb[e0], b1v = cb[e0 + 1];
        float v00 = cacc[nt][0] + b0v, v01 = cacc[nt][1] + b1v;   // row r
        float v10 = cacc[nt][2] + b0v, v11 = cacc[nt][3] + b1v;   // row r+8
        size_t o0 = (size_t)r * DMODEL + e0;
        size_t o1 = (size_t)(r + 8) * DMODEL + e0;
        if (w == 0) {
            *(float2*)(g_q + o0) = make_float2(v00, v01);
            *(float2*)(g_q + o1) = make_float2(v10, v11);
        } else if (w == 1) {
            __nv_bfloat16 h00 = __float2bfloat16(v00);
            __nv_bfloat16 h01 = __float2bfloat16(v01);
            __nv_bfloat16 h10 = __float2bfloat16(v10);
            __nv_bfloat16 h11 = __float2bfloat16(v11);
            *(__nv_bfloat162*)(g_kh16 + o0) = __nv_bfloat162(h00, h01);
            *(__nv_bfloat162*)(g_kh16 + o1) = __nv_bfloat162(h10, h11);
            *(__nv_bfloat162*)(g_kl16 + o0) = __nv_bfloat162(
                __float2bfloat16(v00 - __bfloat162float(h00)),
                __float2bfloat16(v01 - __bfloat162float(h01)));
            *(__nv_bfloat162*)(g_kl16 + o1) = __nv_bfloat162(
                __float2bfloat16(v10 - __bfloat162float(h10)),
                __float2bfloat16(v11 - __bfloat162float(h11)));
        } else {
            *(float2*)(g_vt + o0) = make_float2(__uint_as_float(cvt_tf32(v00)),
                                                __uint_as_float(cvt_tf32(v01)));
            *(float2*)(g_vt + o1) = make_float2(__uint_as_float(cvt_tf32(v10)),
                                                __uint_as_float(cvt_tf32(v11)));
        }
    }
}

// ================= K3: flash attention, split-K x2, bf16 QK + tf32 PV =================
#define KS16    12
#define VSTRIDE 24
#define KCH     32
__global__ void k_attn() {
    __shared__ __align__(16) uint32 sKh[2 * KCH * KS16];
    __shared__ __align__(16) uint32 sKl[2 * KCH * KS16];
    __shared__ __align__(16) float  sV [2 * KCH * VSTRIDE];

    const int tid  = threadIdx.x;
    const int warp = tid >> 5, lane = tid & 31;
    const int gid  = lane >> 2, tig = lane & 3;
    const int qt = blockIdx.x, h = blockIdx.y;
    const int sb = blockIdx.z >> 1, kh = blockIdx.z & 1;
    const int qbase = qt * 128 + warp * 32;
    const int kbeg = kh * KHALF;

    const float sc = 0.25f * 1.4426950408889634f;

    uint32 ahi[2][4], alo[2][4];
#pragma unroll
    for (int g = 0; g < 2; g++) {
#pragma unroll
        for (int rr = 0; rr < 2; rr++) {
            const float* qr = g_q + ((size_t)(sb * TFULL) + qbase + g * 16 + gid + rr * 8) * DMODEL + h * DH;
            float2 pa = *(const float2*)(qr + 2 * tig);
            float2 pb = *(const float2*)(qr + 2 * tig + 8);
            float ax = pa.x * sc, ay = pa.y * sc;
            float bx = pb.x * sc, by = pb.y * sc;
            float axh = __bfloat162float(__float2bfloat16(ax));
            float ayh = __bfloat162float(__float2bfloat16(ay));
            float bxh = __bfloat162float(__float2bfloat16(bx));
            float byh = __bfloat162float(__float2bfloat16(by));
            ahi[g][rr]     = pkbf(axh, ayh);
            alo[g][rr]     = pkbf(ax - axh, ay - ayh);
            ahi[g][rr + 2] = pkbf(bxh, byh);
            alo[g][rr + 2] = pkbf(bx - bxh, by - byh);
        }
    }

    float m_lo[2] = { -1e30f, -1e30f }, m_hi[2] = { -1e30f, -1e30f };
    float l_lo[2] = { 0.f, 0.f },       l_hi[2] = { 0.f, 0.f };
    float oc[2][2][4];
#pragma unroll
    for (int g = 0; g < 2; g++)
#pragma unroll
        for (int nv = 0; nv < 2; nv++)
#pragma unroll
            for (int i = 0; i < 4; i++) oc[g][nv][i] = 0.f;

    const int sigma = (gid >> 1) + ((gid & 1) << 2);

    const int kr = (tid & 63) >> 1, kh2 = tid & 1;
    const int vr = tid >> 2,        vc  = tid & 3;
    const size_t gbase = (size_t)(sb * TFULL) * DMODEL + h * DH;
    const __nv_bfloat16* gK = (tid < 64) ? g_kh16 : g_kl16;
    const uint32 sK_b = (uint32)__cvta_generic_to_shared(tid < 64 ? sKh : sKl)
                        + (kr * KS16 + kh2 * 4) * 4;
    const uint32 sV_b = (uint32)__cvta_generic_to_shared(sV) + (vr * VSTRIDE + vc * 4) * 4;

    const uint32* kh_base = sKh + sigma * KS16 + tig;
    const uint32* kl_base = sKl + sigma * KS16 + tig;
    const float* v0_base = sV + tig * VSTRIDE + gid;
    const float* v1_base = sV + (tig + 4) * VSTRIDE + gid;

    {
        cp16(sK_b, gK + gbase + (size_t)(kbeg + kr) * DMODEL + kh2 * 8);
        cp16(sV_b, g_vt + gbase + (size_t)(kbeg + vr) * DMODEL + vc * 4);
        asm volatile("cp.async.commit_group;" ::: "memory");
    }

#pragma unroll 2
    for (int c = 0; c < KHALF / KCH; c++) {
        asm volatile("cp.async.wait_group 0;" ::: "memory");
        __syncthreads();
        if (c + 1 < KHALF / KCH) {
            int nb = (c + 1) & 1;
            int rbase = kbeg + (c + 1) * KCH;
            cp16(sK_b + nb * (KCH * KS16 * 4),
                 gK + gbase + (size_t)(rbase + kr) * DMODEL + kh2 * 8);
            cp16(sV_b + nb * (KCH * VSTRIDE * 4),
                 g_vt + gbase + (size_t)(rbase + vr) * DMODEL + vc * 4);
            asm volatile("cp.async.commit_group;" ::: "memory");
        }
        const int buf = c & 1;
        const uint32* khB = kh_base + buf * (KCH * KS16);
        const uint32* klB = kl_base + buf * (KCH * KS16);
        const float* v0B = v0_base + buf * (KCH * VSTRIDE);
        const float* v1B = v1_base + buf * (KCH * VSTRIDE);

        float cS[2][4][4];
#pragma unroll
        for (int nt = 0; nt < 4; nt++) {
#pragma unroll
            for (int g = 0; g < 2; g++) {
                cS[g][nt][0] = 0.f; cS[g][nt][1] = 0.f;
                cS[g][nt][2] = 0.f; cS[g][nt][3] = 0.f;
            }
            uint32 b0h = khB[nt * 8 * KS16];
            uint32 b1h = khB[nt * 8 * KS16 + 4];
            uint32 b0l = klB[nt * 8 * KS16];
            uint32 b1l = klB[nt * 8 * KS16 + 4];
#pragma unroll
            for (int g = 0; g < 2; g++) {
                mma_bf16(cS[g][nt], ahi[g], b0h, b1h);
                mma_bf16(cS[g][nt], ahi[g], b0l, b1l);
                mma_bf16(cS[g][nt], alo[g], b0h, b1h);
            }
        }

#pragma unroll
        for (int g = 0; g < 2; g++) {
            float mx0 = m_lo[g], mx1 = m_hi[g];
#pragma unroll
            for (int nt = 0; nt < 4; nt++) {
                mx0 = fmaxf(mx0, fmaxf(cS[g][nt][0], cS[g][nt][1]));
                mx1 = fmaxf(mx1, fmaxf(cS[g][nt][2], cS[g][nt][3]));
            }
            mx0 = fmaxf(mx0, __shfl_xor_sync(0xffffffffu, mx0, 1));
            mx0 = fmaxf(mx0, __shfl_xor_sync(0xffffffffu, mx0, 2));
            mx1 = fmaxf(mx1, __shfl_xor_sync(0xffffffffu, mx1, 1));
            mx1 = fmaxf(mx1, __shfl_xor_sync(0xffffffffu, mx1, 2));
            float cr0 = exp2f(m_lo[g] - mx0), cr1 = exp2f(m_hi[g] - mx1);
            m_lo[g] = mx0; m_hi[g] = mx1;
            l_lo[g] *= cr0; l_hi[g] *= cr1;
#pragma unroll
            for (int nv = 0; nv < 2; nv++) {
                oc[g][nv][0] *= cr0; oc[g][nv][1] *= cr0;
                oc[g][nv][2] *= cr1; oc[g][nv][3] *= cr1;
            }
#pragma unroll
            for (int nt = 0; nt < 4; nt++) {
                float p0 = exp2f(cS[g][nt][0] - mx0);
                float p1 = exp2f(cS[g][nt][1] - mx0);
                float p2 = exp2f(cS[g][nt][2] - mx1);
                float p3 = exp2f(cS[g][nt][3] - mx1);
                l_lo[g] += p0 + p1;
                l_hi[g] += p2 + p3;
                cS[g][nt][0] = p0;
                cS[g][nt][1] = p1;
                cS[g][nt][2] = p2;
                cS[g][nt][3] = p3;
            }
        }

#pragma unroll
        for (int j = 0; j < 4; j++) {
            const float* v0 = v0B + 8 * j * VSTRIDE;
            const float* v1 = v1B + 8 * j * VSTRIDE;
            uint32 b0a = __float_as_uint(v0[0]);
            uint32 b1a = __float_as_uint(v1[0]);
            uint32 b0b = __float_as_uint(v0[8]);
            uint32 b1b = __float_as_uint(v1[8]);
#pragma unroll
            for (int g = 0; g < 2; g++) {
                uint32 ap[4] = { __float_as_uint(cS[g][j][0]), __float_as_uint(cS[g][j][2]),
                                 __float_as_uint(cS[g][j][1]), __float_as_uint(cS[g][j][3]) };
                mma_tf32(oc[g][0], ap, b0a, b1a);
                mma_tf32(oc[g][1], ap, b0b, b1b);
            }
        }
    }

#pragma unroll
    for (int g = 0; g < 2; g++) {
        float ll = l_lo[g], lh = l_hi[g];
        ll += __shfl_xor_sync(0xffffffffu, ll, 1);
        ll += __shfl_xor_sync(0xffffffffu, ll, 2);
        lh += __shfl_xor_sync(0xffffffffu, lh, 1);
        lh += __shfl_xor_sync(0xffffffffu, lh, 2);

        const int r1 = qbase + g * 16 + gid;
        float* pb = g_pacc + (((size_t)(kh * (SNUM * BNUM) + sb)) * TFULL + r1) * DMODEL + h * DH;
#pragma unroll
        for (int nv = 0; nv < 2; nv++) {
            *(float2*)(pb + 2 * tig + 8 * nv) =
                make_float2(oc[g][nv][0], oc[g][nv][1]);
            *(float2*)(pb + 8 * DMODEL + 2 * tig + 8 * nv) =
                make_float2(oc[g][nv][2], oc[g][nv][3]);
        }
        if (tig == 0) {
            float2* pml = (float2*)g_pml;
            size_t base = ((size_t)(kh * (SNUM * BNUM) + sb)) * TFULL;
            pml[(base + r1) * HNUM + h]     = make_float2(m_lo[g], ll);
            pml[(base + r1 + 8) * HNUM + h] = make_float2(m_hi[g], lh);
        }
    }
}

// ================= K3b: merge split-K halves =================
__global__ void k_merge() {
    const int idx = blockIdx.x * 256 + threadIdx.x;
    const int h = idx & 7;
    const int t = (idx >> 3) & (TFULL - 1);
    const int sb = idx >> 14;
    const size_t r0 = (size_t)sb * TFULL + t;
    const size_t r1 = (size_t)(SNUM * BNUM + sb) * TFULL + t;

    float2 ml0 = ((const float2*)g_pml)[r0 * HNUM + h];
    float2 ml1 = ((const float2*)g_pml)[r1 * HNUM + h];
    float M = fmaxf(ml0.x, ml1.x);
    float e0 = exp2f(ml0.x - M);
    float e1 = exp2f(ml1.x - M);
    float inv = 1.f / (e0 * ml0.y + e1 * ml1.y);
    e0 *= inv; e1 *= inv;

    const float* p0 = g_pacc + r0 * DMODEL + h * DH;
    const float* p1 = g_pacc + r1 * DMODEL + h * DH;
    float* ob = g_o + ((size_t)sb * TFULL + t) * DMODEL + h * DH;
#pragma unroll
    for (int i = 0; i < 4; i++) {
        float4 a = *(const float4*)(p0 + i * 4);
        float4 b = *(const float4*)(p1 + i * 4);
        *(float4*)(ob + i * 4) = make_float4(a.x * e0 + b.x * e1,
                                             a.y * e0 + b.y * e1,
                                             a.z * e0 + b.z * e1,
                                             a.w * e0 + b.w * e1);
    }
}

// ================= K4: partial t-sums =================
__global__ void k_meanred() {
    const int s = blockIdx.x, b = blockIdx.y, ch = blockIdx.z;
    const int d = threadIdx.x;
    const float* base = g_o + (((size_t)(s * BNUM + b) * TFULL) + ch * 128) * DMODEL + d;
    float sum = 0.f;
#pragma unroll 8
    for (int t = 0; t < 128; t++) sum += base[t * DMODEL];
    g_meanp[((s * BNUM + b) * 16 + ch) * DMODEL + d] = sum;
}

// ================= K5: gate computation =================
__global__ void k_gate(const float* __restrict__ out_w, const float* __restrict__ out_b,
                       const float* __restrict__ gate_w, const float* __restrict__ gate_b) {
    __shared__ float sh_m[DMODEL];
    __shared__ float sh_gf[DMODEL];
    __shared__ float sh_lg[SNUM];
    const int d = threadIdx.x;
    for (int b = 0; b < BNUM; b++) {
        float mv = 0.f;
#pragma unroll
        for (int s = 0; s < SNUM; s++)
#pragma unroll
            for (int c = 0; c < 16; c++)
                mv += g_meanp[((s * BNUM + b) * 16 + c) * DMODEL + d];
        sh_m[d] = mv;
        __syncthreads();
        float acc = 0.f;
        const float* ow = out_w + d * DMODEL;
#pragma unroll 4
        for (int dd = 0; dd < DMODEL; dd++) acc += ow[dd] * sh_m[dd];
        sh_gf[d] = acc * (1.0f / (TFULL * SNUM)) + out_b[d];
        __syncthreads();
        if (d < SNUM) {
            float lg = gate_b[d];
            for (int dd = 0; dd < DMODEL; dd++) lg += sh_gf[dd] * gate_w[d * DMODEL + dd];
            sh_lg[d] = lg;
        }
        __syncthreads();
        if (d == 0) {
            float mx = fmaxf(sh_lg[0], fmaxf(sh_lg[1], sh_lg[2]));
            float e0 = __expf(sh_lg[0] - mx);
            float e1 = __expf(sh_lg[1] - mx);
            float e2 = __expf(sh_lg[2] - mx);
            float inv = 1.f / (e0 + e1 + e2);
            g_gate[b * 3 + 0] = e0 * inv;
            g_gate[b * 3 + 1] = e1 * inv;
            g_gate[b * 3 + 2] = e2 * inv;
        }
        __syncthreads();
    }
}

// ================= K6: gated combine + output projection (128 blocks) =================
__global__ void __launch_bounds__(256) k_final(const float* __restrict__ out_w,
                                               const float* __restrict__ out_b,
                                               float* __restrict__ Z) {
    __shared__ float shI[32][33];
    __shared__ float shWt[128][33];
    const int row0 = blockIdx.x * 32;
    const int tid = threadIdx.x;
    const int b = row0 >> 11;
    const float gt0 = g_gate[b * 3 + 0];
    const float gt1 = g_gate[b * 3 + 1];
    const float gt2 = g_gate[b * 3 + 2];
    const int ty = tid >> 4, tx = tid & 15;
    const size_t SB = (size_t)BNUM * TFULL * DMODEL;

    float acc[2][8];
#pragma unroll
    for (int i = 0; i < 2; i++)
#pragma unroll
        for (int j = 0; j < 8; j++) acc[i][j] = 0.f;

    for (int c0 = 0; c0 < DMODEL; c0 += 32) {
#pragma unroll
        for (int i = 0; i < 4; i++) {
            int lin = tid + i * 256;
            int rr = lin >> 5, cc = lin & 31;
            size_t idx = (size_t)(row0 + rr) * DMODEL + c0 + cc;
            float v0 = g_o[idx];
            float v1 = g_o[SB + idx];
            float v2 = g_o[2 * SB + idx];
            shI[rr][cc] = gt0 * v0 + gt1 * v1 + gt2 * v2;
        }
#pragma unroll
        for (int i = 0; i < 16; i++) {
            int lin = tid + i * 256;
            shWt[lin >> 5][lin & 31] = out_w[(lin >> 5) * DMODEL + c0 + (lin & 31)];
        }
        __syncthreads();
#pragma unroll
        for (int cc = 0; cc < 32; cc++) {
            float ir[2], wr[8];
#pragma unroll
            for (int i = 0; i < 2; i++) ir[i] = shI[i * 16 + ty][cc];
#pragma unroll
            for (int j = 0; j < 8; j++) wr[j] = shWt[j * 16 + tx][cc];
#pragma unroll
            for (int i = 0; i < 2; i++)
#pragma unroll
                for (int j = 0; j < 8; j++) acc[i][j] += ir[i] * wr[j];
        }
        __syncthreads();
    }

#pragma unroll
    for (int i = 0; i < 2; i++) {
        int r = row0 + i * 16 + ty;
#pragma unroll
        for (int j = 0; j < 8; j++) {
            int e = j * 16 + tx;
            Z[(size_t)r * DMODEL + e] = acc[i][j] + out_b[e];
        }
    }
}

// ================= launch =================
extern "C" void kernel_launch(void* const* d_in, const int* in_sizes, int n_in,
                              void* d_out, int out_size) {
    const float* x      = (const float*)d_in[0];
    const float* Wq     = (const float*)d_in[1];
    const float* bq     = (const float*)d_in[2];
    const float* Wk     = (const float*)d_in[3];
    const float* bk     = (const float*)d_in[4];
    const float* Wv     = (const float*)d_in[5];
    const float* bv     = (const float*)d_in[6];
    const float* in_w   = (const float*)d_in[7];
    const float* in_b   = (const float*)d_in[8];
    const float* out_w  = (const float*)d_in[9];
    const float* out_b  = (const float*)d_in[10];
    const float* gate_w = (const float*)d_in[11];
    const float* gate_b = (const float*)d_in[12];
    float* Z = (float*)d_out;

    k_swt    <<<BNUM * CIN, 256>>>(x);
    k_compose<<<dim3(9, 16), 256>>>(Wq, bq, Wk, bk, Wv, bv, in_w, in_b);
    k_qkv    <<<dim3(192, 3), 128>>>();
    k_attn   <<<dim3(16, HNUM, SNUM * BNUM * 2), 128>>>();
    k_merge  <<<384, 256>>>();
    k_meanred<<<dim3(SNUM, BNUM, 16), 128>>>();
    k_gate   <<<1, DMODEL>>>(out_w, out_b, gate_w, gate_b);
    k_final  <<<128, 256>>>(out_w, out_b, Z);
}

// round 15
// speedup vs baseline: 1.4222x; 1.0183x over previous
#include <cuda_runtime.h>
#include <cuda_bf16.h>

#define TFULL 2048
#define CIN   64
#define DMODEL 128
#define SNUM  3
#define BNUM  2
#define HNUM  8
#define DH    16
#define KHALF 1024

typedef unsigned int uint32;

__device__ __forceinline__ uint32 cvt_tf32(float x) {
    uint32 r; asm("cvt.rna.tf32.f32 %0,%1;" : "=r"(r) : "f"(x)); return r;
}
__device__ __forceinline__ void mma_tf32(float* d, const uint32* a, uint32 b0, uint32 b1) {
    asm volatile("mma.sync.aligned.m16n8k8.row.col.f32.tf32.tf32.f32 "
        "{%0,%1,%2,%3},{%4,%5,%6,%7},{%8,%9},{%0,%1,%2,%3};"
        : "+f"(d[0]), "+f"(d[1]), "+f"(d[2]), "+f"(d[3])
        : "r"(a[0]), "r"(a[1]), "r"(a[2]), "r"(a[3]), "r"(b0), "r"(b1));
}
__device__ __forceinline__ void mma_bf16(float* d, const uint32* a, uint32 b0, uint32 b1) {
    asm volatile("mma.sync.aligned.m16n8k16.row.col.f32.bf16.bf16.f32 "
        "{%0,%1,%2,%3},{%4,%5,%6,%7},{%8,%9},{%0,%1,%2,%3};"
        : "+f"(d[0]), "+f"(d[1]), "+f"(d[2]), "+f"(d[3])
        : "r"(a[0]), "r"(a[1]), "r"(a[2]), "r"(a[3]), "r"(b0), "r"(b1));
}
__device__ __forceinline__ void cp16(uint32 saddr, const void* g) {
    asm volatile("cp.async.cg.shared.global [%0], [%1], 16;" :: "r"(saddr), "l"(g));
}
__device__ __forceinline__ uint32 pkbf(float a, float b) {
    __nv_bfloat162 t = __floats2bfloat162_rn(a, b);
    return *reinterpret_cast<uint32*>(&t);
}

// ---------------- wavelet filters ----------------
__constant__ float c_DEC_LO[8] = {
    -0.010597401784997278f,  0.032883011666982945f,  0.030841381835986965f,
    -0.18703481171888114f,  -0.02798376941698385f,   0.6308807679295904f,
     0.7148465705525415f,    0.23037781330885523f };
__constant__ float c_DEC_HI[8] = {
    -0.23037781330885523f,   0.7148465705525415f,   -0.6308807679295904f,
    -0.02798376941698385f,   0.18703481171888114f,   0.030841381835986965f,
    -0.032883011666982945f, -0.010597401784997278f };

// ---------------- scratch ----------------
__device__ float g_W   [SNUM*BNUM*CIN*TFULL];             // channel-major
__device__ uint32 g_Ahi[SNUM*3*DMODEL*(CIN/2)];
__device__ uint32 g_Alo[SNUM*3*DMODEL*(CIN/2)];
__device__ float g_cb  [SNUM*3*DMODEL];
__device__ float g_q   [SNUM*BNUM*TFULL*DMODEL];
__device__ __nv_bfloat16 g_kh16[SNUM*BNUM*TFULL*DMODEL];
__device__ __nv_bfloat16 g_kl16[SNUM*BNUM*TFULL*DMODEL];
__device__ float g_vt  [SNUM*BNUM*TFULL*DMODEL];
__device__ float g_o   [SNUM*BNUM*TFULL*DMODEL];
__device__ float g_pacc[2*SNUM*BNUM*TFULL*DMODEL];
__device__ float g_pml [2*SNUM*BNUM*TFULL*HNUM*2];
__device__ float g_meanp[SNUM*BNUM*16*DMODEL];
__device__ float g_gate[BNUM*SNUM];   // unused now (gate computed in k_final)

// ================= K0: fused SWT + weight-compose (independent work) =================
// blocks [0,128): SWT for (b,c).  blocks [128, 128+144): compose.
__global__ void k_prep(const float* __restrict__ x,
                       const float* __restrict__ Wq, const float* __restrict__ bq,
                       const float* __restrict__ Wk, const float* __restrict__ bk,
                       const float* __restrict__ Wv, const float* __restrict__ bv,
                       const float* __restrict__ in_w, const float* __restrict__ in_b) {
    const int tid = threadIdx.x;
    if (blockIdx.x < 128) {
        // ---- SWT ----
        __shared__ float sh[2][TFULL];
        const int b = blockIdx.x >> 6;
        const int c = blockIdx.x & 63;
        for (int t = tid; t < TFULL; t += 256)
            sh[0][t] = x[(b * TFULL + t) * CIN + c];
        __syncthreads();
        int cur = 0;
        for (int j = 0; j < 3; j++) {
            const int step = 1 << j;
            float* wout = g_W + ((size_t)(((2 - j) * BNUM + b) * CIN + c)) * TFULL;
            for (int t = tid; t < TFULL; t += 256) {
                float d = 0.f, a = 0.f;
#pragma unroll
                for (int l = 0; l < 8; l++) {
                    float val = sh[cur][(t - l * step) & (TFULL - 1)];
                    d += val * c_DEC_HI[l];
                    a += val * c_DEC_LO[l];
                }
                wout[t] = d;
                sh[cur ^ 1][t] = a;
            }
            __syncthreads();
            cur ^= 1;
        }
    } else {
        // ---- compose ----
        const int blk = blockIdx.x - 128;      // 0..143
        const int sw = blk / 16;               // 0..8
        const int chunk = blk % 16;
        const int s = sw / 3, w = sw % 3;
        const float* Wx = (w == 0) ? Wq : (w == 1) ? Wk : Wv;
        const float* bx = (w == 0) ? bq : (w == 1) ? bk : bv;

        const int idx = chunk * 256 + tid;     // 0..4095
        const int e = idx >> 5, cp = idx & 31;
        const int c0 = 2 * cp;
        const float* iw = in_w + (w * DMODEL + e) * DMODEL;
        const float* wc0 = Wx + s * DMODEL * CIN + c0;
        float a0 = 0.f, a1 = 0.f;
#pragma unroll 4
        for (int dd = 0; dd < DMODEL; dd++) {
            float ww = iw[dd];
            a0 += ww * wc0[dd * CIN];
            a1 += ww * wc0[dd * CIN + 1];
        }
        float h0 = __bfloat162float(__float2bfloat16(a0));
        float h1 = __bfloat162float(__float2bfloat16(a1));
        const size_t oidx = (size_t)(sw * DMODEL + e) * (CIN / 2) + cp;
        g_Ahi[oidx] = pkbf(h0, h1);
        g_Alo[oidx] = pkbf(a0 - h0, a1 - h1);

        if (chunk == 0 && tid < DMODEL) {
            const int ee = tid;
            const float* iw2 = in_w + (w * DMODEL + ee) * DMODEL;
            float bb = in_b[w * DMODEL + ee];
#pragma unroll 4
            for (int dd = 0; dd < DMODEL; dd++) bb += iw2[dd] * bx[s * DMODEL + dd];
            g_cb[sw * DMODEL + ee] = bb;
        }
    }
}

// ================= K2: q/k/v projection on tensor cores (bf16 2-term split) =================
#define QS 20
__global__ void __launch_bounds__(128) k_qkv() {
    __shared__ uint32 sWh[64 * QS], sWl[64 * QS];
    __shared__ uint32 sAh[128 * QS], sAl[128 * QS];
    const int row0 = blockIdx.x * 64;
    const int w = blockIdx.y;
    const int s = row0 >> 12;
    const int sbi = row0 >> 11;
    const int t0 = row0 & (TFULL - 1);
    const int tid = threadIdx.x;
    const int warp = tid >> 5, lane = tid & 31;
    const int gid = lane >> 2, tig = lane & 3;

    float cacc[16][4];
#pragma unroll
    for (int nt = 0; nt < 16; nt++)
#pragma unroll
        for (int i = 0; i < 4; i++) cacc[nt][i] = 0.f;

    const size_t abase = (size_t)((s * 3 + w) * DMODEL) * (CIN / 2);

    for (int p = 0; p < 2; p++) {
        const int c0p = p * 32;
        __nv_bfloat16* wh16 = (__nv_bfloat16*)sWh;
        __nv_bfloat16* wl16 = (__nv_bfloat16*)sWl;
#pragma unroll
        for (int i = 0; i < 16; i++) {
            int lin = tid + i * 128;
            int c = lin >> 6, tt = lin & 63;
            float wv = g_W[((size_t)(sbi * CIN + c0p + c)) * TFULL + t0 + tt];
            __nv_bfloat16 hb = __float2bfloat16(wv);
            wh16[tt * (2 * QS) + c] = hb;
            wl16[tt * (2 * QS) + c] = __float2bfloat16(wv - __bfloat162float(hb));
        }
#pragma unroll
        for (int i = 0; i < 16; i++) {
            int lin = tid + i * 128;
            int e = lin >> 4, cu = lin & 15;
            size_t gi = abase + (size_t)e * (CIN / 2) + p * 16 + cu;
            sAh[e * QS + cu] = g_Ahi[gi];
            sAl[e * QS + cu] = g_Alo[gi];
        }
        __syncthreads();

#pragma unroll
        for (int ks = 0; ks < 2; ks++) {
            const int ko = ks * 8;
            const int r0 = warp * 16 + gid;
            uint32 ah[4], al[4];
            ah[0] = sWh[r0 * QS + ko + tig];
            ah[1] = sWh[(r0 + 8) * QS + ko + tig];
            ah[2] = sWh[r0 * QS + ko + tig + 4];
            ah[3] = sWh[(r0 + 8) * QS + ko + tig + 4];
            al[0] = sWl[r0 * QS + ko + tig];
            al[1] = sWl[(r0 + 8) * QS + ko + tig];
            al[2] = sWl[r0 * QS + ko + tig + 4];
            al[3] = sWl[(r0 + 8) * QS + ko + tig + 4];
#pragma unroll
            for (int nt = 0; nt < 16; nt++) {
                const int er = 8 * nt + gid;
                uint32 b0h = sAh[er * QS + ko + tig];
                uint32 b1h = sAh[er * QS + ko + tig + 4];
                uint32 b0l = sAl[er * QS + ko + tig];
                uint32 b1l = sAl[er * QS + ko + tig + 4];
                mma_bf16(cacc[nt], ah, b0h, b1h);
                mma_bf16(cacc[nt], ah, b0l, b1l);
                mma_bf16(cacc[nt], al, b0h, b1h);
            }
        }
        __syncthreads();
    }

    const float* cb = g_cb + (s * 3 + w) * DMODEL;
    const int r = row0 + warp * 16 + gid;
#pragma unroll
    for (int nt = 0; nt < 16; nt++) {
        const int e0 = 8 * nt + 2 * tig;
        float b0v = cb[e0], b1v = cb[e0 + 1];
        float v00 = cacc[nt][0] + b0v, v01 = cacc[nt][1] + b1v;
        float v10 = cacc[nt][2] + b0v, v11 = cacc[nt][3] + b1v;
        size_t o0 = (size_t)r * DMODEL + e0;
        size_t o1 = (size_t)(r + 8) * DMODEL + e0;
        if (w == 0) {
            *(float2*)(g_q + o0) = make_float2(v00, v01);
            *(float2*)(g_q + o1) = make_float2(v10, v11);
        } else if (w == 1) {
            __nv_bfloat16 h00 = __float2bfloat16(v00);
            __nv_bfloat16 h01 = __float2bfloat16(v01);
            __nv_bfloat16 h10 = __float2bfloat16(v10);
            __nv_bfloat16 h11 = __float2bfloat16(v11);
            *(__nv_bfloat162*)(g_kh16 + o0) = __nv_bfloat162(h00, h01);
            *(__nv_bfloat162*)(g_kh16 + o1) = __nv_bfloat162(h10, h11);
            *(__nv_bfloat162*)(g_kl16 + o0) = __nv_bfloat162(
                __float2bfloat16(v00 - __bfloat162float(h00)),
                __float2bfloat16(v01 - __bfloat162float(h01)));
            *(__nv_bfloat162*)(g_kl16 + o1) = __nv_bfloat162(
                __float2bfloat16(v10 - __bfloat162float(h10)),
                __float2bfloat16(v11 - __bfloat162float(h11)));
        } else {
            *(float2*)(g_vt + o0) = make_float2(__uint_as_float(cvt_tf32(v00)),
                                                __uint_as_float(cvt_tf32(v01)));
            *(float2*)(g_vt + o1) = make_float2(__uint_as_float(cvt_tf32(v10)),
                                                __uint_as_float(cvt_tf32(v11)));
        }
    }
}

// ================= K3: flash attention, split-K x2, bf16 QK + tf32 PV =================
#define KS16    12
#define VSTRIDE 24
#define KCH     32
__global__ void k_attn() {
    __shared__ __align__(16) uint32 sKh[2 * KCH * KS16];
    __shared__ __align__(16) uint32 sKl[2 * KCH * KS16];
    __shared__ __align__(16) float  sV [2 * KCH * VSTRIDE];

    const int tid  = threadIdx.x;
    const int warp = tid >> 5, lane = tid & 31;
    const int gid  = lane >> 2, tig = lane & 3;
    const int qt = blockIdx.x, h = blockIdx.y;
    const int sb = blockIdx.z >> 1, kh = blockIdx.z & 1;
    const int qbase = qt * 128 + warp * 32;
    const int kbeg = kh * KHALF;

    const float sc = 0.25f * 1.4426950408889634f;

    uint32 ahi[2][4], alo[2][4];
#pragma unroll
    for (int g = 0; g < 2; g++) {
#pragma unroll
        for (int rr = 0; rr < 2; rr++) {
            const float* qr = g_q + ((size_t)(sb * TFULL) + qbase + g * 16 + gid + rr * 8) * DMODEL + h * DH;
            float2 pa = *(const float2*)(qr + 2 * tig);
            float2 pb = *(const float2*)(qr + 2 * tig + 8);
            float ax = pa.x * sc, ay = pa.y * sc;
            float bx = pb.x * sc, by = pb.y * sc;
            float axh = __bfloat162float(__float2bfloat16(ax));
            float ayh = __bfloat162float(__float2bfloat16(ay));
            float bxh = __bfloat162float(__float2bfloat16(bx));
            float byh = __bfloat162float(__float2bfloat16(by));
            ahi[g][rr]     = pkbf(axh, ayh);
            alo[g][rr]     = pkbf(ax - axh, ay - ayh);
            ahi[g][rr + 2] = pkbf(bxh, byh);
            alo[g][rr + 2] = pkbf(bx - bxh, by - byh);
        }
    }

    float m_lo[2] = { -1e30f, -1e30f }, m_hi[2] = { -1e30f, -1e30f };
    float l_lo[2] = { 0.f, 0.f },       l_hi[2] = { 0.f, 0.f };
    float oc[2][2][4];
#pragma unroll
    for (int g = 0; g < 2; g++)
#pragma unroll
        for (int nv = 0; nv < 2; nv++)
#pragma unroll
            for (int i = 0; i < 4; i++) oc[g][nv][i] = 0.f;

    const int sigma = (gid >> 1) + ((gid & 1) << 2);

    const int kr = (tid & 63) >> 1, kh2 = tid & 1;
    const int vr = tid >> 2,        vc  = tid & 3;
    const size_t gbase = (size_t)(sb * TFULL) * DMODEL + h * DH;
    const __nv_bfloat16* gK = (tid < 64) ? g_kh16 : g_kl16;
    const uint32 sK_b = (uint32)__cvta_generic_to_shared(tid < 64 ? sKh : sKl)
                        + (kr * KS16 + kh2 * 4) * 4;
    const uint32 sV_b = (uint32)__cvta_generic_to_shared(sV) + (vr * VSTRIDE + vc * 4) * 4;

    const uint32* kh_base = sKh + sigma * KS16 + tig;
    const uint32* kl_base = sKl + sigma * KS16 + tig;
    const float* v0_base = sV + tig * VSTRIDE + gid;
    const float* v1_base = sV + (tig + 4) * VSTRIDE + gid;

    {
        cp16(sK_b, gK + gbase + (size_t)(kbeg + kr) * DMODEL + kh2 * 8);
        cp16(sV_b, g_vt + gbase + (size_t)(kbeg + vr) * DMODEL + vc * 4);
        asm volatile("cp.async.commit_group;" ::: "memory");
    }

#pragma unroll 2
    for (int c = 0; c < KHALF / KCH; c++) {
        asm volatile("cp.async.wait_group 0;" ::: "memory");
        __syncthreads();
        if (c + 1 < KHALF / KCH) {
            int nb = (c + 1) & 1;
            int rbase = kbeg + (c + 1) * KCH;
            cp16(sK_b + nb * (KCH * KS16 * 4),
                 gK + gbase + (size_t)(rbase + kr) * DMODEL + kh2 * 8);
            cp16(sV_b + nb * (KCH * VSTRIDE * 4),
                 g_vt + gbase + (size_t)(rbase + vr) * DMODEL + vc * 4);
            asm volatile("cp.async.commit_group;" ::: "memory");
        }
        const int buf = c & 1;
        const uint32* khB = kh_base + buf * (KCH * KS16);
        const uint32* klB = kl_base + buf * (KCH * KS16);
        const float* v0B = v0_base + buf * (KCH * VSTRIDE);
        const float* v1B = v1_base + buf * (KCH * VSTRIDE);

        float cS[2][4][4];
#pragma unroll
        for (int nt = 0; nt < 4; nt++) {
#pragma unroll
            for (int g = 0; g < 2; g++) {
                cS[g][nt][0] = 0.f; cS[g][nt][1] = 0.f;
                cS[g][nt][2] = 0.f; cS[g][nt][3] = 0.f;
            }
            uint32 b0h = khB[nt * 8 * KS16];
            uint32 b1h = khB[nt * 8 * KS16 + 4];
            uint32 b0l = klB[nt * 8 * KS16];
            uint32 b1l = klB[nt * 8 * KS16 + 4];
#pragma unroll
            for (int g = 0; g < 2; g++) {
                mma_bf16(cS[g][nt], ahi[g], b0h, b1h);
                mma_bf16(cS[g][nt], ahi[g], b0l, b1l);
                mma_bf16(cS[g][nt], alo[g], b0h, b1h);
            }
        }

#pragma unroll
        for (int g = 0; g < 2; g++) {
            float mx0 = m_lo[g], mx1 = m_hi[g];
#pragma unroll
            for (int nt = 0; nt < 4; nt++) {
                mx0 = fmaxf(mx0, fmaxf(cS[g][nt][0], cS[g][nt][1]));
                mx1 = fmaxf(mx1, fmaxf(cS[g][nt][2], cS[g][nt][3]));
            }
            mx0 = fmaxf(mx0, __shfl_xor_sync(0xffffffffu, mx0, 1));
            mx0 = fmaxf(mx0, __shfl_xor_sync(0xffffffffu, mx0, 2));
            mx1 = fmaxf(mx1, __shfl_xor_sync(0xffffffffu, mx1, 1));
            mx1 = fmaxf(mx1, __shfl_xor_sync(0xffffffffu, mx1, 2));
            float cr0 = exp2f(m_lo[g] - mx0), cr1 = exp2f(m_hi[g] - mx1);
            m_lo[g] = mx0; m_hi[g] = mx1;
            l_lo[g] *= cr0; l_hi[g] *= cr1;
#pragma unroll
            for (int nv = 0; nv < 2; nv++) {
                oc[g][nv][0] *= cr0; oc[g][nv][1] *= cr0;
                oc[g][nv][2] *= cr1; oc[g][nv][3] *= cr1;
            }
#pragma unroll
            for (int nt = 0; nt < 4; nt++) {
                float p0 = exp2f(cS[g][nt][0] - mx0);
                float p1 = exp2f(cS[g][nt][1] - mx0);
                float p2 = exp2f(cS[g][nt][2] - mx1);
                float p3 = exp2f(cS[g][nt][3] - mx1);
                l_lo[g] += p0 + p1;
                l_hi[g] += p2 + p3;
                cS[g][nt][0] = p0;
                cS[g][nt][1] = p1;
                cS[g][nt][2] = p2;
                cS[g][nt][3] = p3;
            }
        }

#pragma unroll
        for (int j = 0; j < 4; j++) {
            const float* v0 = v0B + 8 * j * VSTRIDE;
            const float* v1 = v1B + 8 * j * VSTRIDE;
            uint32 b0a = __float_as_uint(v0[0]);
            uint32 b1a = __float_as_uint(v1[0]);
            uint32 b0b = __float_as_uint(v0[8]);
            uint32 b1b = __float_as_uint(v1[8]);
#pragma unroll
            for (int g = 0; g < 2; g++) {
                uint32 ap[4] = { __float_as_uint(cS[g][j][0]), __float_as_uint(cS[g][j][2]),
                                 __float_as_uint(cS[g][j][1]), __float_as_uint(cS[g][j][3]) };
                mma_tf32(oc[g][0], ap, b0a, b1a);
                mma_tf32(oc[g][1], ap, b0b, b1b);
            }
        }
    }

#pragma unroll
    for (int g = 0; g < 2; g++) {
        float ll = l_lo[g], lh = l_hi[g];
        ll += __shfl_xor_sync(0xffffffffu, ll, 1);
        ll += __shfl_xor_sync(0xffffffffu, ll, 2);
        lh += __shfl_xor_sync(0xffffffffu, lh, 1);
        lh += __shfl_xor_sync(0xffffffffu, lh, 2);

        const int r1 = qbase + g * 16 + gid;
        float* pb = g_pacc + (((size_t)(kh * (SNUM * BNUM) + sb)) * TFULL + r1) * DMODEL + h * DH;
#pragma unroll
        for (int nv = 0; nv < 2; nv++) {
            *(float2*)(pb + 2 * tig + 8 * nv) =
                make_float2(oc[g][nv][0], oc[g][nv][1]);
            *(float2*)(pb + 8 * DMODEL + 2 * tig + 8 * nv) =
                make_float2(oc[g][nv][2], oc[g][nv][3]);
        }
        if (tig == 0) {
            float2* pml = (float2*)g_pml;
            size_t base = ((size_t)(kh * (SNUM * BNUM) + sb)) * TFULL;
            pml[(base + r1) * HNUM + h]     = make_float2(m_lo[g], ll);
            pml[(base + r1 + 8) * HNUM + h] = make_float2(m_hi[g], lh);
        }
    }
}

// ================= K3b: fused merge + t-sum =================
// grid (16 chunks, 6 sb), block 256. Merges split-K halves into g_o and
// accumulates per-d sums over the 128-t chunk (deterministic fixed order).
__global__ void k_mergesum() {
    __shared__ float2 sh_sc[128 * HNUM];   // (e0,e1) per (t_local, h)
    __shared__ float  sh_sum[256];
    const int ch = blockIdx.x, sb = blockIdx.y;
    const int tid = threadIdx.x;
    const int t0 = ch * 128;
    const size_t base0 = (size_t)sb * TFULL;
    const size_t base1 = (size_t)(SNUM * BNUM + sb) * TFULL;

    // phase A: merge scales per (t_local, h)
    const float2* pml = (const float2*)g_pml;
#pragma unroll
    for (int i = 0; i < 4; i++) {
        int k = tid + i * 256;             // 0..1023
        int tl = k >> 3, h = k & 7;
        float2 ml0 = pml[(base0 + t0 + tl) * HNUM + h];
        float2 ml1 = pml[(base1 + t0 + tl) * HNUM + h];
        float M = fmaxf(ml0.x, ml1.x);
        float e0 = exp2f(ml0.x - M);
        float e1 = exp2f(ml1.x - M);
        float inv = 1.f / (e0 * ml0.y + e1 * ml1.y);
        sh_sc[tl * HNUM + h] = make_float2(e0 * inv, e1 * inv);
    }
    __syncthreads();

    // phase B: merge + accumulate. thread = (d, tp); t order fixed per thread.
    const int d = tid & 127, tp = tid >> 7;
    const int hh = d >> 4;
    float sum = 0.f;
    for (int tl = tp; tl < 128; tl += 2) {
        float2 scv = sh_sc[tl * HNUM + hh];
        size_t ri = (base0 + t0 + tl) * DMODEL + d;
        float p0 = g_pacc[ri];
        float p1 = g_pacc[(base1 + t0 + tl) * DMODEL + d];
        float o = p0 * scv.x + p1 * scv.y;
        g_o[ri] = o;
        sum += o;
    }
    sh_sum[tid] = sum;
    __syncthreads();
    if (tid < 128)
        g_meanp[((size_t)sb * 16 + ch) * DMODEL + d] = sh_sum[tid] + sh_sum[tid + 128];
}

// ================= K6: gate (per-block redundant) + gated combine + out-proj =================
__global__ void __launch_bounds__(256) k_final(const float* __restrict__ out_w,
                                               const float* __restrict__ out_b,
                                               const float* __restrict__ gate_w,
                                               const float* __restrict__ gate_b,
                                               float* __restrict__ Z) {
    __shared__ float shI[32][33];
    __shared__ float shWt[128][33];
    __shared__ float sh_m[DMODEL];
    __shared__ float sh_gf[DMODEL];
    __shared__ float sh_g[4];
    const int row0 = blockIdx.x * 32;
    const int tid = threadIdx.x;
    const int b = row0 >> 11;
    const int ty = tid >> 4, tx = tid & 15;
    const size_t SB = (size_t)BNUM * TFULL * DMODEL;

    // ---- compute gate for batch b (redundant per block; trivial cost) ----
    if (tid < DMODEL) {
        float mv = 0.f;
#pragma unroll
        for (int s = 0; s < SNUM; s++)
#pragma unroll
            for (int c = 0; c < 16; c++)
                mv += g_meanp[((size_t)(s * BNUM + b) * 16 + c) * DMODEL + tid];
        sh_m[tid] = mv;
    }
    __syncthreads();
    if (tid < DMODEL) {
        float acc = 0.f;
        const float* ow = out_w + tid * DMODEL;
#pragma unroll 4
        for (int dd = 0; dd < DMODEL; dd++) acc += ow[dd] * sh_m[dd];
        sh_gf[tid] = acc * (1.0f / (TFULL * SNUM)) + out_b[tid];
    }
    __syncthreads();
    if (tid < SNUM) {
        float lg = gate_b[tid];
        for (int dd = 0; dd < DMODEL; dd++) lg += sh_gf[dd] * gate_w[tid * DMODEL + dd];
        sh_m[tid] = lg;                    // reuse sh_m for logits
    }
    __syncthreads();
    if (tid == 0) {
        float mx = fmaxf(sh_m[0], fmaxf(sh_m[1], sh_m[2]));
        float e0 = __expf(sh_m[0] - mx);
        float e1 = __expf(sh_m[1] - mx);
        float e2 = __expf(sh_m[2] - mx);
        float inv = 1.f / (e0 + e1 + e2);
        sh_g[0] = e0 * inv; sh_g[1] = e1 * inv; sh_g[2] = e2 * inv;
    }
    __syncthreads();
    const float gt0 = sh_g[0], gt1 = sh_g[1], gt2 = sh_g[2];

    float acc[2][8];
#pragma unroll
    for (int i = 0; i < 2; i++)
#pragma unroll
        for (int j = 0; j < 8; j++) acc[i][j] = 0.f;

    for (int c0 = 0; c0 < DMODEL; c0 += 32) {
#pragma unroll
        for (int i = 0; i < 4; i++) {
            int lin = tid + i * 256;
            int rr = lin >> 5, cc = lin & 31;
            size_t idx = (size_t)(row0 + rr) * DMODEL + c0 + cc;
            float v0 = g_o[idx];
            float v1 = g_o[SB + idx];
            float v2 = g_o[2 * SB + idx];
            shI[rr][cc] = gt0 * v0 + gt1 * v1 + gt2 * v2;
        }
#pragma unroll
        for (int i = 0; i < 16; i++) {
            int lin = tid + i * 256;
            shWt[lin >> 5][lin & 31] = out_w[(lin >> 5) * DMODEL + c0 + (lin & 31)];
        }
        __syncthreads();
#pragma unroll
        for (int cc = 0; cc < 32; cc++) {
            float ir[2], wr[8];
#pragma unroll
            for (int i = 0; i < 2; i++) ir[i] = shI[i * 16 + ty][cc];
#pragma unroll
            for (int j = 0; j < 8; j++) wr[j] = shWt[j * 16 + tx][cc];
#pragma unroll
            for (int i = 0; i < 2; i++)
#pragma unroll
                for (int j = 0; j < 8; j++) acc[i][j] += ir[i] * wr[j];
        }
        __syncthreads();
    }

#pragma unroll
    for (int i = 0; i < 2; i++) {
        int r = row0 + i * 16 + ty;
#pragma unroll
        for (int j = 0; j < 8; j++) {
            int e = j * 16 + tx;
            Z[(size_t)r * DMODEL + e] = acc[i][j] + out_b[e];
        }
    }
}

// ================= launch =================
extern "C" void kernel_launch(void* const* d_in, const int* in_sizes, int n_in,
                              void* d_out, int out_size) {
    const float* x      = (const float*)d_in[0];
    const float* Wq     = (const float*)d_in[1];
    const float* bq     = (const float*)d_in[2];
    const float* Wk     = (const float*)d_in[3];
    const float* bk     = (const float*)d_in[4];
    const float* Wv     = (const float*)d_in[5];
    const float* bv     = (const float*)d_in[6];
    const float* in_w   = (const float*)d_in[7];
    const float* in_b   = (const float*)d_in[8];
    const float* out_w  = (const float*)d_in[9];
    const float* out_b  = (const float*)d_in[10];
    const float* gate_w = (const float*)d_in[11];
    const float* gate_b = (const float*)d_in[12];
    float* Z = (float*)d_out;

    k_prep    <<<128 + 144, 256>>>(x, Wq, bq, Wk, bk, Wv, bv, in_w, in_b);
    k_qkv     <<<dim3(192, 3), 128>>>();
    k_attn    <<<dim3(16, HNUM, SNUM * BNUM * 2), 128>>>();
    k_mergesum<<<dim3(16, SNUM * BNUM), 256>>>();
    k_final   <<<128, 256>>>(out_w, out_b, gate_w, gate_b, Z);
}

// round 16
// speedup vs baseline: 1.5348x; 1.0792x over previous
#include <cuda_runtime.h>
#include <cuda_bf16.h>

#define TFULL 2048
#define CIN   64
#define DMODEL 128
#define SNUM  3
#define BNUM  2
#define HNUM  8
#define DH    16
#define KHALF 1024

typedef unsigned int uint32;

__device__ __forceinline__ uint32 cvt_tf32(float x) {
    uint32 r; asm("cvt.rna.tf32.f32 %0,%1;" : "=r"(r) : "f"(x)); return r;
}
__device__ __forceinline__ void mma_tf32(float* d, const uint32* a, uint32 b0, uint32 b1) {
    asm volatile("mma.sync.aligned.m16n8k8.row.col.f32.tf32.tf32.f32 "
        "{%0,%1,%2,%3},{%4,%5,%6,%7},{%8,%9},{%0,%1,%2,%3};"
        : "+f"(d[0]), "+f"(d[1]), "+f"(d[2]), "+f"(d[3])
        : "r"(a[0]), "r"(a[1]), "r"(a[2]), "r"(a[3]), "r"(b0), "r"(b1));
}
__device__ __forceinline__ void mma_bf16(float* d, const uint32* a, uint32 b0, uint32 b1) {
    asm volatile("mma.sync.aligned.m16n8k16.row.col.f32.bf16.bf16.f32 "
        "{%0,%1,%2,%3},{%4,%5,%6,%7},{%8,%9},{%0,%1,%2,%3};"
        : "+f"(d[0]), "+f"(d[1]), "+f"(d[2]), "+f"(d[3])
        : "r"(a[0]), "r"(a[1]), "r"(a[2]), "r"(a[3]), "r"(b0), "r"(b1));
}
__device__ __forceinline__ void cp16(uint32 saddr, const void* g) {
    asm volatile("cp.async.cg.shared.global [%0], [%1], 16;" :: "r"(saddr), "l"(g));
}
__device__ __forceinline__ uint32 pkbf(float a, float b) {
    __nv_bfloat162 t = __floats2bfloat162_rn(a, b);
    return *reinterpret_cast<uint32*>(&t);
}

// ---------------- wavelet filters ----------------
__constant__ float c_DEC_LO[8] = {
    -0.010597401784997278f,  0.032883011666982945f,  0.030841381835986965f,
    -0.18703481171888114f,  -0.02798376941698385f,   0.6308807679295904f,
     0.7148465705525415f,    0.23037781330885523f };
__constant__ float c_DEC_HI[8] = {
    -0.23037781330885523f,   0.7148465705525415f,   -0.6308807679295904f,
    -0.02798376941698385f,   0.18703481171888114f,   0.030841381835986965f,
    -0.032883011666982945f, -0.010597401784997278f };

// ---------------- scratch ----------------
__device__ float g_W   [SNUM*BNUM*CIN*TFULL];             // channel-major
__device__ uint32 g_Ahi[SNUM*3*DMODEL*(CIN/2)];
__device__ uint32 g_Alo[SNUM*3*DMODEL*(CIN/2)];
__device__ float g_cb  [SNUM*3*DMODEL];
__device__ float g_q   [SNUM*BNUM*TFULL*DMODEL];
__device__ __nv_bfloat16 g_kh16[SNUM*BNUM*TFULL*DMODEL];
__device__ __nv_bfloat16 g_kl16[SNUM*BNUM*TFULL*DMODEL];
__device__ float g_vt  [SNUM*BNUM*TFULL*DMODEL];
__device__ float g_o   [SNUM*BNUM*TFULL*DMODEL];
__device__ float g_pacc[2*SNUM*BNUM*TFULL*DMODEL];
__device__ float g_pml [2*SNUM*BNUM*TFULL*HNUM*2];
__device__ float g_meanp[SNUM*BNUM*64*DMODEL];            // 64 chunks of 32 t

// ================= K0: fused SWT + weight-compose =================
__global__ void k_prep(const float* __restrict__ x,
                       const float* __restrict__ Wq, const float* __restrict__ bq,
                       const float* __restrict__ Wk, const float* __restrict__ bk,
                       const float* __restrict__ Wv, const float* __restrict__ bv,
                       const float* __restrict__ in_w, const float* __restrict__ in_b) {
    const int tid = threadIdx.x;
    if (blockIdx.x < 128) {
        __shared__ float sh[2][TFULL];
        const int b = blockIdx.x >> 6;
        const int c = blockIdx.x & 63;
        for (int t = tid; t < TFULL; t += 256)
            sh[0][t] = x[(b * TFULL + t) * CIN + c];
        __syncthreads();
        int cur = 0;
        for (int j = 0; j < 3; j++) {
            const int step = 1 << j;
            float* wout = g_W + ((size_t)(((2 - j) * BNUM + b) * CIN + c)) * TFULL;
            for (int t = tid; t < TFULL; t += 256) {
                float d = 0.f, a = 0.f;
#pragma unroll
                for (int l = 0; l < 8; l++) {
                    float val = sh[cur][(t - l * step) & (TFULL - 1)];
                    d += val * c_DEC_HI[l];
                    a += val * c_DEC_LO[l];
                }
                wout[t] = d;
                sh[cur ^ 1][t] = a;
            }
            __syncthreads();
            cur ^= 1;
        }
    } else {
        const int blk = blockIdx.x - 128;
        const int sw = blk / 16;
        const int chunk = blk % 16;
        const int s = sw / 3, w = sw % 3;
        const float* Wx = (w == 0) ? Wq : (w == 1) ? Wk : Wv;
        const float* bx = (w == 0) ? bq : (w == 1) ? bk : bv;

        const int idx = chunk * 256 + tid;
        const int e = idx >> 5, cp = idx & 31;
        const int c0 = 2 * cp;
        const float* iw = in_w + (w * DMODEL + e) * DMODEL;
        const float* wc0 = Wx + s * DMODEL * CIN + c0;
        float a0 = 0.f, a1 = 0.f;
#pragma unroll 4
        for (int dd = 0; dd < DMODEL; dd++) {
            float ww = iw[dd];
            a0 += ww * wc0[dd * CIN];
            a1 += ww * wc0[dd * CIN + 1];
        }
        float h0 = __bfloat162float(__float2bfloat16(a0));
        float h1 = __bfloat162float(__float2bfloat16(a1));
        const size_t oidx = (size_t)(sw * DMODEL + e) * (CIN / 2) + cp;
        g_Ahi[oidx] = pkbf(h0, h1);
        g_Alo[oidx] = pkbf(a0 - h0, a1 - h1);

        if (chunk == 0 && tid < DMODEL) {
            const int ee = tid;
            const float* iw2 = in_w + (w * DMODEL + ee) * DMODEL;
            float bb = in_b[w * DMODEL + ee];
#pragma unroll 4
            for (int dd = 0; dd < DMODEL; dd++) bb += iw2[dd] * bx[s * DMODEL + dd];
            g_cb[sw * DMODEL + ee] = bb;
        }
    }
}

// ================= K2: q/k/v projection on tensor cores =================
#define QS 20
__global__ void __launch_bounds__(128) k_qkv() {
    __shared__ uint32 sWh[64 * QS], sWl[64 * QS];
    __shared__ uint32 sAh[128 * QS], sAl[128 * QS];
    const int row0 = blockIdx.x * 64;
    const int w = blockIdx.y;
    const int s = row0 >> 12;
    const int sbi = row0 >> 11;
    const int t0 = row0 & (TFULL - 1);
    const int tid = threadIdx.x;
    const int warp = tid >> 5, lane = tid & 31;
    const int gid = lane >> 2, tig = lane & 3;

    float cacc[16][4];
#pragma unroll
    for (int nt = 0; nt < 16; nt++)
#pragma unroll
        for (int i = 0; i < 4; i++) cacc[nt][i] = 0.f;

    const size_t abase = (size_t)((s * 3 + w) * DMODEL) * (CIN / 2);

    for (int p = 0; p < 2; p++) {
        const int c0p = p * 32;
        __nv_bfloat16* wh16 = (__nv_bfloat16*)sWh;
        __nv_bfloat16* wl16 = (__nv_bfloat16*)sWl;
#pragma unroll
        for (int i = 0; i < 16; i++) {
            int lin = tid + i * 128;
            int c = lin >> 6, tt = lin & 63;
            float wv = g_W[((size_t)(sbi * CIN + c0p + c)) * TFULL + t0 + tt];
            __nv_bfloat16 hb = __float2bfloat16(wv);
            wh16[tt * (2 * QS) + c] = hb;
            wl16[tt * (2 * QS) + c] = __float2bfloat16(wv - __bfloat162float(hb));
        }
#pragma unroll
        for (int i = 0; i < 16; i++) {
            int lin = tid + i * 128;
            int e = lin >> 4, cu = lin & 15;
            size_t gi = abase + (size_t)e * (CIN / 2) + p * 16 + cu;
            sAh[e * QS + cu] = g_Ahi[gi];
            sAl[e * QS + cu] = g_Alo[gi];
        }
        __syncthreads();

#pragma unroll
        for (int ks = 0; ks < 2; ks++) {
            const int ko = ks * 8;
            const int r0 = warp * 16 + gid;
            uint32 ah[4], al[4];
            ah[0] = sWh[r0 * QS + ko + tig];
            ah[1] = sWh[(r0 + 8) * QS + ko + tig];
            ah[2] = sWh[r0 * QS + ko + tig + 4];
            ah[3] = sWh[(r0 + 8) * QS + ko + tig + 4];
            al[0] = sWl[r0 * QS + ko + tig];
            al[1] = sWl[(r0 + 8) * QS + ko + tig];
            al[2] = sWl[r0 * QS + ko + tig + 4];
            al[3] = sWl[(r0 + 8) * QS + ko + tig + 4];
#pragma unroll
            for (int nt = 0; nt < 16; nt++) {
                const int er = 8 * nt + gid;
                uint32 b0h = sAh[er * QS + ko + tig];
                uint32 b1h = sAh[er * QS + ko + tig + 4];
                uint32 b0l = sAl[er * QS + ko + tig];
                uint32 b1l = sAl[er * QS + ko + tig + 4];
                mma_bf16(cacc[nt], ah, b0h, b1h);
                mma_bf16(cacc[nt], ah, b0l, b1l);
                mma_bf16(cacc[nt], al, b0h, b1h);
            }
        }
        __syncthreads();
    }

    const float* cb = g_cb + (s * 3 + w) * DMODEL;
    const int r = row0 + warp * 16 + gid;
#pragma unroll
    for (int nt = 0; nt < 16; nt++) {
        const int e0 = 8 * nt + 2 * tig;
        float b0v = cb[e0], b1v = cb[e0 + 1];
        float v00 = cacc[nt][0] + b0v, v01 = cacc[nt][1] + b1v;
        float v10 = cacc[nt][2] + b0v, v11 = cacc[nt][3] + b1v;
        size_t o0 = (size_t)r * DMODEL + e0;
        size_t o1 = (size_t)(r + 8) * DMODEL + e0;
        if (w == 0) {
            *(float2*)(g_q + o0) = make_float2(v00, v01);
            *(float2*)(g_q + o1) = make_float2(v10, v11);
        } else if (w == 1) {
            __nv_bfloat16 h00 = __float2bfloat16(v00);
            __nv_bfloat16 h01 = __float2bfloat16(v01);
            __nv_bfloat16 h10 = __float2bfloat16(v10);
            __nv_bfloat16 h11 = __float2bfloat16(v11);
            *(__nv_bfloat162*)(g_kh16 + o0) = __nv_bfloat162(h00, h01);
            *(__nv_bfloat162*)(g_kh16 + o1) = __nv_bfloat162(h10, h11);
            *(__nv_bfloat162*)(g_kl16 + o0) = __nv_bfloat162(
                __float2bfloat16(v00 - __bfloat162float(h00)),
                __float2bfloat16(v01 - __bfloat162float(h01)));
            *(__nv_bfloat162*)(g_kl16 + o1) = __nv_bfloat162(
                __float2bfloat16(v10 - __bfloat162float(h10)),
                __float2bfloat16(v11 - __bfloat162float(h11)));
        } else {
            *(float2*)(g_vt + o0) = make_float2(__uint_as_float(cvt_tf32(v00)),
                                                __uint_as_float(cvt_tf32(v01)));
            *(float2*)(g_vt + o1) = make_float2(__uint_as_float(cvt_tf32(v10)),
                                                __uint_as_float(cvt_tf32(v11)));
        }
    }
}

// ================= K3: flash attention, split-K x2, bf16 QK + tf32 PV =================
#define KS16    12
#define VSTRIDE 24
#define KCH     32
__global__ void k_attn() {
    __shared__ __align__(16) uint32 sKh[2 * KCH * KS16];
    __shared__ __align__(16) uint32 sKl[2 * KCH * KS16];
    __shared__ __align__(16) float  sV [2 * KCH * VSTRIDE];

    const int tid  = threadIdx.x;
    const int warp = tid >> 5, lane = tid & 31;
    const int gid  = lane >> 2, tig = lane & 3;
    const int qt = blockIdx.x, h = blockIdx.y;
    const int sb = blockIdx.z >> 1, kh = blockIdx.z & 1;
    const int qbase = qt * 128 + warp * 32;
    const int kbeg = kh * KHALF;

    const float sc = 0.25f * 1.4426950408889634f;

    uint32 ahi[2][4], alo[2][4];
#pragma unroll
    for (int g = 0; g < 2; g++) {
#pragma unroll
        for (int rr = 0; rr < 2; rr++) {
            const float* qr = g_q + ((size_t)(sb * TFULL) + qbase + g * 16 + gid + rr * 8) * DMODEL + h * DH;
            float2 pa = *(const float2*)(qr + 2 * tig);
            float2 pb = *(const float2*)(qr + 2 * tig + 8);
            float ax = pa.x * sc, ay = pa.y * sc;
            float bx = pb.x * sc, by = pb.y * sc;
            float axh = __bfloat162float(__float2bfloat16(ax));
            float ayh = __bfloat162float(__float2bfloat16(ay));
            float bxh = __bfloat162float(__float2bfloat16(bx));
            float byh = __bfloat162float(__float2bfloat16(by));
            ahi[g][rr]     = pkbf(axh, ayh);
            alo[g][rr]     = pkbf(ax - axh, ay - ayh);
            ahi[g][rr + 2] = pkbf(bxh, byh);
            alo[g][rr + 2] = pkbf(bx - bxh, by - byh);
        }
    }

    float m_lo[2] = { -1e30f, -1e30f }, m_hi[2] = { -1e30f, -1e30f };
    float l_lo[2] = { 0.f, 0.f },       l_hi[2] = { 0.f, 0.f };
    float oc[2][2][4];
#pragma unroll
    for (int g = 0; g < 2; g++)
#pragma unroll
        for (int nv = 0; nv < 2; nv++)
#pragma unroll
            for (int i = 0; i < 4; i++) oc[g][nv][i] = 0.f;

    const int sigma = (gid >> 1) + ((gid & 1) << 2);

    const int kr = (tid & 63) >> 1, kh2 = tid & 1;
    const int vr = tid >> 2,        vc  = tid & 3;
    const size_t gbase = (size_t)(sb * TFULL) * DMODEL + h * DH;
    const __nv_bfloat16* gK = (tid < 64) ? g_kh16 : g_kl16;
    const uint32 sK_b = (uint32)__cvta_generic_to_shared(tid < 64 ? sKh : sKl)
                        + (kr * KS16 + kh2 * 4) * 4;
    const uint32 sV_b = (uint32)__cvta_generic_to_shared(sV) + (vr * VSTRIDE + vc * 4) * 4;

    const uint32* kh_base = sKh + sigma * KS16 + tig;
    const uint32* kl_base = sKl + sigma * KS16 + tig;
    const float* v0_base = sV + tig * VSTRIDE + gid;
    const float* v1_base = sV + (tig + 4) * VSTRIDE + gid;

    {
        cp16(sK_b, gK + gbase + (size_t)(kbeg + kr) * DMODEL + kh2 * 8);
        cp16(sV_b, g_vt + gbase + (size_t)(kbeg + vr) * DMODEL + vc * 4);
        asm volatile("cp.async.commit_group;" ::: "memory");
    }

#pragma unroll 2
    for (int c = 0; c < KHALF / KCH; c++) {
        asm volatile("cp.async.wait_group 0;" ::: "memory");
        __syncthreads();
        if (c + 1 < KHALF / KCH) {
            int nb = (c + 1) & 1;
            int rbase = kbeg + (c + 1) * KCH;
            cp16(sK_b + nb * (KCH * KS16 * 4),
                 gK + gbase + (size_t)(rbase + kr) * DMODEL + kh2 * 8);
            cp16(sV_b + nb * (KCH * VSTRIDE * 4),
                 g_vt + gbase + (size_t)(rbase + vr) * DMODEL + vc * 4);
            asm volatile("cp.async.commit_group;" ::: "memory");
        }
        const int buf = c & 1;
        const uint32* khB = kh_base + buf * (KCH * KS16);
        const uint32* klB = kl_base + buf * (KCH * KS16);
        const float* v0B = v0_base + buf * (KCH * VSTRIDE);
        const float* v1B = v1_base + buf * (KCH * VSTRIDE);

        float cS[2][4][4];
#pragma unroll
        for (int nt = 0; nt < 4; nt++) {
#pragma unroll
            for (int g = 0; g < 2; g++) {
                cS[g][nt][0] = 0.f; cS[g][nt][1] = 0.f;
                cS[g][nt][2] = 0.f; cS[g][nt][3] = 0.f;
            }
            uint32 b0h = khB[nt * 8 * KS16];
            uint32 b1h = khB[nt * 8 * KS16 + 4];
            uint32 b0l = klB[nt * 8 * KS16];
            uint32 b1l = klB[nt * 8 * KS16 + 4];
#pragma unroll
            for (int g = 0; g < 2; g++) {
                mma_bf16(cS[g][nt], ahi[g], b0h, b1h);
                mma_bf16(cS[g][nt], ahi[g], b0l, b1l);
                mma_bf16(cS[g][nt], alo[g], b0h, b1h);
            }
        }

#pragma unroll
        for (int g = 0; g < 2; g++) {
            float mx0 = m_lo[g], mx1 = m_hi[g];
#pragma unroll
            for (int nt = 0; nt < 4; nt++) {
                mx0 = fmaxf(mx0, fmaxf(cS[g][nt][0], cS[g][nt][1]));
                mx1 = fmaxf(mx1, fmaxf(cS[g][nt][2], cS[g][nt][3]));
            }
            mx0 = fmaxf(mx0, __shfl_xor_sync(0xffffffffu, mx0, 1));
            mx0 = fmaxf(mx0, __shfl_xor_sync(0xffffffffu, mx0, 2));
            mx1 = fmaxf(mx1, __shfl_xor_sync(0xffffffffu, mx1, 1));
            mx1 = fmaxf(mx1, __shfl_xor_sync(0xffffffffu, mx1, 2));
            float cr0 = exp2f(m_lo[g] - mx0), cr1 = exp2f(m_hi[g] - mx1);
            m_lo[g] = mx0; m_hi[g] = mx1;
            l_lo[g] *= cr0; l_hi[g] *= cr1;
#pragma unroll
            for (int nv = 0; nv < 2; nv++) {
                oc[g][nv][0] *= cr0; oc[g][nv][1] *= cr0;
                oc[g][nv][2] *= cr1; oc[g][nv][3] *= cr1;
            }
#pragma unroll
            for (int nt = 0; nt < 4; nt++) {
                float p0 = exp2f(cS[g][nt][0] - mx0);
                float p1 = exp2f(cS[g][nt][1] - mx0);
                float p2 = exp2f(cS[g][nt][2] - mx1);
                float p3 = exp2f(cS[g][nt][3] - mx1);
                l_lo[g] += p0 + p1;
                l_hi[g] += p2 + p3;
                cS[g][nt][0] = p0;
                cS[g][nt][1] = p1;
                cS[g][nt][2] = p2;
                cS[g][nt][3] = p3;
            }
        }

#pragma unroll
        for (int j = 0; j < 4; j++) {
            const float* v0 = v0B + 8 * j * VSTRIDE;
            const float* v1 = v1B + 8 * j * VSTRIDE;
            uint32 b0a = __float_as_uint(v0[0]);
            uint32 b1a = __float_as_uint(v1[0]);
            uint32 b0b = __float_as_uint(v0[8]);
            uint32 b1b = __float_as_uint(v1[8]);
#pragma unroll
            for (int g = 0; g < 2; g++) {
                uint32 ap[4] = { __float_as_uint(cS[g][j][0]), __float_as_uint(cS[g][j][2]),
                                 __float_as_uint(cS[g][j][1]), __float_as_uint(cS[g][j][3]) };
                mma_tf32(oc[g][0], ap, b0a, b1a);
                mma_tf32(oc[g][1], ap, b0b, b1b);
            }
        }
    }

#pragma unroll
    for (int g = 0; g < 2; g++) {
        float ll = l_lo[g], lh = l_hi[g];
        ll += __shfl_xor_sync(0xffffffffu, ll, 1);
        ll += __shfl_xor_sync(0xffffffffu, ll, 2);
        lh += __shfl_xor_sync(0xffffffffu, lh, 1);
        lh += __shfl_xor_sync(0xffffffffu, lh, 2);

        const int r1 = qbase + g * 16 + gid;
        float* pb = g_pacc + (((size_t)(kh * (SNUM * BNUM) + sb)) * TFULL + r1) * DMODEL + h * DH;
#pragma unroll
        for (int nv = 0; nv < 2; nv++) {
            *(float2*)(pb + 2 * tig + 8 * nv) =
                make_float2(oc[g][nv][0], oc[g][nv][1]);
            *(float2*)(pb + 8 * DMODEL + 2 * tig + 8 * nv) =
                make_float2(oc[g][nv][2], oc[g][nv][3]);
        }
        if (tig == 0) {
            float2* pml = (float2*)g_pml;
            size_t base = ((size_t)(kh * (SNUM * BNUM) + sb)) * TFULL;
            pml[(base + r1) * HNUM + h]     = make_float2(m_lo[g], ll);
            pml[(base + r1 + 8) * HNUM + h] = make_float2(m_hi[g], lh);
        }
    }
}

// ================= K3b: fused merge + t-sum (vectorized, 384 blocks) =================
// grid (64 chunks of 32 t, 6 sb), block 256 = 32 d-quads x 8 t-phases.
__global__ void k_mergesum() {
    __shared__ float2 sh_sc[32 * HNUM];          // (e0,e1) per (t_local, h)
    __shared__ float4 sh_sum[256];
    const int ch = blockIdx.x, sb = blockIdx.y;
    const int tid = threadIdx.x;
    const int t0 = ch * 32;
    const size_t base0 = (size_t)sb * TFULL;
    const size_t base1 = (size_t)(SNUM * BNUM + sb) * TFULL;

    // phase A: merge scales -- 32 t x 8 h = 256, one per thread
    {
        const float2* pml = (const float2*)g_pml;
        int tl = tid >> 3, h = tid & 7;
        float2 ml0 = pml[(base0 + t0 + tl) * HNUM + h];
        float2 ml1 = pml[(base1 + t0 + tl) * HNUM + h];
        float M = fmaxf(ml0.x, ml1.x);
        float e0 = exp2f(ml0.x - M);
        float e1 = exp2f(ml1.x - M);
        float inv = 1.f / (e0 * ml0.y + e1 * ml1.y);
        sh_sc[tl * HNUM + h] = make_float2(e0 * inv, e1 * inv);
    }
    __syncthreads();

    // phase B: vectorized merge + accumulate. thread = (d-quad, t-phase).
    const int dq = tid & 31, tp = tid >> 5;      // dq: 4 consecutive d, tp: 0..7
    const int d0 = dq * 4;
    const int hh = d0 >> 4;
    float4 sum = make_float4(0.f, 0.f, 0.f, 0.f);
#pragma unroll
    for (int it = 0; it < 4; it++) {
        int tl = tp + it * 8;
        float2 scv = sh_sc[tl * HNUM + hh];
        size_t ri = (base0 + t0 + tl) * DMODEL + d0;
        float4 p0 = *(const float4*)(g_pacc + ri);
        float4 p1 = *(const float4*)(g_pacc + (base1 + t0 + tl) * DMODEL + d0);
        float4 o;
        o.x = p0.x * scv.x + p1.x * scv.y;
        o.y = p0.y * scv.x + p1.y * scv.y;
        o.z = p0.z * scv.x + p1.z * scv.y;
        o.w = p0.w * scv.x + p1.w * scv.y;
        *(float4*)(g_o + ri) = o;
        sum.x += o.x; sum.y += o.y; sum.z += o.z; sum.w += o.w;
    }
    sh_sum[tid] = sum;
    __syncthreads();
    // reduce over 8 t-phases (fixed order -> deterministic)
    if (tid < 32) {
        float4 acc = sh_sum[tid];
#pragma unroll
        for (int p = 1; p < 8; p++) {
            float4 v = sh_sum[tid + p * 32];
            acc.x += v.x; acc.y += v.y; acc.z += v.z; acc.w += v.w;
        }
        *(float4*)(g_meanp + ((size_t)sb * 64 + ch) * DMODEL + d0) = acc;
    }
}

// ================= K6: gate (per-block redundant) + gated combine + out-proj =================
__global__ void __launch_bounds__(256) k_final(const float* __restrict__ out_w,
                                               const float* __restrict__ out_b,
                                               const float* __restrict__ gate_w,
                                               const float* __restrict__ gate_b,
                                               float* __restrict__ Z) {
    __shared__ float shI[32][33];
    __shared__ float shWt[128][33];
    __shared__ float sh_m[DMODEL];
    __shared__ float sh_gf[DMODEL];
    __shared__ float sh_g[4];
    const int row0 = blockIdx.x * 32;
    const int tid = threadIdx.x;
    const int b = row0 >> 11;
    const int ty = tid >> 4, tx = tid & 15;
    const size_t SB = (size_t)BNUM * TFULL * DMODEL;

    // ---- gate for batch b (redundant per block) ----
    if (tid < DMODEL) {
        float mv = 0.f;
#pragma unroll
        for (int s = 0; s < SNUM; s++)
#pragma unroll 8
            for (int c = 0; c < 64; c++)
                mv += g_meanp[((size_t)(s * BNUM + b) * 64 + c) * DMODEL + tid];
        sh_m[tid] = mv;
    }
    __syncthreads();
    if (tid < DMODEL) {
        float acc = 0.f;
        const float* ow = out_w + tid * DMODEL;
#pragma unroll 4
        for (int dd = 0; dd < DMODEL; dd++) acc += ow[dd] * sh_m[dd];
        sh_gf[tid] = acc * (1.0f / (TFULL * SNUM)) + out_b[tid];
    }
    __syncthreads();
    if (tid < SNUM) {
        float lg = gate_b[tid];
        for (int dd = 0; dd < DMODEL; dd++) lg += sh_gf[dd] * gate_w[tid * DMODEL + dd];
        sh_m[tid] = lg;
    }
    __syncthreads();
    if (tid == 0) {
        float mx = fmaxf(sh_m[0], fmaxf(sh_m[1], sh_m[2]));
        float e0 = __expf(sh_m[0] - mx);
        float e1 = __expf(sh_m[1] - mx);
        float e2 = __expf(sh_m[2] - mx);
        float inv = 1.f / (e0 + e1 + e2);
        sh_g[0] = e0 * inv; sh_g[1] = e1 * inv; sh_g[2] = e2 * inv;
    }
    __syncthreads();
    const float gt0 = sh_g[0], gt1 = sh_g[1], gt2 = sh_g[2];

    float acc[2][8];
#pragma unroll
    for (int i = 0; i < 2; i++)
#pragma unroll
        for (int j = 0; j < 8; j++) acc[i][j] = 0.f;

    for (int c0 = 0; c0 < DMODEL; c0 += 32) {
#pragma unroll
        for (int i = 0; i < 4; i++) {
            int lin = tid + i * 256;
            int rr = lin >> 5, cc = lin & 31;
            size_t idx = (size_t)(row0 + rr) * DMODEL + c0 + cc;
            float v0 = g_o[idx];
            float v1 = g_o[SB + idx];
            float v2 = g_o[2 * SB + idx];
            shI[rr][cc] = gt0 * v0 + gt1 * v1 + gt2 * v2;
        }
#pragma unroll
        for (int i = 0; i < 16; i++) {
            int lin = tid + i * 256;
            shWt[lin >> 5][lin & 31] = out_w[(lin >> 5) * DMODEL + c0 + (lin & 31)];
        }
        __syncthreads();
#pragma unroll
        for (int cc = 0; cc < 32; cc++) {
            float ir[2], wr[8];
#pragma unroll
            for (int i = 0; i < 2; i++) ir[i] = shI[i * 16 + ty][cc];
#pragma unroll
            for (int j = 0; j < 8; j++) wr[j] = shWt[j * 16 + tx][cc];
#pragma unroll
            for (int i = 0; i < 2; i++)
#pragma unroll
                for (int j = 0; j < 8; j++) acc[i][j] += ir[i] * wr[j];
        }
        __syncthreads();
    }

#pragma unroll
    for (int i = 0; i < 2; i++) {
        int r = row0 + i * 16 + ty;
#pragma unroll
        for (int j = 0; j < 8; j++) {
            int e = j * 16 + tx;
            Z[(size_t)r * DMODEL + e] = acc[i][j] + out_b[e];
        }
    }
}

// ================= launch =================
extern "C" void kernel_launch(void* const* d_in, const int* in_sizes, int n_in,
                              void* d_out, int out_size) {
    const float* x      = (const float*)d_in[0];
    const float* Wq     = (const float*)d_in[1];
    const float* bq     = (const float*)d_in[2];
    const float* Wk     = (const float*)d_in[3];
    const float* bk     = (const float*)d_in[4];
    const float* Wv     = (const float*)d_in[5];
    const float* bv     = (const float*)d_in[6];
    const float* in_w   = (const float*)d_in[7];
    const float* in_b   = (const float*)d_in[8];
    const float* out_w  = (const float*)d_in[9];
    const float* out_b  = (const float*)d_in[10];
    const float* gate_w = (const float*)d_in[11];
    const float* gate_b = (const float*)d_in[12];
    float* Z = (float*)d_out;

    k_prep    <<<128 + 144, 256>>>(x, Wq, bq, Wk, bk, Wv, bv, in_w, in_b);
    k_qkv     <<<dim3(192, 3), 128>>>();
    k_attn    <<<dim3(16, HNUM, SNUM * BNUM * 2), 128>>>();
    k_mergesum<<<dim3(64, SNUM * BNUM), 256>>>();
    k_final   <<<128, 256>>>(out_w, out_b, gate_w, gate_b, Z);
}

// round 17
// speedup vs baseline: 1.5502x; 1.0100x over previous
#include <cuda_runtime.h>
#include <cuda_bf16.h>

#define TFULL 2048
#define CIN   64
#define DMODEL 128
#define SNUM  3
#define BNUM  2
#define HNUM  8
#define DH    16
#define KQTR  512

typedef unsigned int uint32;

__device__ __forceinline__ uint32 cvt_tf32(float x) {
    uint32 r; asm("cvt.rna.tf32.f32 %0,%1;" : "=r"(r) : "f"(x)); return r;
}
__device__ __forceinline__ void mma_tf32(float* d, const uint32* a, uint32 b0, uint32 b1) {
    asm volatile("mma.sync.aligned.m16n8k8.row.col.f32.tf32.tf32.f32 "
        "{%0,%1,%2,%3},{%4,%5,%6,%7},{%8,%9},{%0,%1,%2,%3};"
        : "+f"(d[0]), "+f"(d[1]), "+f"(d[2]), "+f"(d[3])
        : "r"(a[0]), "r"(a[1]), "r"(a[2]), "r"(a[3]), "r"(b0), "r"(b1));
}
__device__ __forceinline__ void mma_bf16(float* d, const uint32* a, uint32 b0, uint32 b1) {
    asm volatile("mma.sync.aligned.m16n8k16.row.col.f32.bf16.bf16.f32 "
        "{%0,%1,%2,%3},{%4,%5,%6,%7},{%8,%9},{%0,%1,%2,%3};"
        : "+f"(d[0]), "+f"(d[1]), "+f"(d[2]), "+f"(d[3])
        : "r"(a[0]), "r"(a[1]), "r"(a[2]), "r"(a[3]), "r"(b0), "r"(b1));
}
__device__ __forceinline__ void cp16(uint32 saddr, const void* g) {
    asm volatile("cp.async.cg.shared.global [%0], [%1], 16;" :: "r"(saddr), "l"(g));
}
__device__ __forceinline__ uint32 pkbf(float a, float b) {
    __nv_bfloat162 t = __floats2bfloat162_rn(a, b);
    return *reinterpret_cast<uint32*>(&t);
}

// ---------------- wavelet filters ----------------
__constant__ float c_DEC_LO[8] = {
    -0.010597401784997278f,  0.032883011666982945f,  0.030841381835986965f,
    -0.18703481171888114f,  -0.02798376941698385f,   0.6308807679295904f,
     0.7148465705525415f,    0.23037781330885523f };
__constant__ float c_DEC_HI[8] = {
    -0.23037781330885523f,   0.7148465705525415f,   -0.6308807679295904f,
    -0.02798376941698385f,   0.18703481171888114f,   0.030841381835986965f,
    -0.032883011666982945f, -0.010597401784997278f };

// ---------------- scratch ----------------
__device__ float g_W   [SNUM*BNUM*CIN*TFULL];             // channel-major
__device__ uint32 g_Ahi[SNUM*3*DMODEL*(CIN/2)];
__device__ uint32 g_Alo[SNUM*3*DMODEL*(CIN/2)];
__device__ float g_cb  [SNUM*3*DMODEL];
__device__ float g_q   [SNUM*BNUM*TFULL*DMODEL];
__device__ __nv_bfloat16 g_kh16[SNUM*BNUM*TFULL*DMODEL];
__device__ __nv_bfloat16 g_kl16[SNUM*BNUM*TFULL*DMODEL];
__device__ float g_vt  [SNUM*BNUM*TFULL*DMODEL];
__device__ float g_o   [SNUM*BNUM*TFULL*DMODEL];
__device__ float g_pacc[4*SNUM*BNUM*TFULL*DMODEL];        // split-K x4 partials
__device__ float g_pml [4*SNUM*BNUM*TFULL*HNUM*2];
__device__ float g_meanp[SNUM*BNUM*64*DMODEL];            // 64 chunks of 32 t

// ================= K0: fused SWT + weight-compose =================
__global__ void k_prep(const float* __restrict__ x,
                       const float* __restrict__ Wq, const float* __restrict__ bq,
                       const float* __restrict__ Wk, const float* __restrict__ bk,
                       const float* __restrict__ Wv, const float* __restrict__ bv,
                       const float* __restrict__ in_w, const float* __restrict__ in_b) {
    const int tid = threadIdx.x;
    if (blockIdx.x < 128) {
        __shared__ float sh[2][TFULL];
        const int b = blockIdx.x >> 6;
        const int c = blockIdx.x & 63;
        for (int t = tid; t < TFULL; t += 256)
            sh[0][t] = x[(b * TFULL + t) * CIN + c];
        __syncthreads();
        int cur = 0;
        for (int j = 0; j < 3; j++) {
            const int step = 1 << j;
            float* wout = g_W + ((size_t)(((2 - j) * BNUM + b) * CIN + c)) * TFULL;
            for (int t = tid; t < TFULL; t += 256) {
                float d = 0.f, a = 0.f;
#pragma unroll
                for (int l = 0; l < 8; l++) {
                    float val = sh[cur][(t - l * step) & (TFULL - 1)];
                    d += val * c_DEC_HI[l];
                    a += val * c_DEC_LO[l];
                }
                wout[t] = d;
                sh[cur ^ 1][t] = a;
            }
            __syncthreads();
            cur ^= 1;
        }
    } else {
        const int blk = blockIdx.x - 128;
        const int sw = blk / 16;
        const int chunk = blk % 16;
        const int s = sw / 3, w = sw % 3;
        const float* Wx = (w == 0) ? Wq : (w == 1) ? Wk : Wv;
        const float* bx = (w == 0) ? bq : (w == 1) ? bk : bv;

        const int idx = chunk * 256 + tid;
        const int e = idx >> 5, cp = idx & 31;
        const int c0 = 2 * cp;
        const float* iw = in_w + (w * DMODEL + e) * DMODEL;
        const float* wc0 = Wx + s * DMODEL * CIN + c0;
        float a0 = 0.f, a1 = 0.f;
#pragma unroll 4
        for (int dd = 0; dd < DMODEL; dd++) {
            float ww = iw[dd];
            a0 += ww * wc0[dd * CIN];
            a1 += ww * wc0[dd * CIN + 1];
        }
        float h0 = __bfloat162float(__float2bfloat16(a0));
        float h1 = __bfloat162float(__float2bfloat16(a1));
        const size_t oidx = (size_t)(sw * DMODEL + e) * (CIN / 2) + cp;
        g_Ahi[oidx] = pkbf(h0, h1);
        g_Alo[oidx] = pkbf(a0 - h0, a1 - h1);

        if (chunk == 0 && tid < DMODEL) {
            const int ee = tid;
            const float* iw2 = in_w + (w * DMODEL + ee) * DMODEL;
            float bb = in_b[w * DMODEL + ee];
#pragma unroll 4
            for (int dd = 0; dd < DMODEL; dd++) bb += iw2[dd] * bx[s * DMODEL + dd];
            g_cb[sw * DMODEL + ee] = bb;
        }
    }
}

// ================= K2: q/k/v projection on tensor cores =================
#define QS 20
__global__ void __launch_bounds__(128) k_qkv() {
    __shared__ uint32 sWh[64 * QS], sWl[64 * QS];
    __shared__ uint32 sAh[128 * QS], sAl[128 * QS];
    const int row0 = blockIdx.x * 64;
    const int w = blockIdx.y;
    const int s = row0 >> 12;
    const int sbi = row0 >> 11;
    const int t0 = row0 & (TFULL - 1);
    const int tid = threadIdx.x;
    const int warp = tid >> 5, lane = tid & 31;
    const int gid = lane >> 2, tig = lane & 3;

    float cacc[16][4];
#pragma unroll
    for (int nt = 0; nt < 16; nt++)
#pragma unroll
        for (int i = 0; i < 4; i++) cacc[nt][i] = 0.f;

    const size_t abase = (size_t)((s * 3 + w) * DMODEL) * (CIN / 2);

    for (int p = 0; p < 2; p++) {
        const int c0p = p * 32;
        __nv_bfloat16* wh16 = (__nv_bfloat16*)sWh;
        __nv_bfloat16* wl16 = (__nv_bfloat16*)sWl;
#pragma unroll
        for (int i = 0; i < 16; i++) {
            int lin = tid + i * 128;
            int c = lin >> 6, tt = lin & 63;
            float wv = g_W[((size_t)(sbi * CIN + c0p + c)) * TFULL + t0 + tt];
            __nv_bfloat16 hb = __float2bfloat16(wv);
            wh16[tt * (2 * QS) + c] = hb;
            wl16[tt * (2 * QS) + c] = __float2bfloat16(wv - __bfloat162float(hb));
        }
#pragma unroll
        for (int i = 0; i < 16; i++) {
            int lin = tid + i * 128;
            int e = lin >> 4, cu = lin & 15;
            size_t gi = abase + (size_t)e * (CIN / 2) + p * 16 + cu;
            sAh[e * QS + cu] = g_Ahi[gi];
            sAl[e * QS + cu] = g_Alo[gi];
        }
        __syncthreads();

#pragma unroll
        for (int ks = 0; ks < 2; ks++) {
            const int ko = ks * 8;
            const int r0 = warp * 16 + gid;
            uint32 ah[4], al[4];
            ah[0] = sWh[r0 * QS + ko + tig];
            ah[1] = sWh[(r0 + 8) * QS + ko + tig];
            ah[2] = sWh[r0 * QS + ko + tig + 4];
            ah[3] = sWh[(r0 + 8) * QS + ko + tig + 4];
            al[0] = sWl[r0 * QS + ko + tig];
            al[1] = sWl[(r0 + 8) * QS + ko + tig];
            al[2] = sWl[r0 * QS + ko + tig + 4];
            al[3] = sWl[(r0 + 8) * QS + ko + tig + 4];
#pragma unroll
            for (int nt = 0; nt < 16; nt++) {
                const int er = 8 * nt + gid;
                uint32 b0h = sAh[er * QS + ko + tig];
                uint32 b1h = sAh[er * QS + ko + tig + 4];
                uint32 b0l = sAl[er * QS + ko + tig];
                uint32 b1l = sAl[er * QS + ko + tig + 4];
                mma_bf16(cacc[nt], ah, b0h, b1h);
                mma_bf16(cacc[nt], ah, b0l, b1l);
                mma_bf16(cacc[nt], al, b0h, b1h);
            }
        }
        __syncthreads();
    }

    const float* cb = g_cb + (s * 3 + w) * DMODEL;
    const int r = row0 + warp * 16 + gid;
#pragma unroll
    for (int nt = 0; nt < 16; nt++) {
        const int e0 = 8 * nt + 2 * tig;
        float b0v = cb[e0], b1v = cb[e0 + 1];
        float v00 = cacc[nt][0] + b0v, v01 = cacc[nt][1] + b1v;
        float v10 = cacc[nt][2] + b0v, v11 = cacc[nt][3] + b1v;
        size_t o0 = (size_t)r * DMODEL + e0;
        size_t o1 = (size_t)(r + 8) * DMODEL + e0;
        if (w == 0) {
            *(float2*)(g_q + o0) = make_float2(v00, v01);
            *(float2*)(g_q + o1) = make_float2(v10, v11);
        } else if (w == 1) {
            __nv_bfloat16 h00 = __float2bfloat16(v00);
            __nv_bfloat16 h01 = __float2bfloat16(v01);
            __nv_bfloat16 h10 = __float2bfloat16(v10);
            __nv_bfloat16 h11 = __float2bfloat16(v11);
            *(__nv_bfloat162*)(g_kh16 + o0) = __nv_bfloat162(h00, h01);
            *(__nv_bfloat162*)(g_kh16 + o1) = __nv_bfloat162(h10, h11);
            *(__nv_bfloat162*)(g_kl16 + o0) = __nv_bfloat162(
                __float2bfloat16(v00 - __bfloat162float(h00)),
                __float2bfloat16(v01 - __bfloat162float(h01)));
            *(__nv_bfloat162*)(g_kl16 + o1) = __nv_bfloat162(
                __float2bfloat16(v10 - __bfloat162float(h10)),
                __float2bfloat16(v11 - __bfloat162float(h11)));
        } else {
            *(float2*)(g_vt + o0) = make_float2(__uint_as_float(cvt_tf32(v00)),
                                                __uint_as_float(cvt_tf32(v01)));
            *(float2*)(g_vt + o1) = make_float2(__uint_as_float(cvt_tf32(v10)),
                                                __uint_as_float(cvt_tf32(v11)));
        }
    }
}

// ================= K3: flash attention, split-K x4, bf16 QK + tf32 PV =================
#define KS16    12
#define VSTRIDE 24
#define KCH     32
__global__ void k_attn() {
    __shared__ __align__(16) uint32 sKh[2 * KCH * KS16];
    __shared__ __align__(16) uint32 sKl[2 * KCH * KS16];
    __shared__ __align__(16) float  sV [2 * KCH * VSTRIDE];

    const int tid  = threadIdx.x;
    const int warp = tid >> 5, lane = tid & 31;
    const int gid  = lane >> 2, tig = lane & 3;
    const int qt = blockIdx.x, h = blockIdx.y;
    const int sb = blockIdx.z >> 2, kh = blockIdx.z & 3;
    const int qbase = qt * 128 + warp * 32;
    const int kbeg = kh * KQTR;

    const float sc = 0.25f * 1.4426950408889634f;

    uint32 ahi[2][4], alo[2][4];
#pragma unroll
    for (int g = 0; g < 2; g++) {
#pragma unroll
        for (int rr = 0; rr < 2; rr++) {
            const float* qr = g_q + ((size_t)(sb * TFULL) + qbase + g * 16 + gid + rr * 8) * DMODEL + h * DH;
            float2 pa = *(const float2*)(qr + 2 * tig);
            float2 pb = *(const float2*)(qr + 2 * tig + 8);
            float ax = pa.x * sc, ay = pa.y * sc;
            float bx = pb.x * sc, by = pb.y * sc;
            float axh = __bfloat162float(__float2bfloat16(ax));
            float ayh = __bfloat162float(__float2bfloat16(ay));
            float bxh = __bfloat162float(__float2bfloat16(bx));
            float byh = __bfloat162float(__float2bfloat16(by));
            ahi[g][rr]     = pkbf(axh, ayh);
            alo[g][rr]     = pkbf(ax - axh, ay - ayh);
            ahi[g][rr + 2] = pkbf(bxh, byh);
            alo[g][rr + 2] = pkbf(bx - bxh, by - byh);
        }
    }

    float m_lo[2] = { -1e30f, -1e30f }, m_hi[2] = { -1e30f, -1e30f };
    float l_lo[2] = { 0.f, 0.f },       l_hi[2] = { 0.f, 0.f };
    float oc[2][2][4];
#pragma unroll
    for (int g = 0; g < 2; g++)
#pragma unroll
        for (int nv = 0; nv < 2; nv++)
#pragma unroll
            for (int i = 0; i < 4; i++) oc[g][nv][i] = 0.f;

    const int sigma = (gid >> 1) + ((gid & 1) << 2);

    const int kr = (tid & 63) >> 1, kh2 = tid & 1;
    const int vr = tid >> 2,        vc  = tid & 3;
    const size_t gbase = (size_t)(sb * TFULL) * DMODEL + h * DH;
    const __nv_bfloat16* gK = (tid < 64) ? g_kh16 : g_kl16;
    const uint32 sK_b = (uint32)__cvta_generic_to_shared(tid < 64 ? sKh : sKl)
                        + (kr * KS16 + kh2 * 4) * 4;
    const uint32 sV_b = (uint32)__cvta_generic_to_shared(sV) + (vr * VSTRIDE + vc * 4) * 4;

    const uint32* kh_base = sKh + sigma * KS16 + tig;
    const uint32* kl_base = sKl + sigma * KS16 + tig;
    const float* v0_base = sV + tig * VSTRIDE + gid;
    const float* v1_base = sV + (tig + 4) * VSTRIDE + gid;

    {
        cp16(sK_b, gK + gbase + (size_t)(kbeg + kr) * DMODEL + kh2 * 8);
        cp16(sV_b, g_vt + gbase + (size_t)(kbeg + vr) * DMODEL + vc * 4);
        asm volatile("cp.async.commit_group;" ::: "memory");
    }

#pragma unroll 2
    for (int c = 0; c < KQTR / KCH; c++) {
        asm volatile("cp.async.wait_group 0;" ::: "memory");
        __syncthreads();
        if (c + 1 < KQTR / KCH) {
            int nb = (c + 1) & 1;
            int rbase = kbeg + (c + 1) * KCH;
            cp16(sK_b + nb * (KCH * KS16 * 4),
                 gK + gbase + (size_t)(rbase + kr) * DMODEL + kh2 * 8);
            cp16(sV_b + nb * (KCH * VSTRIDE * 4),
                 g_vt + gbase + (size_t)(rbase + vr) * DMODEL + vc * 4);
            asm volatile("cp.async.commit_group;" ::: "memory");
        }
        const int buf = c & 1;
        const uint32* khB = kh_base + buf * (KCH * KS16);
        const uint32* klB = kl_base + buf * (KCH * KS16);
        const float* v0B = v0_base + buf * (KCH * VSTRIDE);
        const float* v1B = v1_base + buf * (KCH * VSTRIDE);

        float cS[2][4][4];
#pragma unroll
        for (int nt = 0; nt < 4; nt++) {
#pragma unroll
            for (int g = 0; g < 2; g++) {
                cS[g][nt][0] = 0.f; cS[g][nt][1] = 0.f;
                cS[g][nt][2] = 0.f; cS[g][nt][3] = 0.f;
            }
            uint32 b0h = khB[nt * 8 * KS16];
            uint32 b1h = khB[nt * 8 * KS16 + 4];
            uint32 b0l = klB[nt * 8 * KS16];
            uint32 b1l = klB[nt * 8 * KS16 + 4];
#pragma unroll
            for (int g = 0; g < 2; g++) {
                mma_bf16(cS[g][nt], ahi[g], b0h, b1h);
                mma_bf16(cS[g][nt], ahi[g], b0l, b1l);
                mma_bf16(cS[g][nt], alo[g], b0h, b1h);
            }
        }

#pragma unroll
        for (int g = 0; g < 2; g++) {
            float mx0 = m_lo[g], mx1 = m_hi[g];
#pragma unroll
            for (int nt = 0; nt < 4; nt++) {
                mx0 = fmaxf(mx0, fmaxf(cS[g][nt][0], cS[g][nt][1]));
                mx1 = fmaxf(mx1, fmaxf(cS[g][nt][2], cS[g][nt][3]));
            }
            mx0 = fmaxf(mx0, __shfl_xor_sync(0xffffffffu, mx0, 1));
            mx0 = fmaxf(mx0, __shfl_xor_sync(0xffffffffu, mx0, 2));
            mx1 = fmaxf(mx1, __shfl_xor_sync(0xffffffffu, mx1, 1));
            mx1 = fmaxf(mx1, __shfl_xor_sync(0xffffffffu, mx1, 2));
            float cr0 = exp2f(m_lo[g] - mx0), cr1 = exp2f(m_hi[g] - mx1);
            m_lo[g] = mx0; m_hi[g] = mx1;
            l_lo[g] *= cr0; l_hi[g] *= cr1;
#pragma unroll
            for (int nv = 0; nv < 2; nv++) {
                oc[g][nv][0] *= cr0; oc[g][nv][1] *= cr0;
                oc[g][nv][2] *= cr1; oc[g][nv][3] *= cr1;
            }
#pragma unroll
            for (int nt = 0; nt < 4; nt++) {
                float p0 = exp2f(cS[g][nt][0] - mx0);
                float p1 = exp2f(cS[g][nt][1] - mx0);
                float p2 = exp2f(cS[g][nt][2] - mx1);
                float p3 = exp2f(cS[g][nt][3] - mx1);
                l_lo[g] += p0 + p1;
                l_hi[g] += p2 + p3;
                cS[g][nt][0] = p0;
                cS[g][nt][1] = p1;
                cS[g][nt][2] = p2;
                cS[g][nt][3] = p3;
            }
        }

#pragma unroll
        for (int j = 0; j < 4; j++) {
            const float* v0 = v0B + 8 * j * VSTRIDE;
            const float* v1 = v1B + 8 * j * VSTRIDE;
            uint32 b0a = __float_as_uint(v0[0]);
            uint32 b1a = __float_as_uint(v1[0]);
            uint32 b0b = __float_as_uint(v0[8]);
            uint32 b1b = __float_as_uint(v1[8]);
#pragma unroll
            for (int g = 0; g < 2; g++) {
                uint32 ap[4] = { __float_as_uint(cS[g][j][0]), __float_as_uint(cS[g][j][2]),
                                 __float_as_uint(cS[g][j][1]), __float_as_uint(cS[g][j][3]) };
                mma_tf32(oc[g][0], ap, b0a, b1a);
                mma_tf32(oc[g][1], ap, b0b, b1b);
            }
        }
    }

#pragma unroll
    for (int g = 0; g < 2; g++) {
        float ll = l_lo[g], lh = l_hi[g];
        ll += __shfl_xor_sync(0xffffffffu, ll, 1);
        ll += __shfl_xor_sync(0xffffffffu, ll, 2);
        lh += __shfl_xor_sync(0xffffffffu, lh, 1);
        lh += __shfl_xor_sync(0xffffffffu, lh, 2);

        const int r1 = qbase + g * 16 + gid;
        float* pb = g_pacc + (((size_t)(kh * (SNUM * BNUM) + sb)) * TFULL + r1) * DMODEL + h * DH;
#pragma unroll
        for (int nv = 0; nv < 2; nv++) {
            *(float2*)(pb + 2 * tig + 8 * nv) =
                make_float2(oc[g][nv][0], oc[g][nv][1]);
            *(float2*)(pb + 8 * DMODEL + 2 * tig + 8 * nv) =
                make_float2(oc[g][nv][2], oc[g][nv][3]);
        }
        if (tig == 0) {
            float2* pml = (float2*)g_pml;
            size_t base = ((size_t)(kh * (SNUM * BNUM) + sb)) * TFULL;
            pml[(base + r1) * HNUM + h]     = make_float2(m_lo[g], ll);
            pml[(base + r1 + 8) * HNUM + h] = make_float2(m_hi[g], lh);
        }
    }
}

// ================= K3b: fused 4-way merge + t-sum =================
// grid (64 chunks of 32 t, 6 sb), block 256 = 32 d-quads x 8 t-phases.
__global__ void k_mergesum() {
    __shared__ float4 sh_sc[32 * HNUM];          // 4 merge weights per (t_local, h)
    __shared__ float4 sh_sum[256];
    const int ch = blockIdx.x, sb = blockIdx.y;
    const int tid = threadIdx.x;
    const int t0 = ch * 32;
    const size_t SBT = (size_t)(SNUM * BNUM) * TFULL;
    const size_t base = (size_t)sb * TFULL;

    // phase A: 4-way log-sum-exp merge weights -- one (tl,h) per thread
    {
        const float2* pml = (const float2*)g_pml;
        int tl = tid >> 3, h = tid & 7;
        size_t ri = (base + t0 + tl) * HNUM + h;
        float2 ml0 = pml[ri];
        float2 ml1 = pml[SBT * HNUM + ri];
        float2 ml2 = pml[2 * SBT * HNUM + ri];
        float2 ml3 = pml[3 * SBT * HNUM + ri];
        float M = fmaxf(fmaxf(ml0.x, ml1.x), fmaxf(ml2.x, ml3.x));
        float e0 = exp2f(ml0.x - M);
        float e1 = exp2f(ml1.x - M);
        float e2 = exp2f(ml2.x - M);
        float e3 = exp2f(ml3.x - M);
        float inv = 1.f / (e0 * ml0.y + e1 * ml1.y + e2 * ml2.y + e3 * ml3.y);
        sh_sc[tl * HNUM + h] = make_float4(e0 * inv, e1 * inv, e2 * inv, e3 * inv);
    }
    __syncthreads();

    // phase B: vectorized merge + accumulate
    const int dq = tid & 31, tp = tid >> 5;
    const int d0 = dq * 4;
    const int hh = d0 >> 4;
    float4 sum = make_float4(0.f, 0.f, 0.f, 0.f);
#pragma unroll
    for (int it = 0; it < 4; it++) {
        int tl = tp + it * 8;
        float4 scv = sh_sc[tl * HNUM + hh];
        size_t ri = (base + t0 + tl) * DMODEL + d0;
        float4 p0 = *(const float4*)(g_pacc + ri);
        float4 p1 = *(const float4*)(g_pacc + SBT * DMODEL + ri);
        float4 p2 = *(const float4*)(g_pacc + 2 * SBT * DMODEL + ri);
        float4 p3 = *(const float4*)(g_pacc + 3 * SBT * DMODEL + ri);
        float4 o;
        o.x = p0.x * scv.x + p1.x * scv.y + p2.x * scv.z + p3.x * scv.w;
        o.y = p0.y * scv.x + p1.y * scv.y + p2.y * scv.z + p3.y * scv.w;
        o.z = p0.z * scv.x + p1.z * scv.y + p2.z * scv.z + p3.z * scv.w;
        o.w = p0.w * scv.x + p1.w * scv.y + p2.w * scv.z + p3.w * scv.w;
        *(float4*)(g_o + ri) = o;
        sum.x += o.x; sum.y += o.y; sum.z += o.z; sum.w += o.w;
    }
    sh_sum[tid] = sum;
    __syncthreads();
    if (tid < 32) {
        float4 acc = sh_sum[tid];
#pragma unroll
        for (int p = 1; p < 8; p++) {
            float4 v = sh_sum[tid + p * 32];
            acc.x += v.x; acc.y += v.y; acc.z += v.z; acc.w += v.w;
        }
        *(float4*)(g_meanp + ((size_t)sb * 64 + ch) * DMODEL + d0) = acc;
    }
}

// ================= K6: gate (per-block redundant) + gated combine + out-proj =================
__global__ void __launch_bounds__(256) k_final(const float* __restrict__ out_w,
                                               const float* __restrict__ out_b,
                                               const float* __restrict__ gate_w,
                                               const float* __restrict__ gate_b,
                                               float* __restrict__ Z) {
    __shared__ float shI[32][33];
    __shared__ float shWt[128][33];
    __shared__ float sh_m[DMODEL];
    __shared__ float sh_gf[DMODEL];
    __shared__ float sh_g[4];
    const int row0 = blockIdx.x * 32;
    const int tid = threadIdx.x;
    const int b = row0 >> 11;
    const int ty = tid >> 4, tx = tid & 15;
    const size_t SB = (size_t)BNUM * TFULL * DMODEL;

    if (tid < DMODEL) {
        float mv = 0.f;
#pragma unroll
        for (int s = 0; s < SNUM; s++)
#pragma unroll 8
            for (int c = 0; c < 64; c++)
                mv += g_meanp[((size_t)(s * BNUM + b) * 64 + c) * DMODEL + tid];
        sh_m[tid] = mv;
    }
    __syncthreads();
    if (tid < DMODEL) {
        float acc = 0.f;
        const float* ow = out_w + tid * DMODEL;
#pragma unroll 4
        for (int dd = 0; dd < DMODEL; dd++) acc += ow[dd] * sh_m[dd];
        sh_gf[tid] = acc * (1.0f / (TFULL * SNUM)) + out_b[tid];
    }
    __syncthreads();
    if (tid < SNUM) {
        float lg = gate_b[tid];
        for (int dd = 0; dd < DMODEL; dd++) lg += sh_gf[dd] * gate_w[tid * DMODEL + dd];
        sh_m[tid] = lg;
    }
    __syncthreads();
    if (tid == 0) {
        float mx = fmaxf(sh_m[0], fmaxf(sh_m[1], sh_m[2]));
        float e0 = __expf(sh_m[0] - mx);
        float e1 = __expf(sh_m[1] - mx);
        float e2 = __expf(sh_m[2] - mx);
        float inv = 1.f / (e0 + e1 + e2);
        sh_g[0] = e0 * inv; sh_g[1] = e1 * inv; sh_g[2] = e2 * inv;
    }
    __syncthreads();
    const float gt0 = sh_g[0], gt1 = sh_g[1], gt2 = sh_g[2];

    float acc[2][8];
#pragma unroll
    for (int i = 0; i < 2; i++)
#pragma unroll
        for (int j = 0; j < 8; j++) acc[i][j] = 0.f;

    for (int c0 = 0; c0 < DMODEL; c0 += 32) {
#pragma unroll
        for (int i = 0; i < 4; i++) {
            int lin = tid + i * 256;
            int rr = lin >> 5, cc = lin & 31;
            size_t idx = (size_t)(row0 + rr) * DMODEL + c0 + cc;
            float v0 = g_o[idx];
            float v1 = g_o[SB + idx];
            float v2 = g_o[2 * SB + idx];
            shI[rr][cc] = gt0 * v0 + gt1 * v1 + gt2 * v2;
        }
#pragma unroll
        for (int i = 0; i < 16; i++) {
            int lin = tid + i * 256;
            shWt[lin >> 5][lin & 31] = out_w[(lin >> 5) * DMODEL + c0 + (lin & 31)];
        }
        __syncthreads();
#pragma unroll
        for (int cc = 0; cc < 32; cc++) {
            float ir[2], wr[8];
#pragma unroll
            for (int i = 0; i < 2; i++) ir[i] = shI[i * 16 + ty][cc];
#pragma unroll
            for (int j = 0; j < 8; j++) wr[j] = shWt[j * 16 + tx][cc];
#pragma unroll
            for (int i = 0; i < 2; i++)
#pragma unroll
                for (int j = 0; j < 8; j++) acc[i][j] += ir[i] * wr[j];
        }
        __syncthreads();
    }

#pragma unroll
    for (int i = 0; i < 2; i++) {
        int r = row0 + i * 16 + ty;
#pragma unroll
        for (int j = 0; j < 8; j++) {
            int e = j * 16 + tx;
            Z[(size_t)r * DMODEL + e] = acc[i][j] + out_b[e];
        }
    }
}

// ================= launch =================
extern "C" void kernel_launch(void* const* d_in, const int* in_sizes, int n_in,
                              void* d_out, int out_size) {
    const float* x      = (const float*)d_in[0];
    const float* Wq     = (const float*)d_in[1];
    const float* bq     = (const float*)d_in[2];
    const float* Wk     = (const float*)d_in[3];
    const float* bk     = (const float*)d_in[4];
    const float* Wv     = (const float*)d_in[5];
    const float* bv     = (const float*)d_in[6];
    const float* in_w   = (const float*)d_in[7];
    const float* in_b   = (const float*)d_in[8];
    const float* out_w  = (const float*)d_in[9];
    const float* out_b  = (const float*)d_in[10];
    const float* gate_w = (const float*)d_in[11];
    const float* gate_b = (const float*)d_in[12];
    float* Z = (float*)d_out;

    k_prep    <<<128 + 144, 256>>>(x, Wq, bq, Wk, bk, Wv, bv, in_w, in_b);
    k_qkv     <<<dim3(192, 3), 128>>>();
    k_attn    <<<dim3(16, HNUM, SNUM * BNUM * 4), 128>>>();
    k_mergesum<<<dim3(64, SNUM * BNUM), 256>>>();
    k_final   <<<128, 256>>>(out_w, out_b, gate_w, gate_b, Z);
}